// round 4
// baseline (speedup 1.0000x reference)
#include <cuda_runtime.h>
#include <math.h>

#define NH 64      // B*H
#define NN 4096
#define DD 64
#define MM 256

#define SCALE   0.35355339059327379f   // 64^-0.25
#define EPSILON 1e-4f

// ---- scratch (__device__ globals) — 4.3 MB total ----
__device__ float    g_ctxraw [NH * MM * DD];
__device__ float    g_ksumraw[NH * MM];
__device__ float    g_vsum   [NH * DD];
__device__ unsigned g_gmax   [NH];
__device__ float    g_ctxf   [NH * MM * DD];
__device__ float    g_ksumf  [NH * MM];

__device__ __forceinline__ unsigned enc_f(float f) {
    unsigned u = __float_as_uint(f);
    return (u & 0x80000000u) ? ~u : (u | 0x80000000u);
}
__device__ __forceinline__ float dec_f(unsigned u) {
    return __uint_as_float((u & 0x80000000u) ? (u & 0x7fffffffu) : ~u);
}

// FMA-pipe exp: exp(x) = 2^(x*log2e), poly on fractional part. rel err ~1e-7.
__device__ __forceinline__ float fexp(float x) {
    float y = fmaxf(x * 1.4426950408889634f, -126.0f);
    float n = rintf(y);
    float f = y - n;
    float p = 1.5403530393381609e-4f;
    p = fmaf(p, f, 1.3333558146428443e-3f);
    p = fmaf(p, f, 9.6181291076284772e-3f);
    p = fmaf(p, f, 5.5504108664821580e-2f);
    p = fmaf(p, f, 2.4022650695910071e-1f);
    p = fmaf(p, f, 6.9314718055994531e-1f);
    p = fmaf(p, f, 1.0f);
    return p * __int_as_float(((int)n + 127) << 23);
}

// ---------------------------------------------------------------- K0: init
__global__ void k0_init() {
    int i = blockIdx.x * blockDim.x + threadIdx.x;
    if (i < NH * MM * DD) g_ctxraw[i] = 0.0f;
    if (i < NH * MM)      g_ksumraw[i] = 0.0f;
    if (i < NH * DD)      g_vsum[i] = 0.0f;
    if (i < NH)           g_gmax[i] = enc_f(-1e30f);
}

// =============================================================== Kernel A
// Fused k-side: dash = (s*K)·P^T ; w = exp(dash - diag) ;
// ctx_raw += w^T·V ; ksum_raw += Σ_n w ; vsum += Σ_n V ; gmax = max dash
// grid (8, NH), 256 thr, each block: 8 chunks of 64 rows.
#define A_SMEM ((64*256 + 64*68 + 64*256 + 64*68 + 64 + 256) * 4)
__global__ void __launch_bounds__(256, 1) kA(const float* __restrict__ K,
                                             const float* __restrict__ V,
                                             const float* __restrict__ P) {
    extern __shared__ float sm[];
    float* Pt   = sm;                 // [64][256]  P transposed
    float* kp   = Pt + 64 * 256;      // [64][256]  dash -> w
    float* ks   = kp + 64 * 256;      // [64][68]
    float* vs   = ks + 64 * 68;       // [64][68]
    float* diag = vs + 64 * 68;       // [64]
    float* red  = diag + 64;          // [256]

    int tid  = threadIdx.x;
    int head = blockIdx.y;
    int rbase = blockIdx.x * 512;
    const float* kb = K + (size_t)head * NN * DD;
    const float* vb = V + (size_t)head * NN * DD;

    // ---- load P transposed via staged smem transpose (conflict-free) ----
    for (int c = 0; c < 4; c++) {
        for (int i = tid; i < 64 * 64; i += 256) {
            int r = i >> 6, d = i & 63;
            vs[r * 65 + d] = P[(size_t)(c * 64 + r) * 64 + d];
        }
        __syncthreads();
        int m = tid & 63, q4 = tid >> 6;
        for (int d = q4; d < 64; d += 4)
            Pt[d * 256 + c * 64 + m] = vs[m * 65 + d];
        __syncthreads();
    }

    int t_e = tid & 7, t_m = tid >> 3;
    int ty = tid >> 5, tx = tid & 31;
    float cacc[8][8] = {};
    float ksacc[8] = {};
    float vsacc = 0.0f;
    float lmax = -1e30f;

    for (int ch = 0; ch < 8; ch++) {
        int n0 = rbase + ch * 64;
        __syncthreads();
        for (int i = tid; i < 64 * 64; i += 256) {
            int r = i >> 6, d = i & 63;
            ks[r * 68 + d] = SCALE * kb[(size_t)(n0 + r) * 64 + d];
            vs[r * 68 + d] = vb[(size_t)(n0 + r) * 64 + d];
        }
        __syncthreads();
        if (tid < 64) {
            float s = 0.0f;
            #pragma unroll 8
            for (int d = 0; d < 64; d++) { float t = ks[tid * 68 + d]; s += t * t; }
            diag[tid] = 0.5f * s;
        } else if (tid < 128) {
            int e = tid - 64;
            float s = 0.0f;
            #pragma unroll 8
            for (int r = 0; r < 64; r++) s += vs[r * 68 + e];
            vsacc += s;
        }
        // ---- dash GEMM: kp[64][256] = ks(64x64) · Pt(64x256) ----
        {
            float dacc[8][8] = {};
            #pragma unroll 8
            for (int d = 0; d < 64; d++) {
                float a[8], b[8];
                #pragma unroll
                for (int i = 0; i < 8; i++) a[i] = ks[(ty + 8 * i) * 68 + d];
                #pragma unroll
                for (int j = 0; j < 8; j++) b[j] = Pt[d * 256 + tx + 32 * j];
                #pragma unroll
                for (int i = 0; i < 8; i++)
                    #pragma unroll
                    for (int j = 0; j < 8; j++) dacc[i][j] += a[i] * b[j];
            }
            #pragma unroll
            for (int i = 0; i < 8; i++)
                #pragma unroll
                for (int j = 0; j < 8; j++) {
                    float v = dacc[i][j];
                    lmax = fmaxf(lmax, v);
                    kp[(ty + 8 * i) * 256 + tx + 32 * j] = v;
                }
        }
        __syncthreads();
        // ---- exp (FMA-pipe): w = exp(dash - diag) ----
        #pragma unroll 8
        for (int r = 0; r < 64; r++) {
            int idx = r * 256 + tid;
            kp[idx] = fexp(kp[idx] - diag[r]);
        }
        __syncthreads();
        // ---- ctx GEMM: cacc[m,e] += w^T · V, ksacc += column sums of w ----
        #pragma unroll 4
        for (int nn = 0; nn < 64; nn++) {
            float a[8], b[8];
            #pragma unroll
            for (int i = 0; i < 8; i++) a[i] = kp[nn * 256 + t_m + 32 * i];
            #pragma unroll
            for (int j = 0; j < 8; j++) b[j] = vs[nn * 68 + t_e + 8 * j];
            #pragma unroll
            for (int i = 0; i < 8; i++)
                #pragma unroll
                for (int j = 0; j < 8; j++) cacc[i][j] += a[i] * b[j];
            if (t_e == 0) {
                #pragma unroll
                for (int i = 0; i < 8; i++) ksacc[i] += a[i];
            }
        }
    }

    float* ctx = g_ctxraw + (size_t)head * MM * DD;
    #pragma unroll
    for (int i = 0; i < 8; i++)
        #pragma unroll
        for (int j = 0; j < 8; j++)
            atomicAdd(&ctx[(t_m + 32 * i) * 64 + t_e + 8 * j], cacc[i][j]);
    if (t_e == 0) {
        #pragma unroll
        for (int i = 0; i < 8; i++)
            atomicAdd(&g_ksumraw[head * MM + t_m + 32 * i], ksacc[i]);
    }
    if (tid >= 64 && tid < 128) atomicAdd(&g_vsum[head * DD + tid - 64], vsacc);

    red[tid] = lmax;
    __syncthreads();
    for (int s = 128; s > 0; s >>= 1) {
        if (tid < s) red[tid] = fmaxf(red[tid], red[tid + s]);
        __syncthreads();
    }
    if (tid == 0) atomicMax(&g_gmax[head], enc_f(red[0]));
}

// =============================================================== Kernel B
// Finalize: ctxf = e^{-gmax}·ctx_raw + eps·vsum ; ksumf = e^{-gmax}·ksum_raw + eps·N
__global__ void kB() {
    int head = blockIdx.x;
    int tid = threadIdx.x;
    float emx = fexp(-dec_f(g_gmax[head]));
    g_ksumf[head * MM + tid] = emx * g_ksumraw[head * MM + tid] + EPSILON * (float)NN;
    size_t base = (size_t)head * MM * DD;
    for (int i = tid; i < MM * DD; i += 256) {
        int e = i & 63;
        g_ctxf[base + i] = emx * g_ctxraw[base + i] + EPSILON * g_vsum[head * DD + e];
    }
}

// =============================================================== Kernel C
// Fused q-side: dash = (s*Q)·P^T ; w = exp(dash - diag - rowmax) + eps ;
// out = (w · ctxf) / (w · ksumf)        (ratio factors cancel)
// grid (8, NH), 256 thr, each block: 8 chunks of 64 rows.
#define C_SMEM ((64*256 + 256*64 + 64*256 + 64*68 + 256 + 64 + 64 + 256 + 256 + 64) * 4)
__global__ void __launch_bounds__(256, 1) kC(const float* __restrict__ Q,
                                             const float* __restrict__ P,
                                             float* __restrict__ out) {
    extern __shared__ float sm[];
    float* Pt   = sm;                  // [64][256]
    float* ctxs = Pt + 64 * 256;       // [256][64]
    float* dash = ctxs + 256 * 64;     // [64][256] -> w
    float* qs   = dash + 64 * 256;     // [64][68]
    float* ksums= qs + 64 * 68;        // [256]
    float* diag = ksums + 256;         // [64]
    float* mxs  = diag + 64;           // [64]
    float* pm   = mxs + 64;            // [64][4]
    float* pden = pm + 256;            // [64][4]
    float* dinv = pden + 256;          // [64]

    int tid  = threadIdx.x;
    int head = blockIdx.y;
    int rbase = blockIdx.x * 512;
    const float* qb = Q + (size_t)head * NN * DD;

    // persistent loads: P transposed (staged via qs), ctxf, ksumf
    for (int c = 0; c < 4; c++) {
        for (int i = tid; i < 64 * 64; i += 256) {
            int r = i >> 6, d = i & 63;
            qs[r * 65 + d] = P[(size_t)(c * 64 + r) * 64 + d];
        }
        __syncthreads();
        int m = tid & 63, q4 = tid >> 6;
        for (int d = q4; d < 64; d += 4)
            Pt[d * 256 + c * 64 + m] = qs[m * 65 + d];
        __syncthreads();
    }
    for (int i = tid; i < 256 * 64; i += 256) ctxs[i] = g_ctxf[(size_t)head * MM * DD + i];
    ksums[tid] = g_ksumf[head * MM + tid];

    int ty = tid >> 5, tx = tid & 31;       // dash GEMM layout
    int oy = tid >> 4, ox = tid & 15;       // out GEMM layout (4x4 micro, float4)

    for (int ch = 0; ch < 8; ch++) {
        int n0 = rbase + ch * 64;
        __syncthreads();
        for (int i = tid; i < 64 * 64; i += 256) {
            int r = i >> 6, d = i & 63;
            qs[r * 68 + d] = SCALE * qb[(size_t)(n0 + r) * 64 + d];
        }
        __syncthreads();
        if (tid < 64) {
            float s = 0.0f;
            #pragma unroll 8
            for (int d = 0; d < 64; d++) { float t = qs[tid * 68 + d]; s += t * t; }
            diag[tid] = 0.5f * s;
        }
        // ---- dash GEMM: dash[64][256] = qs(64x64) · Pt(64x256) ----
        {
            float dacc[8][8] = {};
            #pragma unroll 8
            for (int d = 0; d < 64; d++) {
                float a[8], b[8];
                #pragma unroll
                for (int i = 0; i < 8; i++) a[i] = qs[(ty + 8 * i) * 68 + d];
                #pragma unroll
                for (int j = 0; j < 8; j++) b[j] = Pt[d * 256 + tx + 32 * j];
                #pragma unroll
                for (int i = 0; i < 8; i++)
                    #pragma unroll
                    for (int j = 0; j < 8; j++) dacc[i][j] += a[i] * b[j];
            }
            #pragma unroll
            for (int i = 0; i < 8; i++)
                #pragma unroll
                for (int j = 0; j < 8; j++)
                    dash[(ty + 8 * i) * 256 + tx + 32 * j] = dacc[i][j];
        }
        __syncthreads();
        // ---- row max over 256 features ----
        {
            int r = tid >> 2, seg = tid & 3;
            float m = -1e30f;
            #pragma unroll 8
            for (int mm = seg * 64; mm < seg * 64 + 64; mm++) m = fmaxf(m, dash[r * 256 + mm]);
            pm[r * 4 + seg] = m;
        }
        __syncthreads();
        if (tid < 64)
            mxs[tid] = fmaxf(fmaxf(pm[tid * 4], pm[tid * 4 + 1]),
                             fmaxf(pm[tid * 4 + 2], pm[tid * 4 + 3]));
        __syncthreads();
        // ---- w = exp(dash - diag - rowmax) + eps (in place) ----
        #pragma unroll 8
        for (int r = 0; r < 64; r++) {
            int idx = r * 256 + tid;
            dash[idx] = fexp(dash[idx] - diag[r] - mxs[r]) + EPSILON;
        }
        __syncthreads();
        // ---- denominators: den[r] = Σ_m w·ksumf ----
        {
            int r = tid >> 2, seg = tid & 3;
            float s = 0.0f;
            #pragma unroll 8
            for (int mm = seg * 64; mm < seg * 64 + 64; mm++)
                s += dash[r * 256 + mm] * ksums[mm];
            pden[r * 4 + seg] = s;
        }
        __syncthreads();
        if (tid < 64)
            dinv[tid] = 1.0f / (pden[tid * 4] + pden[tid * 4 + 1] +
                                pden[tid * 4 + 2] + pden[tid * 4 + 3]);
        __syncthreads();
        // ---- out GEMM: out[64][64] = w(64x256) · ctxs(256x64), float4 duals ----
        {
            float oacc[4][4] = {};
            #pragma unroll 4
            for (int m = 0; m < 256; m += 4) {
                float4 a[4], b[4];
                #pragma unroll
                for (int i = 0; i < 4; i++)
                    a[i] = *reinterpret_cast<const float4*>(&dash[(oy * 4 + i) * 256 + m]);
                #pragma unroll
                for (int mm = 0; mm < 4; mm++)
                    b[mm] = *reinterpret_cast<const float4*>(&ctxs[(m + mm) * 64 + ox * 4]);
                #pragma unroll
                for (int i = 0; i < 4; i++) {
                    oacc[i][0] += a[i].x * b[0].x; oacc[i][1] += a[i].x * b[0].y;
                    oacc[i][2] += a[i].x * b[0].z; oacc[i][3] += a[i].x * b[0].w;
                    oacc[i][0] += a[i].y * b[1].x; oacc[i][1] += a[i].y * b[1].y;
                    oacc[i][2] += a[i].y * b[1].z; oacc[i][3] += a[i].y * b[1].w;
                    oacc[i][0] += a[i].z * b[2].x; oacc[i][1] += a[i].z * b[2].y;
                    oacc[i][2] += a[i].z * b[2].z; oacc[i][3] += a[i].z * b[2].w;
                    oacc[i][0] += a[i].w * b[3].x; oacc[i][1] += a[i].w * b[3].y;
                    oacc[i][2] += a[i].w * b[3].z; oacc[i][3] += a[i].w * b[3].w;
                }
            }
            float* ob = out + ((size_t)head * NN + n0) * DD;
            #pragma unroll
            for (int i = 0; i < 4; i++) {
                int r = oy * 4 + i;
                float di = dinv[r];
                float4 o;
                o.x = oacc[i][0] * di; o.y = oacc[i][1] * di;
                o.z = oacc[i][2] * di; o.w = oacc[i][3] * di;
                *reinterpret_cast<float4*>(&ob[(size_t)r * 64 + ox * 4]) = o;
            }
        }
    }
}

// ---------------------------------------------------------------- launch
extern "C" void kernel_launch(void* const* d_in, const int* in_sizes, int n_in,
                              void* d_out, int out_size) {
    const float* q = (const float*)d_in[0];
    const float* k = (const float*)d_in[1];
    const float* v = (const float*)d_in[2];
    const float* P = (const float*)d_in[3];
    float* out = (float*)d_out;

    cudaFuncSetAttribute(kA, cudaFuncAttributeMaxDynamicSharedMemorySize, A_SMEM);
    cudaFuncSetAttribute(kC, cudaFuncAttributeMaxDynamicSharedMemorySize, C_SMEM);

    k0_init<<<(NH * MM * DD + 255) / 256, 256>>>();
    kA<<<dim3(8, NH), 256, A_SMEM>>>(k, v, P);
    kB<<<NH, 256>>>();
    kC<<<dim3(8, NH), 256, C_SMEM>>>(q, P, out);
}

// round 5
// speedup vs baseline: 1.0011x; 1.0011x over previous
#include <cuda_runtime.h>
#include <math.h>

#define NH 64      // B*H
#define NN 4096
#define DD 64
#define MM 256

#define SCALE   0.35355339059327379f   // 64^-0.25
#define EPSILON 1e-4f

// ---- scratch (__device__ globals) — 4.3 MB total ----
__device__ float    g_ctxraw [NH * MM * DD];
__device__ float    g_ksumraw[NH * MM];
__device__ float    g_vsum   [NH * DD];
__device__ unsigned g_gmax   [NH];
__device__ float    g_ctxf   [NH * MM * DD];
__device__ float    g_ksumf  [NH * MM];

__device__ __forceinline__ unsigned enc_f(float f) {
    unsigned u = __float_as_uint(f);
    return (u & 0x80000000u) ? ~u : (u | 0x80000000u);
}
__device__ __forceinline__ float dec_f(unsigned u) {
    return __uint_as_float((u & 0x80000000u) ? (u & 0x7fffffffu) : ~u);
}

// FMA-pipe exp: exp(x) = 2^(x*log2e), poly on fractional part. rel err ~1e-7.
__device__ __forceinline__ float fexp(float x) {
    float y = fmaxf(x * 1.4426950408889634f, -126.0f);
    float n = rintf(y);
    float f = y - n;
    float p = 1.5403530393381609e-4f;
    p = fmaf(p, f, 1.3333558146428443e-3f);
    p = fmaf(p, f, 9.6181291076284772e-3f);
    p = fmaf(p, f, 5.5504108664821580e-2f);
    p = fmaf(p, f, 2.4022650695910071e-1f);
    p = fmaf(p, f, 6.9314718055994531e-1f);
    p = fmaf(p, f, 1.0f);
    return p * __int_as_float(((int)n + 127) << 23);
}

// ---------------------------------------------------------------- K0: init
__global__ void k0_init() {
    int i = blockIdx.x * blockDim.x + threadIdx.x;
    if (i < NH * MM * DD) g_ctxraw[i] = 0.0f;
    if (i < NH * MM)      g_ksumraw[i] = 0.0f;
    if (i < NH * DD)      g_vsum[i] = 0.0f;
    if (i < NH)           g_gmax[i] = enc_f(-1e30f);
}

// =============================================================== Kernel A
// Fused k-side: dash = (s*K)·P^T ; w = exp(dash - diag) ;
// ctx_raw += w^T·V ; ksum_raw += Σ_n w ; vsum += Σ_n V ; gmax = max dash
// grid (8, NH), 256 thr, each block: 8 chunks of 64 rows.
#define A_SMEM ((64*256 + 64*68 + 64*256 + 64*68 + 64 + 256) * 4)
__global__ void __launch_bounds__(256, 1) kA(const float* __restrict__ K,
                                             const float* __restrict__ V,
                                             const float* __restrict__ P) {
    extern __shared__ float sm[];
    float* Pt   = sm;                 // [64][256]  P transposed
    float* kp   = Pt + 64 * 256;      // [64][256]  dash -> w
    float* ks   = kp + 64 * 256;      // [64][68]
    float* vs   = ks + 64 * 68;       // [64][68]
    float* diag = vs + 64 * 68;       // [64]
    float* red  = diag + 64;          // [256]

    int tid  = threadIdx.x;
    int head = blockIdx.y;
    int rbase = blockIdx.x * 512;
    const float* kb = K + (size_t)head * NN * DD;
    const float* vb = V + (size_t)head * NN * DD;

    // ---- load P transposed via staged smem transpose (conflict-free) ----
    for (int c = 0; c < 4; c++) {
        for (int i = tid; i < 64 * 64; i += 256) {
            int r = i >> 6, d = i & 63;
            vs[r * 65 + d] = P[(size_t)(c * 64 + r) * 64 + d];
        }
        __syncthreads();
        int m = tid & 63, q4 = tid >> 6;
        for (int d = q4; d < 64; d += 4)
            Pt[d * 256 + c * 64 + m] = vs[m * 65 + d];
        __syncthreads();
    }

    int t_e = tid & 7, t_m = tid >> 3;
    int ty = tid >> 5, tx = tid & 31;
    float cacc[8][8] = {};
    float ksacc[8] = {};
    float vsacc = 0.0f;
    float lmax = -1e30f;

    for (int ch = 0; ch < 8; ch++) {
        int n0 = rbase + ch * 64;
        __syncthreads();
        for (int i = tid; i < 64 * 64; i += 256) {
            int r = i >> 6, d = i & 63;
            ks[r * 68 + d] = SCALE * kb[(size_t)(n0 + r) * 64 + d];
            vs[r * 68 + d] = vb[(size_t)(n0 + r) * 64 + d];
        }
        __syncthreads();
        if (tid < 64) {
            float s = 0.0f;
            #pragma unroll 8
            for (int d = 0; d < 64; d++) { float t = ks[tid * 68 + d]; s += t * t; }
            diag[tid] = 0.5f * s;
        } else if (tid < 128) {
            int e = tid - 64;
            float s = 0.0f;
            #pragma unroll 8
            for (int r = 0; r < 64; r++) s += vs[r * 68 + e];
            vsacc += s;
        }
        // ---- dash GEMM: kp[64][256] = ks(64x64) · Pt(64x256) ----
        {
            float dacc[8][8] = {};
            #pragma unroll 8
            for (int d = 0; d < 64; d++) {
                float a[8], b[8];
                #pragma unroll
                for (int i = 0; i < 8; i++) a[i] = ks[(ty + 8 * i) * 68 + d];
                #pragma unroll
                for (int j = 0; j < 8; j++) b[j] = Pt[d * 256 + tx + 32 * j];
                #pragma unroll
                for (int i = 0; i < 8; i++)
                    #pragma unroll
                    for (int j = 0; j < 8; j++) dacc[i][j] += a[i] * b[j];
            }
            #pragma unroll
            for (int i = 0; i < 8; i++)
                #pragma unroll
                for (int j = 0; j < 8; j++) {
                    float v = dacc[i][j];
                    lmax = fmaxf(lmax, v);
                    kp[(ty + 8 * i) * 256 + tx + 32 * j] = v;
                }
        }
        __syncthreads();
        // ---- exp (FMA-pipe): w = exp(dash - diag) ----
        #pragma unroll 8
        for (int r = 0; r < 64; r++) {
            int idx = r * 256 + tid;
            kp[idx] = fexp(kp[idx] - diag[r]);
        }
        __syncthreads();
        // ---- ctx GEMM: cacc[m,e] += w^T · V, ksacc += column sums of w ----
        #pragma unroll 4
        for (int nn = 0; nn < 64; nn++) {
            float a[8], b[8];
            #pragma unroll
            for (int i = 0; i < 8; i++) a[i] = kp[nn * 256 + t_m + 32 * i];
            #pragma unroll
            for (int j = 0; j < 8; j++) b[j] = vs[nn * 68 + t_e + 8 * j];
            #pragma unroll
            for (int i = 0; i < 8; i++)
                #pragma unroll
                for (int j = 0; j < 8; j++) cacc[i][j] += a[i] * b[j];
            if (t_e == 0) {
                #pragma unroll
                for (int i = 0; i < 8; i++) ksacc[i] += a[i];
            }
        }
    }

    float* ctx = g_ctxraw + (size_t)head * MM * DD;
    #pragma unroll
    for (int i = 0; i < 8; i++)
        #pragma unroll
        for (int j = 0; j < 8; j++)
            atomicAdd(&ctx[(t_m + 32 * i) * 64 + t_e + 8 * j], cacc[i][j]);
    if (t_e == 0) {
        #pragma unroll
        for (int i = 0; i < 8; i++)
            atomicAdd(&g_ksumraw[head * MM + t_m + 32 * i], ksacc[i]);
    }
    if (tid >= 64 && tid < 128) atomicAdd(&g_vsum[head * DD + tid - 64], vsacc);

    red[tid] = lmax;
    __syncthreads();
    for (int s = 128; s > 0; s >>= 1) {
        if (tid < s) red[tid] = fmaxf(red[tid], red[tid + s]);
        __syncthreads();
    }
    if (tid == 0) atomicMax(&g_gmax[head], enc_f(red[0]));
}

// =============================================================== Kernel B
// Finalize: ctxf = e^{-gmax}·ctx_raw + eps·vsum ; ksumf = e^{-gmax}·ksum_raw + eps·N
__global__ void kB() {
    int head = blockIdx.x;
    int tid = threadIdx.x;
    float emx = fexp(-dec_f(g_gmax[head]));
    g_ksumf[head * MM + tid] = emx * g_ksumraw[head * MM + tid] + EPSILON * (float)NN;
    size_t base = (size_t)head * MM * DD;
    for (int i = tid; i < MM * DD; i += 256) {
        int e = i & 63;
        g_ctxf[base + i] = emx * g_ctxraw[base + i] + EPSILON * g_vsum[head * DD + e];
    }
}

// =============================================================== Kernel C
// Fused q-side: dash = (s*Q)·P^T ; w = exp(dash - diag - rowmax) + eps ;
// out = (w · ctxf) / (w · ksumf)        (ratio factors cancel)
// grid (8, NH), 256 thr, each block: 8 chunks of 64 rows.
#define C_SMEM ((64*256 + 256*64 + 64*256 + 64*68 + 256 + 64 + 64 + 256 + 256 + 64) * 4)
__global__ void __launch_bounds__(256, 1) kC(const float* __restrict__ Q,
                                             const float* __restrict__ P,
                                             float* __restrict__ out) {
    extern __shared__ float sm[];
    float* Pt   = sm;                  // [64][256]
    float* ctxs = Pt + 64 * 256;       // [256][64]
    float* dash = ctxs + 256 * 64;     // [64][256] -> w
    float* qs   = dash + 64 * 256;     // [64][68]
    float* ksums= qs + 64 * 68;        // [256]
    float* diag = ksums + 256;         // [64]
    float* mxs  = diag + 64;           // [64]
    float* pm   = mxs + 64;            // [64][4]
    float* pden = pm + 256;            // [64][4]
    float* dinv = pden + 256;          // [64]

    int tid  = threadIdx.x;
    int head = blockIdx.y;
    int rbase = blockIdx.x * 512;
    const float* qb = Q + (size_t)head * NN * DD;

    // persistent loads: P transposed (staged via qs), ctxf, ksumf
    for (int c = 0; c < 4; c++) {
        for (int i = tid; i < 64 * 64; i += 256) {
            int r = i >> 6, d = i & 63;
            qs[r * 65 + d] = P[(size_t)(c * 64 + r) * 64 + d];
        }
        __syncthreads();
        int m = tid & 63, q4 = tid >> 6;
        for (int d = q4; d < 64; d += 4)
            Pt[d * 256 + c * 64 + m] = qs[m * 65 + d];
        __syncthreads();
    }
    for (int i = tid; i < 256 * 64; i += 256) ctxs[i] = g_ctxf[(size_t)head * MM * DD + i];
    ksums[tid] = g_ksumf[head * MM + tid];

    int ty = tid >> 5, tx = tid & 31;       // dash GEMM layout
    int oy = tid >> 4, ox = tid & 15;       // out GEMM layout (4x4 micro, float4)

    for (int ch = 0; ch < 8; ch++) {
        int n0 = rbase + ch * 64;
        __syncthreads();
        for (int i = tid; i < 64 * 64; i += 256) {
            int r = i >> 6, d = i & 63;
            qs[r * 68 + d] = SCALE * qb[(size_t)(n0 + r) * 64 + d];
        }
        __syncthreads();
        if (tid < 64) {
            float s = 0.0f;
            #pragma unroll 8
            for (int d = 0; d < 64; d++) { float t = qs[tid * 68 + d]; s += t * t; }
            diag[tid] = 0.5f * s;
        }
        // ---- dash GEMM: dash[64][256] = qs(64x64) · Pt(64x256) ----
        {
            float dacc[8][8] = {};
            #pragma unroll 8
            for (int d = 0; d < 64; d++) {
                float a[8], b[8];
                #pragma unroll
                for (int i = 0; i < 8; i++) a[i] = qs[(ty + 8 * i) * 68 + d];
                #pragma unroll
                for (int j = 0; j < 8; j++) b[j] = Pt[d * 256 + tx + 32 * j];
                #pragma unroll
                for (int i = 0; i < 8; i++)
                    #pragma unroll
                    for (int j = 0; j < 8; j++) dacc[i][j] += a[i] * b[j];
            }
            #pragma unroll
            for (int i = 0; i < 8; i++)
                #pragma unroll
                for (int j = 0; j < 8; j++)
                    dash[(ty + 8 * i) * 256 + tx + 32 * j] = dacc[i][j];
        }
        __syncthreads();
        // ---- row max over 256 features ----
        {
            int r = tid >> 2, seg = tid & 3;
            float m = -1e30f;
            #pragma unroll 8
            for (int mm = seg * 64; mm < seg * 64 + 64; mm++) m = fmaxf(m, dash[r * 256 + mm]);
            pm[r * 4 + seg] = m;
        }
        __syncthreads();
        if (tid < 64)
            mxs[tid] = fmaxf(fmaxf(pm[tid * 4], pm[tid * 4 + 1]),
                             fmaxf(pm[tid * 4 + 2], pm[tid * 4 + 3]));
        __syncthreads();
        // ---- w = exp(dash - diag - rowmax) + eps (in place) ----
        #pragma unroll 8
        for (int r = 0; r < 64; r++) {
            int idx = r * 256 + tid;
            dash[idx] = fexp(dash[idx] - diag[r] - mxs[r]) + EPSILON;
        }
        __syncthreads();
        // ---- denominators: den[r] = Σ_m w·ksumf ----
        {
            int r = tid >> 2, seg = tid & 3;
            float s = 0.0f;
            #pragma unroll 8
            for (int mm = seg * 64; mm < seg * 64 + 64; mm++)
                s += dash[r * 256 + mm] * ksums[mm];
            pden[r * 4 + seg] = s;
        }
        __syncthreads();
        if (tid < 64)
            dinv[tid] = 1.0f / (pden[tid * 4] + pden[tid * 4 + 1] +
                                pden[tid * 4 + 2] + pden[tid * 4 + 3]);
        __syncthreads();
        // ---- out GEMM: out[64][64] = w(64x256) · ctxs(256x64), float4 duals ----
        {
            float oacc[4][4] = {};
            #pragma unroll 4
            for (int m = 0; m < 256; m += 4) {
                float4 a[4], b[4];
                #pragma unroll
                for (int i = 0; i < 4; i++)
                    a[i] = *reinterpret_cast<const float4*>(&dash[(oy * 4 + i) * 256 + m]);
                #pragma unroll
                for (int mm = 0; mm < 4; mm++)
                    b[mm] = *reinterpret_cast<const float4*>(&ctxs[(m + mm) * 64 + ox * 4]);
                #pragma unroll
                for (int i = 0; i < 4; i++) {
                    oacc[i][0] += a[i].x * b[0].x; oacc[i][1] += a[i].x * b[0].y;
                    oacc[i][2] += a[i].x * b[0].z; oacc[i][3] += a[i].x * b[0].w;
                    oacc[i][0] += a[i].y * b[1].x; oacc[i][1] += a[i].y * b[1].y;
                    oacc[i][2] += a[i].y * b[1].z; oacc[i][3] += a[i].y * b[1].w;
                    oacc[i][0] += a[i].z * b[2].x; oacc[i][1] += a[i].z * b[2].y;
                    oacc[i][2] += a[i].z * b[2].z; oacc[i][3] += a[i].z * b[2].w;
                    oacc[i][0] += a[i].w * b[3].x; oacc[i][1] += a[i].w * b[3].y;
                    oacc[i][2] += a[i].w * b[3].z; oacc[i][3] += a[i].w * b[3].w;
                }
            }
            float* ob = out + ((size_t)head * NN + n0) * DD;
            #pragma unroll
            for (int i = 0; i < 4; i++) {
                int r = oy * 4 + i;
                float di = dinv[r];
                float4 o;
                o.x = oacc[i][0] * di; o.y = oacc[i][1] * di;
                o.z = oacc[i][2] * di; o.w = oacc[i][3] * di;
                *reinterpret_cast<float4*>(&ob[(size_t)r * 64 + ox * 4]) = o;
            }
        }
    }
}

// ---------------------------------------------------------------- launch
extern "C" void kernel_launch(void* const* d_in, const int* in_sizes, int n_in,
                              void* d_out, int out_size) {
    const float* q = (const float*)d_in[0];
    const float* k = (const float*)d_in[1];
    const float* v = (const float*)d_in[2];
    const float* P = (const float*)d_in[3];
    float* out = (float*)d_out;

    cudaFuncSetAttribute(kA, cudaFuncAttributeMaxDynamicSharedMemorySize, A_SMEM);
    cudaFuncSetAttribute(kC, cudaFuncAttributeMaxDynamicSharedMemorySize, C_SMEM);

    k0_init<<<(NH * MM * DD + 255) / 256, 256>>>();
    kA<<<dim3(8, NH), 256, A_SMEM>>>(k, v, P);
    kB<<<NH, 256>>>();
    kC<<<dim3(8, NH), 256, C_SMEM>>>(q, P, out);
}

// round 7
// speedup vs baseline: 1.4934x; 1.4918x over previous
#include <cuda_runtime.h>
#include <cuda_bf16.h>
#include <stdint.h>

#define NH 64
#define NN 4096
#define DD 64
#define MM 256
#define SCALE   0.35355339059327379f   // 64^-0.25
#define EPSILON 1e-4f

// ---------------- scratch ----------------
__device__ float         g_ctxraw [NH*MM*DD];
__device__ float         g_ksumraw[NH*MM];
__device__ unsigned      g_gmax   [NH];
__device__ float         g_ksumf  [NH*MM];
__device__ __nv_bfloat16 g_Ph[MM*DD], g_Pl[MM*DD];        // P hi/lo [256 m][64 d]
__device__ __nv_bfloat16 g_Ch[NH*DD*MM], g_Cl[NH*DD*MM];  // ctx^T hi/lo [64 e][256 m] per head

// ---------------- helpers ----------------
__device__ __forceinline__ unsigned enc_f(float f) {
    unsigned u = __float_as_uint(f);
    return (u & 0x80000000u) ? ~u : (u | 0x80000000u);
}
__device__ __forceinline__ float dec_f(unsigned u) {
    return __uint_as_float((u & 0x80000000u) ? (u & 0x7fffffffu) : ~u);
}
__device__ __forceinline__ float fexp(float x) {
    float y = fmaxf(x * 1.4426950408889634f, -126.0f);
    float n = rintf(y);
    float f = y - n;
    float p = 1.5403530393381609e-4f;
    p = fmaf(p, f, 1.3333558146428443e-3f);
    p = fmaf(p, f, 9.6181291076284772e-3f);
    p = fmaf(p, f, 5.5504108664821580e-2f);
    p = fmaf(p, f, 2.4022650695910071e-1f);
    p = fmaf(p, f, 6.9314718055994531e-1f);
    p = fmaf(p, f, 1.0f);
    return p * __int_as_float(((int)n + 127) << 23);
}

// m16n8k16 bf16 MMA, f32 accumulate in place
__device__ __forceinline__ void MMA(float d[4], const uint32_t a[4], uint32_t b0, uint32_t b1) {
    asm volatile("mma.sync.aligned.m16n8k16.row.col.f32.bf16.bf16.f32 "
        "{%0,%1,%2,%3}, {%4,%5,%6,%7}, {%8,%9}, {%0,%1,%2,%3};"
        : "+f"(d[0]), "+f"(d[1]), "+f"(d[2]), "+f"(d[3])
        : "r"(a[0]), "r"(a[1]), "r"(a[2]), "r"(a[3]), "r"(b0), "r"(b1));
}
// A fragment from row-major bf16 smem. row = rowbase + (lane>>2). koff includes (lane&3)*2.
__device__ __forceinline__ void lda_frag(uint32_t a[4], const char* base, int row, int ld, int koff) {
    a[0] = *(const uint32_t*)(base + ((size_t)(row    )*ld + koff    )*2);
    a[1] = *(const uint32_t*)(base + ((size_t)(row + 8)*ld + koff    )*2);
    a[2] = *(const uint32_t*)(base + ((size_t)(row    )*ld + koff + 8)*2);
    a[3] = *(const uint32_t*)(base + ((size_t)(row + 8)*ld + koff + 8)*2);
}
// B fragment from Bt row-major [ncol][k]. col = colbase + (lane>>2). koff includes (lane&3)*2.
__device__ __forceinline__ void ldb_frag(uint32_t b[2], const char* base, int col, int ld, int koff) {
    b[0] = *(const uint32_t*)(base + ((size_t)col*ld + koff    )*2);
    b[1] = *(const uint32_t*)(base + ((size_t)col*ld + koff + 8)*2);
}

// ---------------- K0: init ----------------
__global__ void k0_init() {
    int i = blockIdx.x * blockDim.x + threadIdx.x;
    if (i < NH*MM*DD) g_ctxraw[i] = 0.0f;
    if (i < NH*MM)    g_ksumraw[i] = 0.0f;
    if (i < NH)       g_gmax[i] = enc_f(-1e30f);
}

// ---------------- kP: P bf16 hi/lo images ----------------
__global__ void kP(const float* __restrict__ P) {
    int i = blockIdx.x * 256 + threadIdx.x;
    float p = P[i];
    __nv_bfloat16 h = __float2bfloat16(p);
    g_Ph[i] = h;
    g_Pl[i] = __float2bfloat16(p - __bfloat162float(h));
}

// =============== kA: k-side fused (dash MMA -> exp -> ctx MMA) ===============
// smem byte offsets
#define A_PH   0        // [256][72] bf16
#define A_PL   36864
#define A_KH   73728    // [128][72]
#define A_KL   92160
#define A_VH   110592   // [64][136]  (V^T)
#define A_VL   128000
#define A_W    145408   // [256][136] bf16 (w^T)
#define A_DIAG 215040   // 128 f32
#define A_KSUM 215552   // 256 f32
#define A_RED  216576   // 256 f32
#define A_SIZE 217600

__global__ void __launch_bounds__(256, 1) kA(const float* __restrict__ K,
                                             const float* __restrict__ V) {
    extern __shared__ char smx[];
    int tid = threadIdx.x, wid = tid >> 5, lane = tid & 31;
    int lr = lane >> 2, qk = (lane & 3) * 2;
    int head = blockIdx.y;
    const float* kb = K + (size_t)head * NN * DD;
    const float* vb = V + (size_t)head * NN * DD;

    char* PH = smx + A_PH; char* PL = smx + A_PL;
    char* KH = smx + A_KH; char* KL = smx + A_KL;
    char* VH = smx + A_VH; char* VL = smx + A_VL;
    char* W  = smx + A_W;
    float* diag_s = (float*)(smx + A_DIAG);
    float* ksum_s = (float*)(smx + A_KSUM);
    float* red    = (float*)(smx + A_RED);

    // persistent P images (repad 64 -> 72 elems/row), word copies
    for (int i = tid; i < 256 * 32; i += 256) {
        int m = i >> 5, dw = i & 31;
        ((uint32_t*)PH)[m * 36 + dw] = ((const uint32_t*)g_Ph)[i];
        ((uint32_t*)PL)[m * 36 + dw] = ((const uint32_t*)g_Pl)[i];
    }
    ksum_s[tid] = 0.0f;

    float cacc[2][8][4] = {};
    float lmax = -1e30f;
    int nbw = (wid & 3) * 32, mbw = (wid >> 2) * 128;

    for (int ch = 0; ch < 4; ch++) {
        int n0 = blockIdx.x * 512 + ch * 128;
        __syncthreads();
        // K hi/lo images (scaled)
        for (int i = tid; i < 128 * 64; i += 256) {
            int n = i >> 6, d = i & 63;
            float kv = SCALE * kb[(size_t)(n0 + n) * 64 + d];
            __nv_bfloat16 h = __float2bfloat16(kv);
            *(__nv_bfloat16*)(KH + (n * 72 + d) * 2) = h;
            *(__nv_bfloat16*)(KL + (n * 72 + d) * 2) = __float2bfloat16(kv - __bfloat162float(h));
        }
        // V^T hi/lo images
        for (int i = tid; i < 64 * 128; i += 256) {
            int e = i >> 7, n = i & 127;
            float vv = vb[(size_t)(n0 + n) * 64 + e];
            __nv_bfloat16 h = __float2bfloat16(vv);
            *(__nv_bfloat16*)(VH + (e * 136 + n) * 2) = h;
            *(__nv_bfloat16*)(VL + (e * 136 + n) * 2) = __float2bfloat16(vv - __bfloat162float(h));
        }
        __syncthreads();
        if (tid < 128) {   // diag[n]
            float s = 0.0f;
            #pragma unroll 8
            for (int d = 0; d < 64; d++) {
                float kh = __bfloat162float(*(__nv_bfloat16*)(KH + (tid * 72 + d) * 2));
                float kl = __bfloat162float(*(__nv_bfloat16*)(KL + (tid * 72 + d) * 2));
                float kv = kh + kl;
                s += kv * kv;
            }
            diag_s[tid] = 0.5f * s;
        }
        __syncthreads();
        // ---- dash MMA + exp epilogue: D[n][m] = Ks . P^T (3-split) ----
        for (int rt = 0; rt < 2; rt++) {
            int arow = nbw + rt * 16 + lr;
            int nr = arow;
            float dg0 = diag_s[nbw + rt * 16 + lr];
            float dg1 = diag_s[nbw + rt * 16 + lr + 8];
            for (int half = 0; half < 2; half++) {
                float acc[8][4] = {};
                for (int ks = 0; ks < 4; ks++) {
                    uint32_t ah[4], al[4];
                    lda_frag(ah, KH, arow, 72, ks * 16 + qk);
                    lda_frag(al, KL, arow, 72, ks * 16 + qk);
                    #pragma unroll
                    for (int ct = 0; ct < 8; ct++) {
                        int bcol = mbw + half * 64 + ct * 8 + lr;
                        uint32_t bh[2], bl[2];
                        ldb_frag(bh, PH, bcol, 72, ks * 16 + qk);
                        ldb_frag(bl, PL, bcol, 72, ks * 16 + qk);
                        MMA(acc[ct], ah, bh[0], bh[1]);
                        MMA(acc[ct], ah, bl[0], bl[1]);
                        MMA(acc[ct], al, bh[0], bh[1]);
                    }
                }
                #pragma unroll
                for (int ct = 0; ct < 8; ct++) {
                    int mc = mbw + half * 64 + ct * 8 + qk;
                    float d0 = acc[ct][0], d1 = acc[ct][1], d2 = acc[ct][2], d3 = acc[ct][3];
                    lmax = fmaxf(lmax, fmaxf(fmaxf(d0, d1), fmaxf(d2, d3)));
                    float w0 = fexp(d0 - dg0), w1 = fexp(d1 - dg0);
                    float w2 = fexp(d2 - dg1), w3 = fexp(d3 - dg1);
                    *(__nv_bfloat16*)(W + ((size_t)mc * 136 + nr) * 2)           = __float2bfloat16(w0);
                    *(__nv_bfloat16*)(W + ((size_t)(mc + 1) * 136 + nr) * 2)     = __float2bfloat16(w1);
                    *(__nv_bfloat16*)(W + ((size_t)mc * 136 + nr + 8) * 2)       = __float2bfloat16(w2);
                    *(__nv_bfloat16*)(W + ((size_t)(mc + 1) * 136 + nr + 8) * 2) = __float2bfloat16(w3);
                    float s0 = w0 + w2, s1 = w1 + w3;
                    s0 += __shfl_xor_sync(0xffffffffu, s0, 4);
                    s0 += __shfl_xor_sync(0xffffffffu, s0, 8);
                    s0 += __shfl_xor_sync(0xffffffffu, s0, 16);
                    s1 += __shfl_xor_sync(0xffffffffu, s1, 4);
                    s1 += __shfl_xor_sync(0xffffffffu, s1, 8);
                    s1 += __shfl_xor_sync(0xffffffffu, s1, 16);
                    if (lane < 4) {
                        atomicAdd(&ksum_s[mc], s0);
                        atomicAdd(&ksum_s[mc + 1], s1);
                    }
                }
            }
        }
        __syncthreads();
        // ---- ctx MMA: cacc[m][e] += w^T . V  (w single x v hi/lo) ----
        for (int ks = 0; ks < 8; ks++) {
            uint32_t aw0[4], aw1[4];
            lda_frag(aw0, W, wid * 32 + lr,      136, ks * 16 + qk);
            lda_frag(aw1, W, wid * 32 + 16 + lr, 136, ks * 16 + qk);
            #pragma unroll
            for (int et = 0; et < 8; et++) {
                int ec = et * 8 + lr;
                uint32_t bh[2], bl[2];
                ldb_frag(bh, VH, ec, 136, ks * 16 + qk);
                ldb_frag(bl, VL, ec, 136, ks * 16 + qk);
                MMA(cacc[0][et], aw0, bh[0], bh[1]);
                MMA(cacc[0][et], aw0, bl[0], bl[1]);
                MMA(cacc[1][et], aw1, bh[0], bh[1]);
                MMA(cacc[1][et], aw1, bl[0], bl[1]);
            }
        }
    }
    // ---- flush ----
    __syncthreads();
    atomicAdd(&g_ksumraw[head * MM + tid], ksum_s[tid]);
    red[tid] = lmax;
    __syncthreads();
    for (int s = 128; s > 0; s >>= 1) {
        if (tid < s) red[tid] = fmaxf(red[tid], red[tid + s]);
        __syncthreads();
    }
    if (tid == 0) atomicMax(&g_gmax[head], enc_f(red[0]));
    float* ctx = g_ctxraw + (size_t)head * MM * DD;
    #pragma unroll
    for (int rt2 = 0; rt2 < 2; rt2++) {
        int m = wid * 32 + rt2 * 16 + lr;
        #pragma unroll
        for (int et = 0; et < 8; et++) {
            int e = et * 8 + qk;
            atomicAdd(&ctx[m * 64 + e],           cacc[rt2][et][0]);
            atomicAdd(&ctx[m * 64 + e + 1],       cacc[rt2][et][1]);
            atomicAdd(&ctx[(m + 8) * 64 + e],     cacc[rt2][et][2]);
            atomicAdd(&ctx[(m + 8) * 64 + e + 1], cacc[rt2][et][3]);
        }
    }
}

// =============== kB: finalize; build ctx^T hi/lo images ===============
__global__ void kB(const float* __restrict__ V) {
    int head = blockIdx.x, tid = threadIdx.x;
    __shared__ float vsum_s[64];
    if (tid < 64) vsum_s[tid] = 0.0f;
    __syncthreads();
    {
        int e = tid & 63, q = tid >> 6;
        const float* vb = V + (size_t)head * NN * DD;
        float part = 0.0f;
        for (int j = 0; j < 1024; j++) part += vb[(size_t)(4 * j + q) * 64 + e];
        atomicAdd(&vsum_s[e], part);
    }
    __syncthreads();
    float emx = fexp(-dec_f(g_gmax[head]));
    g_ksumf[head * MM + tid] = emx * g_ksumraw[head * MM + tid] + EPSILON * (float)NN;
    for (int i = tid; i < MM * DD; i += 256) {
        int m = i >> 6, e = i & 63;
        float cf = emx * g_ctxraw[(size_t)head * MM * DD + i] + EPSILON * vsum_s[e];
        __nv_bfloat16 h = __float2bfloat16(cf);
        g_Ch[(size_t)head * 16384 + e * 256 + m] = h;
        g_Cl[(size_t)head * 16384 + e * 256 + m] = __float2bfloat16(cf - __bfloat162float(h));
    }
}

// =============== kC: q-side fused (dash MMA -> max/exp/den -> out MMA) ===============
#define C_PH   0        // [256][72] bf16
#define C_PL   36864
#define C_CH   73728    // [64][264] bf16 (ctx^T)
#define C_CL   107520
#define C_QH   141312   // [32][72]
#define C_QL   145920
#define C_DASH 150528   // [32][264] f32
#define C_W    184320   // [32][264] bf16
#define C_KSUM 201216   // 256 f32
#define C_DIAG 202240   // 32 f32
#define C_MX   202368   // 32 f32
#define C_PM   202496   // 32*8 f32
#define C_PDEN 203520   // 32*8 f32
#define C_DINV 204544   // 32 f32
#define C_SIZE 204672

__global__ void __launch_bounds__(256, 1) kC(const float* __restrict__ Q,
                                             float* __restrict__ out) {
    extern __shared__ char smx[];
    int tid = threadIdx.x, wid = tid >> 5, lane = tid & 31;
    int lr = lane >> 2, qk = (lane & 3) * 2;
    int head = blockIdx.y;
    const float* qb = Q + (size_t)head * NN * DD;

    char* PH = smx + C_PH; char* PL = smx + C_PL;
    char* CH = smx + C_CH; char* CL = smx + C_CL;
    char* QH = smx + C_QH; char* QL = smx + C_QL;
    float* dash   = (float*)(smx + C_DASH);
    char*  WB     = smx + C_W;
    float* ksum_s = (float*)(smx + C_KSUM);
    float* diag_s = (float*)(smx + C_DIAG);
    float* mxs    = (float*)(smx + C_MX);
    float* pm     = (float*)(smx + C_PM);
    float* pden   = (float*)(smx + C_PDEN);
    float* dinv_s = (float*)(smx + C_DINV);

    // persistent images
    for (int i = tid; i < 256 * 32; i += 256) {
        int m = i >> 5, dw = i & 31;
        ((uint32_t*)PH)[m * 36 + dw] = ((const uint32_t*)g_Ph)[i];
        ((uint32_t*)PL)[m * 36 + dw] = ((const uint32_t*)g_Pl)[i];
    }
    for (int i = tid; i < 64 * 128; i += 256) {   // ctx^T repad 256 -> 264
        int e = i >> 7, mw = i & 127;
        ((uint32_t*)CH)[e * 132 + mw] = ((const uint32_t*)(g_Ch + (size_t)head * 16384))[i];
        ((uint32_t*)CL)[e * 132 + mw] = ((const uint32_t*)(g_Cl + (size_t)head * 16384))[i];
    }
    ksum_s[tid] = g_ksumf[head * MM + tid];

    int rt = wid & 1;                 // dash row-tile (16 rows)
    int mbw = (wid >> 1) * 64;        // dash m range (8 coltiles)
    int ebase = (wid >> 1) * 16;      // out e range (2 coltiles)

    for (int ch = 0; ch < 8; ch++) {
        int n0 = blockIdx.x * 256 + ch * 32;
        __syncthreads();
        // Q hi/lo images (scaled)
        for (int i = tid; i < 32 * 64; i += 256) {
            int n = i >> 6, d = i & 63;
            float qv = SCALE * qb[(size_t)(n0 + n) * 64 + d];
            __nv_bfloat16 h = __float2bfloat16(qv);
            *(__nv_bfloat16*)(QH + (n * 72 + d) * 2) = h;
            *(__nv_bfloat16*)(QL + (n * 72 + d) * 2) = __float2bfloat16(qv - __bfloat162float(h));
        }
        __syncthreads();
        if (tid < 32) {   // diag[n]
            float s = 0.0f;
            #pragma unroll 8
            for (int d = 0; d < 64; d++) {
                float qh = __bfloat162float(*(__nv_bfloat16*)(QH + (tid * 72 + d) * 2));
                float ql = __bfloat162float(*(__nv_bfloat16*)(QL + (tid * 72 + d) * 2));
                float qv = qh + ql;
                s += qv * qv;
            }
            diag_s[tid] = 0.5f * s;
        }
        // ---- dash MMA: D[n][m] = Qs . P^T (3-split) ----
        {
            float acc[8][4] = {};
            int arow = rt * 16 + lr;
            for (int ks = 0; ks < 4; ks++) {
                uint32_t ah[4], al[4];
                lda_frag(ah, QH, arow, 72, ks * 16 + qk);
                lda_frag(al, QL, arow, 72, ks * 16 + qk);
                #pragma unroll
                for (int ct = 0; ct < 8; ct++) {
                    int bcol = mbw + ct * 8 + lr;
                    uint32_t bh[2], bl[2];
                    ldb_frag(bh, PH, bcol, 72, ks * 16 + qk);
                    ldb_frag(bl, PL, bcol, 72, ks * 16 + qk);
                    MMA(acc[ct], ah, bh[0], bh[1]);
                    MMA(acc[ct], ah, bl[0], bl[1]);
                    MMA(acc[ct], al, bh[0], bh[1]);
                }
            }
            #pragma unroll
            for (int ct = 0; ct < 8; ct++) {
                int mc = mbw + ct * 8 + qk;
                *(float2*)&dash[(size_t)(arow)     * 264 + mc] = make_float2(acc[ct][0], acc[ct][1]);
                *(float2*)&dash[(size_t)(arow + 8) * 264 + mc] = make_float2(acc[ct][2], acc[ct][3]);
            }
        }
        __syncthreads();
        {   // row max
            int r = tid >> 3, seg = tid & 7;
            float m = -1e30f;
            #pragma unroll 8
            for (int mm = seg * 32; mm < seg * 32 + 32; mm++) m = fmaxf(m, dash[r * 264 + mm]);
            pm[r * 8 + seg] = m;
        }
        __syncthreads();
        if (tid < 32) {
            float m = -1e30f;
            #pragma unroll
            for (int s = 0; s < 8; s++) m = fmaxf(m, pm[tid * 8 + s]);
            mxs[tid] = m;
        }
        __syncthreads();
        // exp: thread = column m, loop rows
        for (int r = 0; r < 32; r++) {
            float w = fexp(dash[r * 264 + tid] - diag_s[r] - mxs[r]) + EPSILON;
            *(__nv_bfloat16*)(WB + (r * 264 + tid) * 2) = __float2bfloat16(w);
        }
        __syncthreads();
        {   // denominators from bf16 w (consistent with numerator GEMM)
            int r = tid >> 3, seg = tid & 7;
            float s = 0.0f;
            #pragma unroll 8
            for (int mm = seg * 32; mm < seg * 32 + 32; mm++)
                s += __bfloat162float(*(__nv_bfloat16*)(WB + (r * 264 + mm) * 2)) * ksum_s[mm];
            pden[r * 8 + seg] = s;
        }
        __syncthreads();
        if (tid < 32) {
            float s = 0.0f;
            #pragma unroll
            for (int j = 0; j < 8; j++) s += pden[tid * 8 + j];
            dinv_s[tid] = 1.0f / s;
        }
        __syncthreads();
        // ---- out MMA: D[n][e] = w . ctx (w single x ctx hi/lo), k = 256 ----
        {
            float oacc[2][4] = {};
            int arow = rt * 16 + lr;
            for (int ks = 0; ks < 16; ks++) {
                uint32_t aw[4];
                lda_frag(aw, WB, arow, 264, ks * 16 + qk);
                #pragma unroll
                for (int ct = 0; ct < 2; ct++) {
                    int ec = ebase + ct * 8 + lr;
                    uint32_t bh[2], bl[2];
                    ldb_frag(bh, CH, ec, 264, ks * 16 + qk);
                    ldb_frag(bl, CL, ec, 264, ks * 16 + qk);
                    MMA(oacc[ct], aw, bh[0], bh[1]);
                    MMA(oacc[ct], aw, bl[0], bl[1]);
                }
            }
            float di0 = dinv_s[rt * 16 + lr];
            float di1 = dinv_s[rt * 16 + lr + 8];
            int nr = n0 + rt * 16 + lr;
            #pragma unroll
            for (int ct = 0; ct < 2; ct++) {
                int e = ebase + ct * 8 + qk;
                float* ob0 = out + ((size_t)head * NN + nr) * 64 + e;
                float* ob1 = out + ((size_t)head * NN + nr + 8) * 64 + e;
                ob0[0] = oacc[ct][0] * di0;
                ob0[1] = oacc[ct][1] * di0;
                ob1[0] = oacc[ct][2] * di1;
                ob1[1] = oacc[ct][3] * di1;
            }
        }
    }
}

// ---------------- launch ----------------
extern "C" void kernel_launch(void* const* d_in, const int* in_sizes, int n_in,
                              void* d_out, int out_size) {
    const float* q = (const float*)d_in[0];
    const float* k = (const float*)d_in[1];
    const float* v = (const float*)d_in[2];
    const float* P = (const float*)d_in[3];
    float* out = (float*)d_out;

    cudaFuncSetAttribute(kA, cudaFuncAttributeMaxDynamicSharedMemorySize, A_SIZE);
    cudaFuncSetAttribute(kC, cudaFuncAttributeMaxDynamicSharedMemorySize, C_SIZE);

    k0_init<<<(NH * MM * DD + 255) / 256, 256>>>();
    kP<<<64, 256>>>(P);
    kA<<<dim3(8, NH), 256, A_SIZE>>>(k, v);
    kB<<<NH, 256>>>(v);
    kC<<<dim3(16, NH), 256, C_SIZE>>>(q, out);
}

// round 8
// speedup vs baseline: 1.6736x; 1.1207x over previous
#include <cuda_runtime.h>
#include <cuda_bf16.h>
#include <stdint.h>

#define NH 64
#define NN 4096
#define DD 64
#define MM 256
#define SCALE   0.35355339059327379f   // 64^-0.25
#define EPSILON 1e-4f

// ---------------- scratch ----------------
__device__ float         g_ctxraw [NH*MM*DD];
__device__ float         g_ksumraw[NH*MM];
__device__ float         g_vsum   [NH*DD];
__device__ unsigned      g_gmax   [NH];
__device__ float         g_ksumf  [NH*MM];
__device__ __nv_bfloat16 g_Ph[MM*DD], g_Pl[MM*DD];        // P hi/lo [256 m][64 d]
__device__ __nv_bfloat16 g_Ch[NH*DD*MM], g_Cl[NH*DD*MM];  // ctx^T hi/lo [64 e][256 m] per head

// ---------------- helpers ----------------
__device__ __forceinline__ unsigned enc_f(float f) {
    unsigned u = __float_as_uint(f);
    return (u & 0x80000000u) ? ~u : (u | 0x80000000u);
}
__device__ __forceinline__ float dec_f(unsigned u) {
    return __uint_as_float((u & 0x80000000u) ? (u & 0x7fffffffu) : ~u);
}
__device__ __forceinline__ float fexp(float x) {
    float y = fmaxf(x * 1.4426950408889634f, -126.0f);
    float n = rintf(y);
    float f = y - n;
    float p = 1.5403530393381609e-4f;
    p = fmaf(p, f, 1.3333558146428443e-3f);
    p = fmaf(p, f, 9.6181291076284772e-3f);
    p = fmaf(p, f, 5.5504108664821580e-2f);
    p = fmaf(p, f, 2.4022650695910071e-1f);
    p = fmaf(p, f, 6.9314718055994531e-1f);
    p = fmaf(p, f, 1.0f);
    return p * __int_as_float(((int)n + 127) << 23);
}
__device__ __forceinline__ void MMA(float d[4], const uint32_t a[4], uint32_t b0, uint32_t b1) {
    asm volatile("mma.sync.aligned.m16n8k16.row.col.f32.bf16.bf16.f32 "
        "{%0,%1,%2,%3}, {%4,%5,%6,%7}, {%8,%9}, {%0,%1,%2,%3};"
        : "+f"(d[0]), "+f"(d[1]), "+f"(d[2]), "+f"(d[3])
        : "r"(a[0]), "r"(a[1]), "r"(a[2]), "r"(a[3]), "r"(b0), "r"(b1));
}
__device__ __forceinline__ void lda_frag(uint32_t a[4], const char* base, int row, int ld, int koff) {
    a[0] = *(const uint32_t*)(base + ((size_t)(row    )*ld + koff    )*2);
    a[1] = *(const uint32_t*)(base + ((size_t)(row + 8)*ld + koff    )*2);
    a[2] = *(const uint32_t*)(base + ((size_t)(row    )*ld + koff + 8)*2);
    a[3] = *(const uint32_t*)(base + ((size_t)(row + 8)*ld + koff + 8)*2);
}
__device__ __forceinline__ void ldb_frag(uint32_t b[2], const char* base, int col, int ld, int koff) {
    b[0] = *(const uint32_t*)(base + ((size_t)col*ld + koff    )*2);
    b[1] = *(const uint32_t*)(base + ((size_t)col*ld + koff + 8)*2);
}

// ---------------- K0: init ----------------
__global__ void k0_init() {
    int i = blockIdx.x * blockDim.x + threadIdx.x;
    if (i < NH*MM*DD) g_ctxraw[i] = 0.0f;
    if (i < NH*MM)    g_ksumraw[i] = 0.0f;
    if (i < NH*DD)    g_vsum[i] = 0.0f;
    if (i < NH)       g_gmax[i] = enc_f(-1e30f);
}

// ---------------- kP: P bf16 hi/lo images ----------------
__global__ void kP(const float* __restrict__ P) {
    int i = blockIdx.x * 256 + threadIdx.x;
    float p = P[i];
    __nv_bfloat16 h = __float2bfloat16(p);
    g_Ph[i] = h;
    g_Pl[i] = __float2bfloat16(p - __bfloat162float(h));
}

// =============== kA: k-side fused (dash MMA -> exp -> ctx MMA), 512 thr ===============
#define A_PH   0        // [256][72] bf16
#define A_PL   36864
#define A_KH   73728    // [128][72]
#define A_KL   92160
#define A_VH   110592   // [64][136]  (V^T)
#define A_VL   128000
#define A_W    145408   // [256][136] bf16 (w^T)
#define A_DIAG 215040   // 128 f32
#define A_KSUM 215552   // 256 f32
#define A_RED  216576   // 512 f32
#define A_VS   218624   // 64 f32
#define A_SIZE 218880

__global__ void __launch_bounds__(512, 1) kA(const float* __restrict__ K,
                                             const float* __restrict__ V) {
    extern __shared__ char smx[];
    int tid = threadIdx.x, wid = tid >> 5, lane = tid & 31;
    int lr = lane >> 2, qk = (lane & 3) * 2;
    int head = blockIdx.y;
    const float* kb = K + (size_t)head * NN * DD;
    const float* vb = V + (size_t)head * NN * DD;

    char* PH = smx + A_PH; char* PL = smx + A_PL;
    char* KH = smx + A_KH; char* KL = smx + A_KL;
    char* VH = smx + A_VH; char* VL = smx + A_VL;
    char* W  = smx + A_W;
    float* diag_s = (float*)(smx + A_DIAG);
    float* ksum_s = (float*)(smx + A_KSUM);
    float* red    = (float*)(smx + A_RED);
    float* vsum_s = (float*)(smx + A_VS);

    for (int i = tid; i < 256 * 32; i += 512) {
        int m = i >> 5, dw = i & 31;
        ((uint32_t*)PH)[m * 36 + dw] = ((const uint32_t*)g_Ph)[i];
        ((uint32_t*)PL)[m * 36 + dw] = ((const uint32_t*)g_Pl)[i];
    }
    if (tid < 256) ksum_s[tid] = 0.0f;
    if (tid < 64)  vsum_s[tid] = 0.0f;

    float cacc[8][4] = {};
    float lmax = -1e30f;
    int nq = (wid & 3) * 32, mq = (wid >> 2) * 64;   // dash warp tile: 32n x 64m

    for (int ch = 0; ch < 4; ch++) {
        int n0 = blockIdx.x * 512 + ch * 128;
        __syncthreads();
        for (int i = tid; i < 128 * 64; i += 512) {
            int n = i >> 6, d = i & 63;
            float kv = SCALE * kb[(size_t)(n0 + n) * 64 + d];
            __nv_bfloat16 h = __float2bfloat16(kv);
            *(__nv_bfloat16*)(KH + (n * 72 + d) * 2) = h;
            *(__nv_bfloat16*)(KL + (n * 72 + d) * 2) = __float2bfloat16(kv - __bfloat162float(h));
        }
        for (int i = tid; i < 64 * 128; i += 512) {
            int e = i >> 7, n = i & 127;   // e uniform across warp
            float vv = vb[(size_t)(n0 + n) * 64 + e];
            __nv_bfloat16 h = __float2bfloat16(vv);
            *(__nv_bfloat16*)(VH + (e * 136 + n) * 2) = h;
            *(__nv_bfloat16*)(VL + (e * 136 + n) * 2) = __float2bfloat16(vv - __bfloat162float(h));
            float s = vv;
            s += __shfl_xor_sync(0xffffffffu, s, 1);
            s += __shfl_xor_sync(0xffffffffu, s, 2);
            s += __shfl_xor_sync(0xffffffffu, s, 4);
            s += __shfl_xor_sync(0xffffffffu, s, 8);
            s += __shfl_xor_sync(0xffffffffu, s, 16);
            if (lane == 0) atomicAdd(&vsum_s[e], s);
        }
        __syncthreads();
        if (tid < 128) {   // diag[n]
            float s = 0.0f;
            #pragma unroll 8
            for (int d = 0; d < 64; d++) {
                float kh = __bfloat162float(*(__nv_bfloat16*)(KH + (tid * 72 + d) * 2));
                float kl = __bfloat162float(*(__nv_bfloat16*)(KL + (tid * 72 + d) * 2));
                float kv = kh + kl;
                s += kv * kv;
            }
            diag_s[tid] = 0.5f * s;
        }
        __syncthreads();
        // ---- dash MMA + exp epilogue: D[n][m] = Ks . P^T (3-split) ----
        for (int rt = 0; rt < 2; rt++) {
            int arow = nq + rt * 16 + lr;
            float dg0 = diag_s[arow], dg1 = diag_s[arow + 8];
            float acc[8][4] = {};
            for (int ks = 0; ks < 4; ks++) {
                uint32_t ah[4], al[4];
                lda_frag(ah, KH, arow, 72, ks * 16 + qk);
                lda_frag(al, KL, arow, 72, ks * 16 + qk);
                #pragma unroll
                for (int ct = 0; ct < 8; ct++) {
                    int bcol = mq + ct * 8 + lr;
                    uint32_t bh[2], bl[2];
                    ldb_frag(bh, PH, bcol, 72, ks * 16 + qk);
                    ldb_frag(bl, PL, bcol, 72, ks * 16 + qk);
                    MMA(acc[ct], ah, bh[0], bh[1]);
                    MMA(acc[ct], ah, bl[0], bl[1]);
                    MMA(acc[ct], al, bh[0], bh[1]);
                }
            }
            #pragma unroll
            for (int ct = 0; ct < 8; ct++) {
                int mc = mq + ct * 8 + qk;
                float d0 = acc[ct][0], d1 = acc[ct][1], d2 = acc[ct][2], d3 = acc[ct][3];
                lmax = fmaxf(lmax, fmaxf(fmaxf(d0, d1), fmaxf(d2, d3)));
                float w0 = fexp(d0 - dg0), w1 = fexp(d1 - dg0);
                float w2 = fexp(d2 - dg1), w3 = fexp(d3 - dg1);
                *(__nv_bfloat16*)(W + ((size_t)mc * 136 + arow) * 2)           = __float2bfloat16(w0);
                *(__nv_bfloat16*)(W + ((size_t)(mc + 1) * 136 + arow) * 2)     = __float2bfloat16(w1);
                *(__nv_bfloat16*)(W + ((size_t)mc * 136 + arow + 8) * 2)       = __float2bfloat16(w2);
                *(__nv_bfloat16*)(W + ((size_t)(mc + 1) * 136 + arow + 8) * 2) = __float2bfloat16(w3);
                float s0 = w0 + w2, s1 = w1 + w3;
                s0 += __shfl_xor_sync(0xffffffffu, s0, 4);
                s0 += __shfl_xor_sync(0xffffffffu, s0, 8);
                s0 += __shfl_xor_sync(0xffffffffu, s0, 16);
                s1 += __shfl_xor_sync(0xffffffffu, s1, 4);
                s1 += __shfl_xor_sync(0xffffffffu, s1, 8);
                s1 += __shfl_xor_sync(0xffffffffu, s1, 16);
                if (lane < 4) {
                    atomicAdd(&ksum_s[mc], s0);
                    atomicAdd(&ksum_s[mc + 1], s1);
                }
            }
        }
        __syncthreads();
        // ---- ctx MMA: warp = 16 m rows x 64 e, k=128n ----
        for (int ks = 0; ks < 8; ks++) {
            uint32_t aw[4];
            lda_frag(aw, W, wid * 16 + lr, 136, ks * 16 + qk);
            #pragma unroll
            for (int et = 0; et < 8; et++) {
                int ec = et * 8 + lr;
                uint32_t bh[2], bl[2];
                ldb_frag(bh, VH, ec, 136, ks * 16 + qk);
                ldb_frag(bl, VL, ec, 136, ks * 16 + qk);
                MMA(cacc[et], aw, bh[0], bh[1]);
                MMA(cacc[et], aw, bl[0], bl[1]);
            }
        }
    }
    // ---- flush ----
    __syncthreads();
    if (tid < 256) atomicAdd(&g_ksumraw[head * MM + tid], ksum_s[tid]);
    if (tid < 64)  atomicAdd(&g_vsum[head * DD + tid], vsum_s[tid]);
    red[tid] = lmax;
    __syncthreads();
    for (int s = 256; s > 0; s >>= 1) {
        if (tid < s) red[tid] = fmaxf(red[tid], red[tid + s]);
        __syncthreads();
    }
    if (tid == 0) atomicMax(&g_gmax[head], enc_f(red[0]));
    float* ctx = g_ctxraw + (size_t)head * MM * DD;
    {
        int m = wid * 16 + lr;
        #pragma unroll
        for (int et = 0; et < 8; et++) {
            int e = et * 8 + qk;
            atomicAdd(&ctx[m * 64 + e],           cacc[et][0]);
            atomicAdd(&ctx[m * 64 + e + 1],       cacc[et][1]);
            atomicAdd(&ctx[(m + 8) * 64 + e],     cacc[et][2]);
            atomicAdd(&ctx[(m + 8) * 64 + e + 1], cacc[et][3]);
        }
    }
}

// =============== kB: finalize (vsum precomputed in kA) ===============
__global__ void kB() {
    int head = blockIdx.x, tid = threadIdx.x;
    float emx = fexp(-dec_f(g_gmax[head]));
    g_ksumf[head * MM + tid] = emx * g_ksumraw[head * MM + tid] + EPSILON * (float)NN;
    for (int i = tid; i < MM * DD; i += 256) {
        int m = i >> 6, e = i & 63;
        float cf = emx * g_ctxraw[(size_t)head * MM * DD + i] + EPSILON * g_vsum[head * DD + e];
        __nv_bfloat16 h = __float2bfloat16(cf);
        g_Ch[(size_t)head * 16384 + e * 256 + m] = h;
        g_Cl[(size_t)head * 16384 + e * 256 + m] = __float2bfloat16(cf - __bfloat162float(h));
    }
}

// =============== kC: q-side fused, 512 thr ===============
#define C_PH   0        // [256][72] bf16
#define C_PL   36864
#define C_CH   73728    // [64][264] bf16 (ctx^T)
#define C_CL   107520
#define C_QH   141312   // [32][72]
#define C_QL   145920
#define C_DASH 150528   // [32][264] f32
#define C_W    184320   // [32][264] bf16
#define C_KSUM 201216   // 256 f32
#define C_DIAG 202240   // 32 f32
#define C_MX   202368   // 32 f32
#define C_PM   202496   // 32*16 f32
#define C_PDEN 204544   // 32*16 f32
#define C_DINV 206592   // 32 f32
#define C_SIZE 206720

__global__ void __launch_bounds__(512, 1) kC(const float* __restrict__ Q,
                                             float* __restrict__ out) {
    extern __shared__ char smx[];
    int tid = threadIdx.x, wid = tid >> 5, lane = tid & 31;
    int lr = lane >> 2, qk = (lane & 3) * 2;
    int head = blockIdx.y;
    const float* qb = Q + (size_t)head * NN * DD;

    char* PH = smx + C_PH; char* PL = smx + C_PL;
    char* CH = smx + C_CH; char* CL = smx + C_CL;
    char* QH = smx + C_QH; char* QL = smx + C_QL;
    float* dash   = (float*)(smx + C_DASH);
    char*  WB     = smx + C_W;
    float* ksum_s = (float*)(smx + C_KSUM);
    float* diag_s = (float*)(smx + C_DIAG);
    float* mxs    = (float*)(smx + C_MX);
    float* pm     = (float*)(smx + C_PM);
    float* pden   = (float*)(smx + C_PDEN);
    float* dinv_s = (float*)(smx + C_DINV);

    for (int i = tid; i < 256 * 32; i += 512) {
        int m = i >> 5, dw = i & 31;
        ((uint32_t*)PH)[m * 36 + dw] = ((const uint32_t*)g_Ph)[i];
        ((uint32_t*)PL)[m * 36 + dw] = ((const uint32_t*)g_Pl)[i];
    }
    for (int i = tid; i < 64 * 128; i += 512) {
        int e = i >> 7, mw = i & 127;
        ((uint32_t*)CH)[e * 132 + mw] = ((const uint32_t*)(g_Ch + (size_t)head * 16384))[i];
        ((uint32_t*)CL)[e * 132 + mw] = ((const uint32_t*)(g_Cl + (size_t)head * 16384))[i];
    }
    if (tid < 256) ksum_s[tid] = g_ksumf[head * MM + tid];

    int rt = wid & 1;              // 16-row tile
    int mq = wid >> 1;             // dash: 8 groups of 32 m
    int eq = wid >> 1;             // out: 8 groups of 8 e

    for (int ch = 0; ch < 8; ch++) {
        int n0 = blockIdx.x * 256 + ch * 32;
        __syncthreads();
        for (int i = tid; i < 32 * 64; i += 512) {
            int n = i >> 6, d = i & 63;
            float qv = SCALE * qb[(size_t)(n0 + n) * 64 + d];
            __nv_bfloat16 h = __float2bfloat16(qv);
            *(__nv_bfloat16*)(QH + (n * 72 + d) * 2) = h;
            *(__nv_bfloat16*)(QL + (n * 72 + d) * 2) = __float2bfloat16(qv - __bfloat162float(h));
        }
        __syncthreads();
        if (tid < 32) {
            float s = 0.0f;
            #pragma unroll 8
            for (int d = 0; d < 64; d++) {
                float qh = __bfloat162float(*(__nv_bfloat16*)(QH + (tid * 72 + d) * 2));
                float ql = __bfloat162float(*(__nv_bfloat16*)(QL + (tid * 72 + d) * 2));
                float qv = qh + ql;
                s += qv * qv;
            }
            diag_s[tid] = 0.5f * s;
        }
        // ---- dash MMA: warp = 16n x 32m (3-split) ----
        {
            float acc[4][4] = {};
            int arow = rt * 16 + lr;
            for (int ks = 0; ks < 4; ks++) {
                uint32_t ah[4], al[4];
                lda_frag(ah, QH, arow, 72, ks * 16 + qk);
                lda_frag(al, QL, arow, 72, ks * 16 + qk);
                #pragma unroll
                for (int ct = 0; ct < 4; ct++) {
                    int bcol = mq * 32 + ct * 8 + lr;
                    uint32_t bh[2], bl[2];
                    ldb_frag(bh, PH, bcol, 72, ks * 16 + qk);
                    ldb_frag(bl, PL, bcol, 72, ks * 16 + qk);
                    MMA(acc[ct], ah, bh[0], bh[1]);
                    MMA(acc[ct], ah, bl[0], bl[1]);
                    MMA(acc[ct], al, bh[0], bh[1]);
                }
            }
            #pragma unroll
            for (int ct = 0; ct < 4; ct++) {
                int mc = mq * 32 + ct * 8 + qk;
                *(float2*)&dash[(size_t)(arow)     * 264 + mc] = make_float2(acc[ct][0], acc[ct][1]);
                *(float2*)&dash[(size_t)(arow + 8) * 264 + mc] = make_float2(acc[ct][2], acc[ct][3]);
            }
        }
        __syncthreads();
        {   // row max: 32 rows x 16 segs x 16 m
            int r = tid >> 4, seg = tid & 15;
            float m = -1e30f;
            #pragma unroll
            for (int mm = seg * 16; mm < seg * 16 + 16; mm++) m = fmaxf(m, dash[r * 264 + mm]);
            pm[r * 16 + seg] = m;
        }
        __syncthreads();
        if (tid < 32) {
            float m = -1e30f;
            #pragma unroll
            for (int s = 0; s < 16; s++) m = fmaxf(m, pm[tid * 16 + s]);
            mxs[tid] = m;
        }
        __syncthreads();
        {   // exp: 512 threads cover 32x256
            int m_c = tid & 255, rh = tid >> 8;
            for (int r = rh; r < 32; r += 2) {
                float w = fexp(dash[r * 264 + m_c] - diag_s[r] - mxs[r]) + EPSILON;
                *(__nv_bfloat16*)(WB + (r * 264 + m_c) * 2) = __float2bfloat16(w);
            }
        }
        __syncthreads();
        {   // denominators from bf16 w
            int r = tid >> 4, seg = tid & 15;
            float s = 0.0f;
            #pragma unroll
            for (int mm = seg * 16; mm < seg * 16 + 16; mm++)
                s += __bfloat162float(*(__nv_bfloat16*)(WB + (r * 264 + mm) * 2)) * ksum_s[mm];
            pden[r * 16 + seg] = s;
        }
        __syncthreads();
        if (tid < 32) {
            float s = 0.0f;
            #pragma unroll
            for (int j = 0; j < 16; j++) s += pden[tid * 16 + j];
            dinv_s[tid] = 1.0f / s;
        }
        __syncthreads();
        // ---- out MMA: warp = 16n x 8e, k=256 ----
        {
            float oacc[4] = {};
            int arow = rt * 16 + lr;
            for (int ks = 0; ks < 16; ks++) {
                uint32_t aw[4];
                lda_frag(aw, WB, arow, 264, ks * 16 + qk);
                int ec = eq * 8 + lr;
                uint32_t bh[2], bl[2];
                ldb_frag(bh, CH, ec, 264, ks * 16 + qk);
                ldb_frag(bl, CL, ec, 264, ks * 16 + qk);
                MMA(oacc, aw, bh[0], bh[1]);
                MMA(oacc, aw, bl[0], bl[1]);
            }
            float di0 = dinv_s[rt * 16 + lr];
            float di1 = dinv_s[rt * 16 + lr + 8];
            int nr = n0 + rt * 16 + lr;
            int e = eq * 8 + qk;
            float* ob0 = out + ((size_t)head * NN + nr) * 64 + e;
            float* ob1 = out + ((size_t)head * NN + nr + 8) * 64 + e;
            ob0[0] = oacc[0] * di0;
            ob0[1] = oacc[1] * di0;
            ob1[0] = oacc[2] * di1;
            ob1[1] = oacc[3] * di1;
        }
    }
}

// ---------------- launch ----------------
extern "C" void kernel_launch(void* const* d_in, const int* in_sizes, int n_in,
                              void* d_out, int out_size) {
    const float* q = (const float*)d_in[0];
    const float* k = (const float*)d_in[1];
    const float* v = (const float*)d_in[2];
    const float* P = (const float*)d_in[3];
    float* out = (float*)d_out;

    cudaFuncSetAttribute(kA, cudaFuncAttributeMaxDynamicSharedMemorySize, A_SIZE);
    cudaFuncSetAttribute(kC, cudaFuncAttributeMaxDynamicSharedMemorySize, C_SIZE);

    k0_init<<<(NH * MM * DD + 255) / 256, 256>>>();
    kP<<<64, 256>>>(P);
    kA<<<dim3(8, NH), 512, A_SIZE>>>(k, v);
    kB<<<NH, 256>>>();
    kC<<<dim3(16, NH), 512, C_SIZE>>>(q, out);
}

// round 9
// speedup vs baseline: 1.9795x; 1.1828x over previous
#include <cuda_runtime.h>
#include <cuda_bf16.h>
#include <stdint.h>

#define NH 64
#define NN 4096
#define DD 64
#define MM 256
#define SCALE   0.35355339059327379f   // 64^-0.25
#define EPSILON 1e-4f

// ---------------- scratch ----------------
__device__ float         g_ctxraw [NH*MM*DD];
__device__ float         g_ksumraw[NH*MM];
__device__ float         g_vsum   [NH*DD];
__device__ unsigned      g_gmax   [NH];
__device__ float         g_ksumf  [NH*MM];
__device__ __nv_bfloat16 g_Ph[MM*DD], g_Pl[MM*DD];        // P hi/lo [256 m][64 d]
__device__ __nv_bfloat16 g_Ch[NH*DD*MM], g_Cl[NH*DD*MM];  // ctx^T hi/lo [64 e][256 m] per head

// ---------------- helpers ----------------
__device__ __forceinline__ unsigned enc_f(float f) {
    unsigned u = __float_as_uint(f);
    return (u & 0x80000000u) ? ~u : (u | 0x80000000u);
}
__device__ __forceinline__ float dec_f(unsigned u) {
    return __uint_as_float((u & 0x80000000u) ? (u & 0x7fffffffu) : ~u);
}
__device__ __forceinline__ float fexp(float x) {
    float y = fmaxf(x * 1.4426950408889634f, -126.0f);
    float n = rintf(y);
    float f = y - n;
    float p = 1.5403530393381609e-4f;
    p = fmaf(p, f, 1.3333558146428443e-3f);
    p = fmaf(p, f, 9.6181291076284772e-3f);
    p = fmaf(p, f, 5.5504108664821580e-2f);
    p = fmaf(p, f, 2.4022650695910071e-1f);
    p = fmaf(p, f, 6.9314718055994531e-1f);
    p = fmaf(p, f, 1.0f);
    return p * __int_as_float(((int)n + 127) << 23);
}
__device__ __forceinline__ void MMA(float d[4], const uint32_t a[4], uint32_t b0, uint32_t b1) {
    asm volatile("mma.sync.aligned.m16n8k16.row.col.f32.bf16.bf16.f32 "
        "{%0,%1,%2,%3}, {%4,%5,%6,%7}, {%8,%9}, {%0,%1,%2,%3};"
        : "+f"(d[0]), "+f"(d[1]), "+f"(d[2]), "+f"(d[3])
        : "r"(a[0]), "r"(a[1]), "r"(a[2]), "r"(a[3]), "r"(b0), "r"(b1));
}
__device__ __forceinline__ uint32_t cvta_s(const void* p) {
    uint32_t a;
    asm("{ .reg .u64 t; cvta.to.shared.u64 t, %1; cvt.u32.u64 %0, t; }" : "=r"(a) : "l"(p));
    return a;
}
__device__ __forceinline__ void ldsm4(uint32_t r[4], uint32_t a) {
    asm volatile("ldmatrix.sync.aligned.m8n8.x4.shared.b16 {%0,%1,%2,%3}, [%4];"
        : "=r"(r[0]), "=r"(r[1]), "=r"(r[2]), "=r"(r[3]) : "r"(a));
}
__device__ __forceinline__ void ldsm2(uint32_t r[2], uint32_t a) {
    asm volatile("ldmatrix.sync.aligned.m8n8.x2.shared.b16 {%0,%1}, [%2];"
        : "=r"(r[0]), "=r"(r[1]) : "r"(a));
}
__device__ __forceinline__ uint32_t pkbf(__nv_bfloat16 a, __nv_bfloat16 b) {
    uint16_t ua = *(uint16_t*)&a, ub = *(uint16_t*)&b;
    return (uint32_t)ua | ((uint32_t)ub << 16);
}

// ---------------- K0: init ----------------
__global__ void k0_init() {
    int i = blockIdx.x * blockDim.x + threadIdx.x;
    if (i < NH*MM*DD) g_ctxraw[i] = 0.0f;
    if (i < NH*MM)    g_ksumraw[i] = 0.0f;
    if (i < NH*DD)    g_vsum[i] = 0.0f;
    if (i < NH)       g_gmax[i] = enc_f(-1e30f);
}

// ---------------- kP: P bf16 hi/lo images ----------------
__global__ void kP(const float* __restrict__ P) {
    int i = blockIdx.x * 256 + threadIdx.x;
    float p = P[i];
    __nv_bfloat16 h = __float2bfloat16(p);
    g_Ph[i] = h;
    g_Pl[i] = __float2bfloat16(p - __bfloat162float(h));
}

// =============== kA: k-side fused, 512 thr, ldmatrix + ones-column ksum ===============
#define A_PH   0        // [256][72] bf16
#define A_PL   36864
#define A_KH   73728    // [128][72]
#define A_KL   92160
#define A_VH   110592   // [72][136]  (V^T; row 64 = ones)
#define A_VL   130176
#define A_W    149760   // [256][136] bf16 (w^T)
#define A_DIAG 219392   // 128 f32
#define A_RED  219904   // 512 f32
#define A_VS   221952   // 64 f32
#define A_SIZE 222208

__global__ void __launch_bounds__(512, 1) kA(const float* __restrict__ K,
                                             const float* __restrict__ V) {
    extern __shared__ char smx[];
    int tid = threadIdx.x, wid = tid >> 5, lane = tid & 31;
    int lr = lane >> 2, qk = (lane & 3) * 2;
    int li = lane & 7;
    int t01 = (lane >> 3) & 1, t23 = (lane >> 4) & 1;
    int head = blockIdx.y;
    const float* kb = K + (size_t)head * NN * DD;
    const float* vb = V + (size_t)head * NN * DD;

    char* PH = smx + A_PH; char* PL = smx + A_PL;
    char* KH = smx + A_KH; char* KL = smx + A_KL;
    char* VH = smx + A_VH; char* VL = smx + A_VL;
    char* W  = smx + A_W;
    float* diag_s = (float*)(smx + A_DIAG);
    float* red    = (float*)(smx + A_RED);
    float* vsum_s = (float*)(smx + A_VS);

    for (int i = tid; i < 256 * 32; i += 512) {
        int m = i >> 5, dw = i & 31;
        ((uint32_t*)PH)[m * 36 + dw] = ((const uint32_t*)g_Ph)[i];
        ((uint32_t*)PL)[m * 36 + dw] = ((const uint32_t*)g_Pl)[i];
    }
    // ones-row (e=64) + zero pad rows 65..71 of V images (never overwritten)
    {
        __nv_bfloat16 one = __float2bfloat16(1.0f);
        __nv_bfloat16 zer = __float2bfloat16(0.0f);
        for (int i = tid; i < 8 * 136; i += 512) {
            int row = 64 + i / 136, col = i % 136;
            *(__nv_bfloat16*)(VH + (row * 136 + col) * 2) = (row == 64 && col < 128) ? one : zer;
            *(__nv_bfloat16*)(VL + (row * 136 + col) * 2) = zer;
        }
    }
    if (tid < 64) vsum_s[tid] = 0.0f;

    int nq = (wid & 3) * 32, mq = (wid >> 2) * 64;   // dash warp tile: 32n x 64m
    // ldmatrix lane addresses
    uint32_t aKH = cvta_s(KH) + (uint32_t)((nq + t01 * 8 + li) * 144) + t23 * 16;
    uint32_t aKL = aKH + (uint32_t)(A_KL - A_KH);
    uint32_t aPH = cvta_s(PH) + (uint32_t)((mq + t23 * 8 + li) * 144) + t01 * 16;
    uint32_t aPL = aPH + (uint32_t)(A_PL - A_PH);
    uint32_t aW  = cvta_s(W)  + (uint32_t)((wid * 16 + t01 * 8 + li) * 272) + t23 * 16;
    uint32_t aVH = cvta_s(VH) + (uint32_t)((t23 * 8 + li) * 272) + t01 * 16;
    uint32_t aVL = aVH + (uint32_t)(A_VL - A_VH);
    uint32_t aV1 = cvta_s(VH) + (uint32_t)((64 + li) * 272) + t01 * 16;  // x2 ones row

    float cacc[9][4] = {};
    float lmax = -1e30f;

    for (int ch = 0; ch < 4; ch++) {
        int n0 = blockIdx.x * 512 + ch * 128;
        __syncthreads();
        for (int i = tid; i < 128 * 64; i += 512) {
            int n = i >> 6, d = i & 63;
            float kv = SCALE * kb[(size_t)(n0 + n) * 64 + d];
            __nv_bfloat16 h = __float2bfloat16(kv);
            *(__nv_bfloat16*)(KH + (n * 72 + d) * 2) = h;
            *(__nv_bfloat16*)(KL + (n * 72 + d) * 2) = __float2bfloat16(kv - __bfloat162float(h));
        }
        for (int i = tid; i < 64 * 128; i += 512) {
            int e = i >> 7, n = i & 127;   // e uniform across warp
            float vv = vb[(size_t)(n0 + n) * 64 + e];
            __nv_bfloat16 h = __float2bfloat16(vv);
            *(__nv_bfloat16*)(VH + (e * 136 + n) * 2) = h;
            *(__nv_bfloat16*)(VL + (e * 136 + n) * 2) = __float2bfloat16(vv - __bfloat162float(h));
            float s = vv;
            s += __shfl_xor_sync(0xffffffffu, s, 1);
            s += __shfl_xor_sync(0xffffffffu, s, 2);
            s += __shfl_xor_sync(0xffffffffu, s, 4);
            s += __shfl_xor_sync(0xffffffffu, s, 8);
            s += __shfl_xor_sync(0xffffffffu, s, 16);
            if (lane == 0) atomicAdd(&vsum_s[e], s);
        }
        __syncthreads();
        if (tid < 128) {   // diag[n]
            float s = 0.0f;
            #pragma unroll 8
            for (int d = 0; d < 64; d++) {
                float kh = __bfloat162float(*(__nv_bfloat16*)(KH + (tid * 72 + d) * 2));
                float kl = __bfloat162float(*(__nv_bfloat16*)(KL + (tid * 72 + d) * 2));
                float kv = kh + kl;
                s += kv * kv;
            }
            diag_s[tid] = 0.5f * s;
        }
        __syncthreads();
        // ---- dash MMA + exp epilogue ----
        for (int rt = 0; rt < 2; rt++) {
            int arow = nq + rt * 16 + lr;
            float dg0 = diag_s[arow], dg1 = diag_s[arow + 8];
            float acc[8][4] = {};
            for (int ks = 0; ks < 4; ks++) {
                uint32_t ah[4], al[4];
                ldsm4(ah, aKH + rt * 2304 + ks * 32);
                ldsm4(al, aKL + rt * 2304 + ks * 32);
                #pragma unroll
                for (int ctp = 0; ctp < 4; ctp++) {
                    uint32_t bh[4], bl[4];
                    ldsm4(bh, aPH + ctp * 2304 + ks * 32);
                    ldsm4(bl, aPL + ctp * 2304 + ks * 32);
                    MMA(acc[2*ctp],   ah, bh[0], bh[1]);
                    MMA(acc[2*ctp],   ah, bl[0], bl[1]);
                    MMA(acc[2*ctp],   al, bh[0], bh[1]);
                    MMA(acc[2*ctp+1], ah, bh[2], bh[3]);
                    MMA(acc[2*ctp+1], ah, bl[2], bl[3]);
                    MMA(acc[2*ctp+1], al, bh[2], bh[3]);
                }
            }
            #pragma unroll
            for (int ct = 0; ct < 8; ct++) {
                int mc = mq + ct * 8 + qk;
                float d0 = acc[ct][0], d1 = acc[ct][1], d2 = acc[ct][2], d3 = acc[ct][3];
                lmax = fmaxf(lmax, fmaxf(fmaxf(d0, d1), fmaxf(d2, d3)));
                float w0 = fexp(d0 - dg0), w1 = fexp(d1 - dg0);
                float w2 = fexp(d2 - dg1), w3 = fexp(d3 - dg1);
                *(__nv_bfloat16*)(W + ((size_t)mc * 136 + arow) * 2)           = __float2bfloat16(w0);
                *(__nv_bfloat16*)(W + ((size_t)(mc + 1) * 136 + arow) * 2)     = __float2bfloat16(w1);
                *(__nv_bfloat16*)(W + ((size_t)mc * 136 + arow + 8) * 2)       = __float2bfloat16(w2);
                *(__nv_bfloat16*)(W + ((size_t)(mc + 1) * 136 + arow + 8) * 2) = __float2bfloat16(w3);
            }
        }
        __syncthreads();
        // ---- ctx MMA: warp = 16 m rows x 72 e (incl. ones col 64 = ksum), k=128n ----
        for (int ks = 0; ks < 8; ks++) {
            uint32_t aw[4];
            ldsm4(aw, aW + ks * 32);
            #pragma unroll
            for (int etp = 0; etp < 4; etp++) {
                uint32_t bh[4], bl[4];
                ldsm4(bh, aVH + etp * 4352 + ks * 32);
                ldsm4(bl, aVL + etp * 4352 + ks * 32);
                MMA(cacc[2*etp],   aw, bh[0], bh[1]);
                MMA(cacc[2*etp],   aw, bl[0], bl[1]);
                MMA(cacc[2*etp+1], aw, bh[2], bh[3]);
                MMA(cacc[2*etp+1], aw, bl[2], bl[3]);
            }
            {   // et = 8: ones column (lo image is zero -> skip)
                uint32_t b2[2];
                ldsm2(b2, aV1 + ks * 32);
                MMA(cacc[8], aw, b2[0], b2[1]);
            }
        }
    }
    // ---- flush ----
    __syncthreads();
    if (tid < 64) atomicAdd(&g_vsum[head * DD + tid], vsum_s[tid]);
    red[tid] = lmax;
    __syncthreads();
    for (int s = 256; s > 0; s >>= 1) {
        if (tid < s) red[tid] = fmaxf(red[tid], red[tid + s]);
        __syncthreads();
    }
    if (tid == 0) atomicMax(&g_gmax[head], enc_f(red[0]));
    float* ctx = g_ctxraw + (size_t)head * MM * DD;
    {
        int m = wid * 16 + lr;
        #pragma unroll
        for (int et = 0; et < 8; et++) {
            int e = et * 8 + qk;
            atomicAdd(&ctx[m * 64 + e],           cacc[et][0]);
            atomicAdd(&ctx[m * 64 + e + 1],       cacc[et][1]);
            atomicAdd(&ctx[(m + 8) * 64 + e],     cacc[et][2]);
            atomicAdd(&ctx[(m + 8) * 64 + e + 1], cacc[et][3]);
        }
        if ((lane & 3) == 0) {   // e = 64 column = ksum
            atomicAdd(&g_ksumraw[head * MM + m],     cacc[8][0]);
            atomicAdd(&g_ksumraw[head * MM + m + 8], cacc[8][2]);
        }
    }
}

// =============== kB: finalize (parallelized: 512 blocks) ===============
__global__ void kB() {
    int b = blockIdx.x, head = b >> 3, part = b & 7;
    int tid = threadIdx.x;
    float emx = fexp(-dec_f(g_gmax[head]));
    if (part == 0) g_ksumf[head * MM + tid] = emx * g_ksumraw[head * MM + tid] + EPSILON * (float)NN;
    int i0 = part * 2048;
    for (int i = i0 + tid; i < i0 + 2048; i += 256) {
        int m = i >> 6, e = i & 63;
        float cf = emx * g_ctxraw[(size_t)head * MM * DD + i] + EPSILON * g_vsum[head * DD + e];
        __nv_bfloat16 h = __float2bfloat16(cf);
        g_Ch[(size_t)head * 16384 + e * 256 + m] = h;
        g_Cl[(size_t)head * 16384 + e * 256 + m] = __float2bfloat16(cf - __bfloat162float(h));
    }
}

// =============== kC: q-side fused, 512 thr, register-resident dash ===============
#define C_PH   0        // [256][72] bf16
#define C_PL   36864
#define C_CH   73728    // [64][264] bf16 (ctx^T)
#define C_CL   107520
#define C_QH   141312   // [32][72]
#define C_QL   145920
#define C_W    150528   // [32][264] bf16
#define C_KSUM 167424   // 256 f32
#define C_DIAG 168448   // 32 f32
#define C_MX   168576   // 32 f32
#define C_PM   168704   // 32*8 f32
#define C_PDEN 169728   // 32*8 f32
#define C_DINV 170752   // 32 f32
#define C_SIZE 170880

__global__ void __launch_bounds__(512, 1) kC(const float* __restrict__ Q,
                                             float* __restrict__ out) {
    extern __shared__ char smx[];
    int tid = threadIdx.x, wid = tid >> 5, lane = tid & 31;
    int lr = lane >> 2, qk = (lane & 3) * 2;
    int li = lane & 7;
    int t01 = (lane >> 3) & 1, t23 = (lane >> 4) & 1;
    int head = blockIdx.y;
    const float* qb = Q + (size_t)head * NN * DD;

    char* PH = smx + C_PH; char* PL = smx + C_PL;
    char* CH = smx + C_CH; char* CL = smx + C_CL;
    char* QH = smx + C_QH; char* QL = smx + C_QL;
    char* WB = smx + C_W;
    float* ksum_s = (float*)(smx + C_KSUM);
    float* diag_s = (float*)(smx + C_DIAG);
    float* mxs    = (float*)(smx + C_MX);
    float* pm     = (float*)(smx + C_PM);
    float* pden   = (float*)(smx + C_PDEN);
    float* dinv_s = (float*)(smx + C_DINV);

    for (int i = tid; i < 256 * 32; i += 512) {
        int m = i >> 5, dw = i & 31;
        ((uint32_t*)PH)[m * 36 + dw] = ((const uint32_t*)g_Ph)[i];
        ((uint32_t*)PL)[m * 36 + dw] = ((const uint32_t*)g_Pl)[i];
    }
    for (int i = tid; i < 64 * 128; i += 512) {
        int e = i >> 7, mw = i & 127;
        ((uint32_t*)CH)[e * 132 + mw] = ((const uint32_t*)(g_Ch + (size_t)head * 16384))[i];
        ((uint32_t*)CL)[e * 132 + mw] = ((const uint32_t*)(g_Cl + (size_t)head * 16384))[i];
    }
    if (tid < 256) ksum_s[tid] = g_ksumf[head * MM + tid];

    int rt = wid & 1, mq8 = wid >> 1;   // dash: 16n x 32m ; out: eq = mq8
    int arow = rt * 16 + lr;

    uint32_t aQH = cvta_s(QH) + (uint32_t)((rt * 16 + t01 * 8 + li) * 144) + t23 * 16;
    uint32_t aQL = aQH + (uint32_t)(C_QL - C_QH);
    uint32_t aPH = cvta_s(PH) + (uint32_t)((mq8 * 32 + t23 * 8 + li) * 144) + t01 * 16;
    uint32_t aPL = aPH + (uint32_t)(C_PL - C_PH);
    uint32_t aWB = cvta_s(WB) + (uint32_t)((rt * 16 + t01 * 8 + li) * 528) + t23 * 16;
    uint32_t aCH = cvta_s(CH) + (uint32_t)((mq8 * 8 + li) * 528) + t01 * 16;  // x2 pattern
    uint32_t aCL = aCH + (uint32_t)(C_CL - C_CH);

    for (int ch = 0; ch < 8; ch++) {
        int n0 = blockIdx.x * 256 + ch * 32;
        __syncthreads();
        for (int i = tid; i < 32 * 64; i += 512) {
            int n = i >> 6, d = i & 63;
            float qv = SCALE * qb[(size_t)(n0 + n) * 64 + d];
            __nv_bfloat16 h = __float2bfloat16(qv);
            *(__nv_bfloat16*)(QH + (n * 72 + d) * 2) = h;
            *(__nv_bfloat16*)(QL + (n * 72 + d) * 2) = __float2bfloat16(qv - __bfloat162float(h));
        }
        __syncthreads();
        if (tid < 32) {
            float s = 0.0f;
            #pragma unroll 8
            for (int d = 0; d < 64; d++) {
                float qh = __bfloat162float(*(__nv_bfloat16*)(QH + (tid * 72 + d) * 2));
                float ql = __bfloat162float(*(__nv_bfloat16*)(QL + (tid * 72 + d) * 2));
                float qv = qh + ql;
                s += qv * qv;
            }
            diag_s[tid] = 0.5f * s;
        }
        // ---- dash MMA in registers ----
        float acc[4][4] = {};
        for (int ks = 0; ks < 4; ks++) {
            uint32_t ah[4], al[4];
            ldsm4(ah, aQH + ks * 32);
            ldsm4(al, aQL + ks * 32);
            #pragma unroll
            for (int ctp = 0; ctp < 2; ctp++) {
                uint32_t bh[4], bl[4];
                ldsm4(bh, aPH + ctp * 2304 + ks * 32);
                ldsm4(bl, aPL + ctp * 2304 + ks * 32);
                MMA(acc[2*ctp],   ah, bh[0], bh[1]);
                MMA(acc[2*ctp],   ah, bl[0], bl[1]);
                MMA(acc[2*ctp],   al, bh[0], bh[1]);
                MMA(acc[2*ctp+1], ah, bh[2], bh[3]);
                MMA(acc[2*ctp+1], ah, bl[2], bl[3]);
                MMA(acc[2*ctp+1], al, bh[2], bh[3]);
            }
        }
        // ---- in-register rowmax ----
        {
            float mx0 = -1e30f, mx1 = -1e30f;
            #pragma unroll
            for (int ct = 0; ct < 4; ct++) {
                mx0 = fmaxf(mx0, fmaxf(acc[ct][0], acc[ct][1]));
                mx1 = fmaxf(mx1, fmaxf(acc[ct][2], acc[ct][3]));
            }
            mx0 = fmaxf(mx0, __shfl_xor_sync(0xffffffffu, mx0, 1));
            mx0 = fmaxf(mx0, __shfl_xor_sync(0xffffffffu, mx0, 2));
            mx1 = fmaxf(mx1, __shfl_xor_sync(0xffffffffu, mx1, 1));
            mx1 = fmaxf(mx1, __shfl_xor_sync(0xffffffffu, mx1, 2));
            if ((lane & 3) == 0) {
                pm[arow * 8 + mq8] = mx0;
                pm[(arow + 8) * 8 + mq8] = mx1;
            }
        }
        __syncthreads();
        if (tid < 32) {
            float m = -1e30f;
            #pragma unroll
            for (int j = 0; j < 8; j++) m = fmaxf(m, pm[tid * 8 + j]);
            mxs[tid] = m;
        }
        __syncthreads();
        // ---- exp + den + W write (bf16-consistent den) ----
        {
            float dg0 = diag_s[arow] + mxs[arow];
            float dg1 = diag_s[arow + 8] + mxs[arow + 8];
            float den0 = 0.0f, den1 = 0.0f;
            #pragma unroll
            for (int ct = 0; ct < 4; ct++) {
                int mc = mq8 * 32 + ct * 8 + qk;
                __nv_bfloat16 b0 = __float2bfloat16(fexp(acc[ct][0] - dg0) + EPSILON);
                __nv_bfloat16 b1 = __float2bfloat16(fexp(acc[ct][1] - dg0) + EPSILON);
                __nv_bfloat16 b2 = __float2bfloat16(fexp(acc[ct][2] - dg1) + EPSILON);
                __nv_bfloat16 b3 = __float2bfloat16(fexp(acc[ct][3] - dg1) + EPSILON);
                den0 += __bfloat162float(b0) * ksum_s[mc] + __bfloat162float(b1) * ksum_s[mc + 1];
                den1 += __bfloat162float(b2) * ksum_s[mc] + __bfloat162float(b3) * ksum_s[mc + 1];
                *(uint32_t*)(WB + ((size_t)arow * 264 + mc) * 2)       = pkbf(b0, b1);
                *(uint32_t*)(WB + ((size_t)(arow + 8) * 264 + mc) * 2) = pkbf(b2, b3);
            }
            den0 += __shfl_xor_sync(0xffffffffu, den0, 1);
            den0 += __shfl_xor_sync(0xffffffffu, den0, 2);
            den1 += __shfl_xor_sync(0xffffffffu, den1, 1);
            den1 += __shfl_xor_sync(0xffffffffu, den1, 2);
            if ((lane & 3) == 0) {
                pden[arow * 8 + mq8] = den0;
                pden[(arow + 8) * 8 + mq8] = den1;
            }
        }
        __syncthreads();
        if (tid < 32) {
            float s = 0.0f;
            #pragma unroll
            for (int j = 0; j < 8; j++) s += pden[tid * 8 + j];
            dinv_s[tid] = 1.0f / s;
        }
        __syncthreads();
        // ---- out MMA: warp = 16n x 8e, k=256 ----
        {
            float oacc[4] = {};
            for (int ks = 0; ks < 16; ks++) {
                uint32_t aw[4], bh[2], bl[2];
                ldsm4(aw, aWB + ks * 32);
                ldsm2(bh, aCH + ks * 32);
                ldsm2(bl, aCL + ks * 32);
                MMA(oacc, aw, bh[0], bh[1]);
                MMA(oacc, aw, bl[0], bl[1]);
            }
            float di0 = dinv_s[arow];
            float di1 = dinv_s[arow + 8];
            int nr = n0 + arow;
            int e = mq8 * 8 + qk;
            float* ob0 = out + ((size_t)head * NN + nr) * 64 + e;
            float* ob1 = out + ((size_t)head * NN + nr + 8) * 64 + e;
            ob0[0] = oacc[0] * di0;
            ob0[1] = oacc[1] * di0;
            ob1[0] = oacc[2] * di1;
            ob1[1] = oacc[3] * di1;
        }
    }
}

// ---------------- launch ----------------
extern "C" void kernel_launch(void* const* d_in, const int* in_sizes, int n_in,
                              void* d_out, int out_size) {
    const float* q = (const float*)d_in[0];
    const float* k = (const float*)d_in[1];
    const float* v = (const float*)d_in[2];
    const float* P = (const float*)d_in[3];
    float* out = (float*)d_out;

    cudaFuncSetAttribute(kA, cudaFuncAttributeMaxDynamicSharedMemorySize, A_SIZE);
    cudaFuncSetAttribute(kC, cudaFuncAttributeMaxDynamicSharedMemorySize, C_SIZE);

    k0_init<<<(NH * MM * DD + 255) / 256, 256>>>();
    kP<<<64, 256>>>(P);
    kA<<<dim3(8, NH), 512, A_SIZE>>>(k, v);
    kB<<<512, 256>>>();
    kC<<<dim3(16, NH), 512, C_SIZE>>>(q, out);
}

// round 10
// speedup vs baseline: 2.5035x; 1.2647x over previous
#include <cuda_runtime.h>
#include <cuda_bf16.h>
#include <stdint.h>

#define NH 64
#define NN 4096
#define DD 64
#define MM 256
#define SCALE   0.35355339059327379f   // 64^-0.25
#define EPSILON 1e-4f

// ---------------- scratch ----------------
__device__ float         g_ctxraw [NH*MM*DD];
__device__ float         g_ksumraw[NH*MM];
__device__ float         g_vsum   [NH*DD];
__device__ unsigned      g_gmax   [NH];
__device__ float         g_ksumf  [NH*MM];
__device__ __nv_bfloat16 g_Ph[MM*DD], g_Pl[MM*DD];   // P hi/lo [256 m][64 d]
__device__ __nv_bfloat16 g_Ch[NH*DD*MM];             // ctx^T [64 e][256 m] per head

// ---------------- helpers ----------------
__device__ __forceinline__ unsigned enc_f(float f) {
    unsigned u = __float_as_uint(f);
    return (u & 0x80000000u) ? ~u : (u | 0x80000000u);
}
__device__ __forceinline__ float dec_f(unsigned u) {
    return __uint_as_float((u & 0x80000000u) ? (u & 0x7fffffffu) : ~u);
}
__device__ __forceinline__ float fexp(float x) {
    float y = fmaxf(x * 1.4426950408889634f, -126.0f);
    float n = rintf(y);
    float f = y - n;
    float p = 1.5403530393381609e-4f;
    p = fmaf(p, f, 1.3333558146428443e-3f);
    p = fmaf(p, f, 9.6181291076284772e-3f);
    p = fmaf(p, f, 5.5504108664821580e-2f);
    p = fmaf(p, f, 2.4022650695910071e-1f);
    p = fmaf(p, f, 6.9314718055994531e-1f);
    p = fmaf(p, f, 1.0f);
    return p * __int_as_float(((int)n + 127) << 23);
}
__device__ __forceinline__ void MMA(float d[4], const uint32_t a[4], uint32_t b0, uint32_t b1) {
    asm volatile("mma.sync.aligned.m16n8k16.row.col.f32.bf16.bf16.f32 "
        "{%0,%1,%2,%3}, {%4,%5,%6,%7}, {%8,%9}, {%0,%1,%2,%3};"
        : "+f"(d[0]), "+f"(d[1]), "+f"(d[2]), "+f"(d[3])
        : "r"(a[0]), "r"(a[1]), "r"(a[2]), "r"(a[3]), "r"(b0), "r"(b1));
}
__device__ __forceinline__ uint32_t cvta_s(const void* p) {
    uint32_t a;
    asm("{ .reg .u64 t; cvta.to.shared.u64 t, %1; cvt.u32.u64 %0, t; }" : "=r"(a) : "l"(p));
    return a;
}
__device__ __forceinline__ void ldsm4(uint32_t r[4], uint32_t a) {
    asm volatile("ldmatrix.sync.aligned.m8n8.x4.shared.b16 {%0,%1,%2,%3}, [%4];"
        : "=r"(r[0]), "=r"(r[1]), "=r"(r[2]), "=r"(r[3]) : "r"(a));
}
__device__ __forceinline__ void ldsm2(uint32_t r[2], uint32_t a) {
    asm volatile("ldmatrix.sync.aligned.m8n8.x2.shared.b16 {%0,%1}, [%2];"
        : "=r"(r[0]), "=r"(r[1]) : "r"(a));
}
__device__ __forceinline__ uint32_t pkbf(__nv_bfloat16 a, __nv_bfloat16 b) {
    uint16_t ua = *(uint16_t*)&a, ub = *(uint16_t*)&b;
    return (uint32_t)ua | ((uint32_t)ub << 16);
}
// load 8 floats, scale, split hi/lo, packed STS.128; returns sum of squares
__device__ __forceinline__ float cv8(const float* src, float scale, char* dhi, char* dlo) {
    float4 u = *(const float4*)src;
    float4 v = *(const float4*)(src + 4);
    float a[8] = {scale*u.x, scale*u.y, scale*u.z, scale*u.w,
                  scale*v.x, scale*v.y, scale*v.z, scale*v.w};
    float ss = 0.0f;
    __nv_bfloat16 h[8];
    uint32_t hw[4], lw[4];
    #pragma unroll
    for (int i = 0; i < 8; i++) { ss += a[i]*a[i]; h[i] = __float2bfloat16(a[i]); }
    #pragma unroll
    for (int i = 0; i < 4; i++) {
        hw[i] = pkbf(h[2*i], h[2*i+1]);
        lw[i] = pkbf(__float2bfloat16(a[2*i]   - __bfloat162float(h[2*i])),
                     __float2bfloat16(a[2*i+1] - __bfloat162float(h[2*i+1])));
    }
    *(uint4*)dhi = make_uint4(hw[0], hw[1], hw[2], hw[3]);
    *(uint4*)dlo = make_uint4(lw[0], lw[1], lw[2], lw[3]);
    return ss;
}

// ---------------- K0: init ----------------
__global__ void k0_init() {
    int i = blockIdx.x * blockDim.x + threadIdx.x;
    if (i < NH*MM*DD) g_ctxraw[i] = 0.0f;
    if (i < NH*MM)    g_ksumraw[i] = 0.0f;
    if (i < NH*DD)    g_vsum[i] = 0.0f;
    if (i < NH)       g_gmax[i] = enc_f(-1e30f);
}

// ---------------- kP: P bf16 hi/lo images ----------------
__global__ void kP(const float* __restrict__ P) {
    int i = blockIdx.x * 256 + threadIdx.x;
    float p = P[i];
    __nv_bfloat16 h = __float2bfloat16(p);
    g_Ph[i] = h;
    g_Pl[i] = __float2bfloat16(p - __bfloat162float(h));
}

// =============== kA: k-side fused, 512 thr ===============
#define A_PH   0        // [256][72] bf16
#define A_PL   36864
#define A_KH   73728    // [128][72]
#define A_KL   92160
#define A_VH   110592   // [72][136]  (V^T; row 64 = ones)
#define A_W    130176   // [256][136] bf16 (w^T)
#define A_DIAG 199808   // 128 f32
#define A_RED  200320   // 512 f32
#define A_VS   202368   // 64 f32
#define A_SIZE 202624

__global__ void __launch_bounds__(512, 1) kA(const float* __restrict__ K,
                                             const float* __restrict__ V) {
    extern __shared__ char smx[];
    int tid = threadIdx.x, wid = tid >> 5, lane = tid & 31;
    int lr = lane >> 2, qk = (lane & 3) * 2;
    int li = lane & 7;
    int t01 = (lane >> 3) & 1, t23 = (lane >> 4) & 1;
    int head = blockIdx.y;
    const float* kb = K + (size_t)head * NN * DD;
    const float* vb = V + (size_t)head * NN * DD;

    char* PH = smx + A_PH; char* PL = smx + A_PL;
    char* KH = smx + A_KH; char* KL = smx + A_KL;
    char* VH = smx + A_VH;
    char* W  = smx + A_W;
    float* diag_s = (float*)(smx + A_DIAG);
    float* red    = (float*)(smx + A_RED);
    float* vsum_s = (float*)(smx + A_VS);

    for (int i = tid; i < 256 * 32; i += 512) {
        int m = i >> 5, dw = i & 31;
        ((uint32_t*)PH)[m * 36 + dw] = ((const uint32_t*)g_Ph)[i];
        ((uint32_t*)PL)[m * 36 + dw] = ((const uint32_t*)g_Pl)[i];
    }
    // ones-row (e=64) + zero pad rows 65..71 of VH (never overwritten)
    {
        __nv_bfloat16 one = __float2bfloat16(1.0f);
        __nv_bfloat16 zer = __float2bfloat16(0.0f);
        for (int i = tid; i < 8 * 136; i += 512) {
            int row = 64 + i / 136, col = i % 136;
            *(__nv_bfloat16*)(VH + (row * 136 + col) * 2) = (row == 64 && col < 128) ? one : zer;
        }
    }
    if (tid < 64) vsum_s[tid] = 0.0f;

    int nq = (wid & 3) * 32, mq = (wid >> 2) * 64;
    // ldmatrix lane addresses
    uint32_t aKH = cvta_s(KH) + (uint32_t)((nq + t01 * 8 + li) * 144) + t23 * 16;
    uint32_t aKL = aKH + (uint32_t)(A_KL - A_KH);
    uint32_t aPH = cvta_s(PH) + (uint32_t)((mq + t23 * 8 + li) * 144) + t01 * 16;
    uint32_t aPL = aPH + (uint32_t)(A_PL - A_PH);
    uint32_t aW  = cvta_s(W)  + (uint32_t)((wid * 16 + t01 * 8 + li) * 272) + t23 * 16;
    uint32_t aVH = cvta_s(VH) + (uint32_t)((t23 * 8 + li) * 272) + t01 * 16;
    uint32_t aV1 = cvta_s(VH) + (uint32_t)((64 + li) * 272) + t01 * 16;

    // K-load mapping: quad per row
    int kln = tid >> 2, kld = (tid & 3) * 16;

    float cacc[9][4] = {};
    float lmax = -1e30f;

    for (int ch = 0; ch < 4; ch++) {
        int n0 = blockIdx.x * 512 + ch * 128;
        __syncthreads();
        // K hi/lo images + fused diag
        {
            const float* src = kb + (size_t)(n0 + kln) * 64 + kld;
            char* dh = KH + kln * 144 + kld * 2;
            char* dl = KL + kln * 144 + kld * 2;
            float part = cv8(src,     SCALE, dh,      dl);
            part      += cv8(src + 8, SCALE, dh + 16, dl + 16);
            part += __shfl_xor_sync(0xffffffffu, part, 1);
            part += __shfl_xor_sync(0xffffffffu, part, 2);
            if ((tid & 3) == 0) diag_s[kln] = 0.5f * part;
        }
        // V^T hi image + vsum
        for (int i = tid; i < 64 * 128; i += 512) {
            int e = i >> 7, n = i & 127;   // e uniform across warp
            float vv = vb[(size_t)(n0 + n) * 64 + e];
            *(__nv_bfloat16*)(VH + (e * 136 + n) * 2) = __float2bfloat16(vv);
            float s = vv;
            s += __shfl_xor_sync(0xffffffffu, s, 1);
            s += __shfl_xor_sync(0xffffffffu, s, 2);
            s += __shfl_xor_sync(0xffffffffu, s, 4);
            s += __shfl_xor_sync(0xffffffffu, s, 8);
            s += __shfl_xor_sync(0xffffffffu, s, 16);
            if (lane == 0) atomicAdd(&vsum_s[e], s);
        }
        __syncthreads();
        // ---- dash MMA + exp epilogue ----
        for (int rt = 0; rt < 2; rt++) {
            int arow = nq + rt * 16 + lr;
            float dg0 = diag_s[arow], dg1 = diag_s[arow + 8];
            float acc[8][4] = {};
            for (int ks = 0; ks < 4; ks++) {
                uint32_t ah[4], al[4];
                ldsm4(ah, aKH + rt * 2304 + ks * 32);
                ldsm4(al, aKL + rt * 2304 + ks * 32);
                #pragma unroll
                for (int ctp = 0; ctp < 4; ctp++) {
                    uint32_t bh[4], bl[4];
                    ldsm4(bh, aPH + ctp * 2304 + ks * 32);
                    ldsm4(bl, aPL + ctp * 2304 + ks * 32);
                    MMA(acc[2*ctp],   ah, bh[0], bh[1]);
                    MMA(acc[2*ctp],   ah, bl[0], bl[1]);
                    MMA(acc[2*ctp],   al, bh[0], bh[1]);
                    MMA(acc[2*ctp+1], ah, bh[2], bh[3]);
                    MMA(acc[2*ctp+1], ah, bl[2], bl[3]);
                    MMA(acc[2*ctp+1], al, bh[2], bh[3]);
                }
            }
            #pragma unroll
            for (int ct = 0; ct < 8; ct++) {
                int mc = mq + ct * 8 + qk;
                float d0 = acc[ct][0], d1 = acc[ct][1], d2 = acc[ct][2], d3 = acc[ct][3];
                lmax = fmaxf(lmax, fmaxf(fmaxf(d0, d1), fmaxf(d2, d3)));
                float w0 = fexp(d0 - dg0), w1 = fexp(d1 - dg0);
                float w2 = fexp(d2 - dg1), w3 = fexp(d3 - dg1);
                *(__nv_bfloat16*)(W + ((size_t)mc * 136 + arow) * 2)           = __float2bfloat16(w0);
                *(__nv_bfloat16*)(W + ((size_t)(mc + 1) * 136 + arow) * 2)     = __float2bfloat16(w1);
                *(__nv_bfloat16*)(W + ((size_t)mc * 136 + arow + 8) * 2)       = __float2bfloat16(w2);
                *(__nv_bfloat16*)(W + ((size_t)(mc + 1) * 136 + arow + 8) * 2) = __float2bfloat16(w3);
            }
        }
        __syncthreads();
        // ---- ctx MMA: warp = 16 m rows x (64 e + ones col), k=128n, single-bf16 V ----
        for (int ks = 0; ks < 8; ks++) {
            uint32_t aw[4];
            ldsm4(aw, aW + ks * 32);
            #pragma unroll
            for (int etp = 0; etp < 4; etp++) {
                uint32_t bh[4];
                ldsm4(bh, aVH + etp * 4352 + ks * 32);
                MMA(cacc[2*etp],   aw, bh[0], bh[1]);
                MMA(cacc[2*etp+1], aw, bh[2], bh[3]);
            }
            {
                uint32_t b2[2];
                ldsm2(b2, aV1 + ks * 32);
                MMA(cacc[8], aw, b2[0], b2[1]);
            }
        }
    }
    // ---- flush ----
    __syncthreads();
    if (tid < 64) atomicAdd(&g_vsum[head * DD + tid], vsum_s[tid]);
    red[tid] = lmax;
    __syncthreads();
    for (int s = 256; s > 0; s >>= 1) {
        if (tid < s) red[tid] = fmaxf(red[tid], red[tid + s]);
        __syncthreads();
    }
    if (tid == 0) atomicMax(&g_gmax[head], enc_f(red[0]));
    float* ctx = g_ctxraw + (size_t)head * MM * DD;
    {
        int m = wid * 16 + lr;
        #pragma unroll
        for (int et = 0; et < 8; et++) {
            int e = et * 8 + qk;
            atomicAdd(&ctx[m * 64 + e],           cacc[et][0]);
            atomicAdd(&ctx[m * 64 + e + 1],       cacc[et][1]);
            atomicAdd(&ctx[(m + 8) * 64 + e],     cacc[et][2]);
            atomicAdd(&ctx[(m + 8) * 64 + e + 1], cacc[et][3]);
        }
        if ((lane & 3) == 0) {
            atomicAdd(&g_ksumraw[head * MM + m],     cacc[8][0]);
            atomicAdd(&g_ksumraw[head * MM + m + 8], cacc[8][2]);
        }
    }
}

// =============== kB: finalize ===============
__global__ void kB() {
    int b = blockIdx.x, head = b >> 3, part = b & 7;
    int tid = threadIdx.x;
    float emx = fexp(-dec_f(g_gmax[head]));
    if (part == 0) g_ksumf[head * MM + tid] = emx * g_ksumraw[head * MM + tid] + EPSILON * (float)NN;
    int i0 = part * 2048;
    for (int i = i0 + tid; i < i0 + 2048; i += 256) {
        int m = i >> 6, e = i & 63;
        float cf = emx * g_ctxraw[(size_t)head * MM * DD + i] + EPSILON * g_vsum[head * DD + e];
        g_Ch[(size_t)head * 16384 + e * 256 + m] = __float2bfloat16(cf);
    }
}

// =============== kC: q-side fused, 512 thr ===============
#define C_PH   0        // [256][72] bf16
#define C_PL   36864
#define C_CH   73728    // [64][264] bf16 (ctx^T)
#define C_QH   107520   // [32][72]
#define C_QL   112128
#define C_W    116736   // [32][264] bf16
#define C_DIAG 133632   // 32 f32
#define C_MX   133760   // 32 f32
#define C_PM   133888   // 32*8 f32
#define C_PDEN 134912   // 32*8 f32
#define C_DINV 135936   // 32 f32
#define C_SIZE 136064

__global__ void __launch_bounds__(512, 1) kC(const float* __restrict__ Q,
                                             float* __restrict__ out) {
    extern __shared__ char smx[];
    int tid = threadIdx.x, wid = tid >> 5, lane = tid & 31;
    int lr = lane >> 2, qk = (lane & 3) * 2;
    int li = lane & 7;
    int t01 = (lane >> 3) & 1, t23 = (lane >> 4) & 1;
    int head = blockIdx.y;
    const float* qb = Q + (size_t)head * NN * DD;

    char* PH = smx + C_PH; char* PL = smx + C_PL;
    char* CH = smx + C_CH;
    char* QH = smx + C_QH; char* QL = smx + C_QL;
    char* WB = smx + C_W;
    float* diag_s = (float*)(smx + C_DIAG);
    float* mxs    = (float*)(smx + C_MX);
    float* pm     = (float*)(smx + C_PM);
    float* pden   = (float*)(smx + C_PDEN);
    float* dinv_s = (float*)(smx + C_DINV);

    for (int i = tid; i < 256 * 32; i += 512) {
        int m = i >> 5, dw = i & 31;
        ((uint32_t*)PH)[m * 36 + dw] = ((const uint32_t*)g_Ph)[i];
        ((uint32_t*)PL)[m * 36 + dw] = ((const uint32_t*)g_Pl)[i];
    }
    for (int i = tid; i < 64 * 128; i += 512) {
        int e = i >> 7, mw = i & 127;
        ((uint32_t*)CH)[e * 132 + mw] = ((const uint32_t*)(g_Ch + (size_t)head * 16384))[i];
    }

    int rt = wid & 1, mq8 = wid >> 1;
    int arow = rt * 16 + lr;

    // ksumf values for this thread's den columns (from L2, once)
    float ksr[8];
    #pragma unroll
    for (int ct = 0; ct < 4; ct++) {
        int mc = mq8 * 32 + ct * 8 + qk;
        ksr[2*ct]   = g_ksumf[head * MM + mc];
        ksr[2*ct+1] = g_ksumf[head * MM + mc + 1];
    }

    uint32_t aQH = cvta_s(QH) + (uint32_t)((rt * 16 + t01 * 8 + li) * 144) + t23 * 16;
    uint32_t aQL = aQH + (uint32_t)(C_QL - C_QH);
    uint32_t aPH = cvta_s(PH) + (uint32_t)((mq8 * 32 + t23 * 8 + li) * 144) + t01 * 16;
    uint32_t aPL = aPH + (uint32_t)(C_PL - C_PH);
    uint32_t aWB = cvta_s(WB) + (uint32_t)((rt * 16 + t01 * 8 + li) * 528) + t23 * 16;
    uint32_t aCH = cvta_s(CH) + (uint32_t)((mq8 * 8 + li) * 528) + (lane >> 3) * 16;

    for (int ch = 0; ch < 8; ch++) {
        int n0 = blockIdx.x * 256 + ch * 32;
        __syncthreads();
        // Q hi/lo images + fused diag (128 threads: quad per row)
        if (tid < 128) {
            int n = tid >> 2, dq = (tid & 3) * 16;
            const float* src = qb + (size_t)(n0 + n) * 64 + dq;
            char* dh = QH + n * 144 + dq * 2;
            char* dl = QL + n * 144 + dq * 2;
            float part = cv8(src,     SCALE, dh,      dl);
            part      += cv8(src + 8, SCALE, dh + 16, dl + 16);
            part += __shfl_xor_sync(0xffffffffu, part, 1);
            part += __shfl_xor_sync(0xffffffffu, part, 2);
            if ((tid & 3) == 0) diag_s[n] = 0.5f * part;
        }
        __syncthreads();
        // ---- dash MMA in registers (3-split) ----
        float acc[4][4] = {};
        for (int ks = 0; ks < 4; ks++) {
            uint32_t ah[4], al[4];
            ldsm4(ah, aQH + ks * 32);
            ldsm4(al, aQL + ks * 32);
            #pragma unroll
            for (int ctp = 0; ctp < 2; ctp++) {
                uint32_t bh[4], bl[4];
                ldsm4(bh, aPH + ctp * 2304 + ks * 32);
                ldsm4(bl, aPL + ctp * 2304 + ks * 32);
                MMA(acc[2*ctp],   ah, bh[0], bh[1]);
                MMA(acc[2*ctp],   ah, bl[0], bl[1]);
                MMA(acc[2*ctp],   al, bh[0], bh[1]);
                MMA(acc[2*ctp+1], ah, bh[2], bh[3]);
                MMA(acc[2*ctp+1], ah, bl[2], bl[3]);
                MMA(acc[2*ctp+1], al, bh[2], bh[3]);
            }
        }
        // ---- in-register rowmax ----
        {
            float mx0 = -1e30f, mx1 = -1e30f;
            #pragma unroll
            for (int ct = 0; ct < 4; ct++) {
                mx0 = fmaxf(mx0, fmaxf(acc[ct][0], acc[ct][1]));
                mx1 = fmaxf(mx1, fmaxf(acc[ct][2], acc[ct][3]));
            }
            mx0 = fmaxf(mx0, __shfl_xor_sync(0xffffffffu, mx0, 1));
            mx0 = fmaxf(mx0, __shfl_xor_sync(0xffffffffu, mx0, 2));
            mx1 = fmaxf(mx1, __shfl_xor_sync(0xffffffffu, mx1, 1));
            mx1 = fmaxf(mx1, __shfl_xor_sync(0xffffffffu, mx1, 2));
            if ((lane & 3) == 0) {
                pm[arow * 8 + mq8] = mx0;
                pm[(arow + 8) * 8 + mq8] = mx1;
            }
        }
        __syncthreads();
        if (tid < 32) {
            float m = -1e30f;
            #pragma unroll
            for (int j = 0; j < 8; j++) m = fmaxf(m, pm[tid * 8 + j]);
            mxs[tid] = m;
        }
        __syncthreads();
        // ---- exp + den (reg ksum) + W write ----
        {
            float dg0 = diag_s[arow] + mxs[arow];
            float dg1 = diag_s[arow + 8] + mxs[arow + 8];
            float den0 = 0.0f, den1 = 0.0f;
            #pragma unroll
            for (int ct = 0; ct < 4; ct++) {
                int mc = mq8 * 32 + ct * 8 + qk;
                __nv_bfloat16 b0 = __float2bfloat16(fexp(acc[ct][0] - dg0) + EPSILON);
                __nv_bfloat16 b1 = __float2bfloat16(fexp(acc[ct][1] - dg0) + EPSILON);
                __nv_bfloat16 b2 = __float2bfloat16(fexp(acc[ct][2] - dg1) + EPSILON);
                __nv_bfloat16 b3 = __float2bfloat16(fexp(acc[ct][3] - dg1) + EPSILON);
                den0 += __bfloat162float(b0) * ksr[2*ct] + __bfloat162float(b1) * ksr[2*ct+1];
                den1 += __bfloat162float(b2) * ksr[2*ct] + __bfloat162float(b3) * ksr[2*ct+1];
                *(uint32_t*)(WB + ((size_t)arow * 264 + mc) * 2)       = pkbf(b0, b1);
                *(uint32_t*)(WB + ((size_t)(arow + 8) * 264 + mc) * 2) = pkbf(b2, b3);
            }
            den0 += __shfl_xor_sync(0xffffffffu, den0, 1);
            den0 += __shfl_xor_sync(0xffffffffu, den0, 2);
            den1 += __shfl_xor_sync(0xffffffffu, den1, 1);
            den1 += __shfl_xor_sync(0xffffffffu, den1, 2);
            if ((lane & 3) == 0) {
                pden[arow * 8 + mq8] = den0;
                pden[(arow + 8) * 8 + mq8] = den1;
            }
        }
        __syncthreads();
        if (tid < 32) {
            float s = 0.0f;
            #pragma unroll
            for (int j = 0; j < 8; j++) s += pden[tid * 8 + j];
            dinv_s[tid] = 1.0f / s;
        }
        __syncthreads();
        // ---- out MMA: warp = 16n x 8e, k=256, single-bf16 ctx, x4 2-ks B frags ----
        {
            float oacc[4] = {};
            for (int ks2 = 0; ks2 < 8; ks2++) {
                uint32_t aw0[4], aw1[4], bc[4];
                ldsm4(aw0, aWB + (2 * ks2) * 32);
                ldsm4(aw1, aWB + (2 * ks2 + 1) * 32);
                ldsm4(bc, aCH + ks2 * 64);
                MMA(oacc, aw0, bc[0], bc[1]);
                MMA(oacc, aw1, bc[2], bc[3]);
            }
            float di0 = dinv_s[arow];
            float di1 = dinv_s[arow + 8];
            int nr = n0 + arow;
            int e = mq8 * 8 + qk;
            float* ob0 = out + ((size_t)head * NN + nr) * 64 + e;
            float* ob1 = out + ((size_t)head * NN + nr + 8) * 64 + e;
            ob0[0] = oacc[0] * di0;
            ob0[1] = oacc[1] * di0;
            ob1[0] = oacc[2] * di1;
            ob1[1] = oacc[3] * di1;
        }
    }
}

// ---------------- launch ----------------
extern "C" void kernel_launch(void* const* d_in, const int* in_sizes, int n_in,
                              void* d_out, int out_size) {
    const float* q = (const float*)d_in[0];
    const float* k = (const float*)d_in[1];
    const float* v = (const float*)d_in[2];
    const float* P = (const float*)d_in[3];
    float* out = (float*)d_out;

    cudaFuncSetAttribute(kA, cudaFuncAttributeMaxDynamicSharedMemorySize, A_SIZE);
    cudaFuncSetAttribute(kC, cudaFuncAttributeMaxDynamicSharedMemorySize, C_SIZE);

    k0_init<<<(NH * MM * DD + 255) / 256, 256>>>();
    kP<<<64, 256>>>(P);
    kA<<<dim3(8, NH), 512, A_SIZE>>>(k, v);
    kB<<<512, 256>>>();
    kC<<<dim3(16, NH), 512, C_SIZE>>>(q, out);
}

// round 11
// speedup vs baseline: 3.3280x; 1.3293x over previous
#include <cuda_runtime.h>
#include <cuda_bf16.h>
#include <stdint.h>

#define NH 64
#define NN 4096
#define DD 64
#define MM 256
#define SCALE   0.35355339059327379f   // 64^-0.25
#define EPSILON 1e-4f

// ---------------- scratch ----------------
__device__ float         g_ctxraw [NH*MM*DD];
__device__ float         g_ksumraw[NH*MM];
__device__ float         g_vsum   [NH*DD];
__device__ unsigned      g_gmax   [NH];
__device__ float         g_ksumf  [NH*MM];
__device__ __nv_bfloat16 g_Ph[MM*DD], g_Pl[MM*DD];   // P hi/lo [256 m][64 d]
__device__ __nv_bfloat16 g_Ch[NH*DD*MM];             // ctx^T [64 e][256 m] per head

// ---------------- helpers ----------------
__device__ __forceinline__ unsigned enc_f(float f) {
    unsigned u = __float_as_uint(f);
    return (u & 0x80000000u) ? ~u : (u | 0x80000000u);
}
__device__ __forceinline__ float dec_f(unsigned u) {
    return __uint_as_float((u & 0x80000000u) ? (u & 0x7fffffffu) : ~u);
}
__device__ __forceinline__ float fexp(float x) {
    float y = fmaxf(x * 1.4426950408889634f, -126.0f);
    float n = rintf(y);
    float f = y - n;
    float p = 1.5403530393381609e-4f;
    p = fmaf(p, f, 1.3333558146428443e-3f);
    p = fmaf(p, f, 9.6181291076284772e-3f);
    p = fmaf(p, f, 5.5504108664821580e-2f);
    p = fmaf(p, f, 2.4022650695910071e-1f);
    p = fmaf(p, f, 6.9314718055994531e-1f);
    p = fmaf(p, f, 1.0f);
    return p * __int_as_float(((int)n + 127) << 23);
}
__device__ __forceinline__ void MMA(float d[4], const uint32_t a[4], uint32_t b0, uint32_t b1) {
    asm volatile("mma.sync.aligned.m16n8k16.row.col.f32.bf16.bf16.f32 "
        "{%0,%1,%2,%3}, {%4,%5,%6,%7}, {%8,%9}, {%0,%1,%2,%3};"
        : "+f"(d[0]), "+f"(d[1]), "+f"(d[2]), "+f"(d[3])
        : "r"(a[0]), "r"(a[1]), "r"(a[2]), "r"(a[3]), "r"(b0), "r"(b1));
}
__device__ __forceinline__ uint32_t cvta_s(const void* p) {
    uint32_t a;
    asm("{ .reg .u64 t; cvta.to.shared.u64 t, %1; cvt.u32.u64 %0, t; }" : "=r"(a) : "l"(p));
    return a;
}
__device__ __forceinline__ void ldsm4(uint32_t r[4], uint32_t a) {
    asm volatile("ldmatrix.sync.aligned.m8n8.x4.shared.b16 {%0,%1,%2,%3}, [%4];"
        : "=r"(r[0]), "=r"(r[1]), "=r"(r[2]), "=r"(r[3]) : "r"(a));
}
__device__ __forceinline__ void ldsm4t(uint32_t r[4], uint32_t a) {
    asm volatile("ldmatrix.sync.aligned.m8n8.x4.trans.shared.b16 {%0,%1,%2,%3}, [%4];"
        : "=r"(r[0]), "=r"(r[1]), "=r"(r[2]), "=r"(r[3]) : "r"(a));
}
__device__ __forceinline__ void ldsm2t(uint32_t r[2], uint32_t a) {
    asm volatile("ldmatrix.sync.aligned.m8n8.x2.trans.shared.b16 {%0,%1}, [%2];"
        : "=r"(r[0]), "=r"(r[1]) : "r"(a));
}
__device__ __forceinline__ uint32_t pkbf(__nv_bfloat16 a, __nv_bfloat16 b) {
    uint16_t ua = *(uint16_t*)&a, ub = *(uint16_t*)&b;
    return (uint32_t)ua | ((uint32_t)ub << 16);
}
// 8 floats (2 float4) -> scale, hi/lo split, packed 16B stores; returns sum sq
__device__ __forceinline__ float cv8r(float4 u, float4 v, float scale, char* dhi, char* dlo) {
    float a[8] = {scale*u.x, scale*u.y, scale*u.z, scale*u.w,
                  scale*v.x, scale*v.y, scale*v.z, scale*v.w};
    float ss = 0.0f;
    __nv_bfloat16 h[8];
    uint32_t hw[4], lw[4];
    #pragma unroll
    for (int i = 0; i < 8; i++) { ss += a[i]*a[i]; h[i] = __float2bfloat16(a[i]); }
    #pragma unroll
    for (int i = 0; i < 4; i++) {
        hw[i] = pkbf(h[2*i], h[2*i+1]);
        lw[i] = pkbf(__float2bfloat16(a[2*i]   - __bfloat162float(h[2*i])),
                     __float2bfloat16(a[2*i+1] - __bfloat162float(h[2*i+1])));
    }
    *(uint4*)dhi = make_uint4(hw[0], hw[1], hw[2], hw[3]);
    *(uint4*)dlo = make_uint4(lw[0], lw[1], lw[2], lw[3]);
    return ss;
}
// 8 floats -> bf16 packed 16B store (no split)
__device__ __forceinline__ void cv8h(float4 u, float4 v, char* dst) {
    uint32_t hw[4];
    hw[0] = pkbf(__float2bfloat16(u.x), __float2bfloat16(u.y));
    hw[1] = pkbf(__float2bfloat16(u.z), __float2bfloat16(u.w));
    hw[2] = pkbf(__float2bfloat16(v.x), __float2bfloat16(v.y));
    hw[3] = pkbf(__float2bfloat16(v.z), __float2bfloat16(v.w));
    *(uint4*)dst = make_uint4(hw[0], hw[1], hw[2], hw[3]);
}

// ---------------- K0: init ----------------
__global__ void k0_init() {
    int i = blockIdx.x * blockDim.x + threadIdx.x;
    if (i < NH*MM*DD) g_ctxraw[i] = 0.0f;
    if (i < NH*MM)    g_ksumraw[i] = 0.0f;
    if (i < NH*DD)    g_vsum[i] = 0.0f;
    if (i < NH)       g_gmax[i] = enc_f(-1e30f);
}

// ---------------- kP: P bf16 hi/lo images ----------------
__global__ void kP(const float* __restrict__ P) {
    int i = blockIdx.x * 256 + threadIdx.x;
    float p = P[i];
    __nv_bfloat16 h = __float2bfloat16(p);
    g_Ph[i] = h;
    g_Pl[i] = __float2bfloat16(p - __bfloat162float(h));
}

// ---------------- kV: vsum[e] = sum_n V[n][e], coalesced ----------------
__global__ void kV(const float* __restrict__ V) {
    __shared__ float vs_s[64];
    int tid = threadIdx.x, head = blockIdx.y;
    if (tid < 64) vs_s[tid] = 0.0f;
    __syncthreads();
    const float* vb = V + (size_t)head * NN * DD;
    int e0 = (tid & 15) * 4;
    int rbase = blockIdx.x * 256 + (tid >> 4);
    float4 a = make_float4(0.f, 0.f, 0.f, 0.f);
    #pragma unroll 4
    for (int i = 0; i < 16; i++) {
        float4 v = *(const float4*)(vb + (size_t)(rbase + i * 16) * 64 + e0);
        a.x += v.x; a.y += v.y; a.z += v.z; a.w += v.w;
    }
    atomicAdd(&vs_s[e0], a.x);
    atomicAdd(&vs_s[e0 + 1], a.y);
    atomicAdd(&vs_s[e0 + 2], a.z);
    atomicAdd(&vs_s[e0 + 3], a.w);
    __syncthreads();
    if (tid < 64) atomicAdd(&g_vsum[head * DD + tid], vs_s[tid]);
}

// =============== kA: k-side fused, 512 thr, coalesced V + trans ldsm + prefetch ===============
#define A_PH   0        // [256][72] bf16
#define A_PL   36864
#define A_KH   73728    // [128][72]
#define A_KL   92160
#define A_VS   110592   // [128][72] bf16, natural [n][e]; col 64 = ones
#define A_W    129024   // [256][136] bf16 (w^T)
#define A_DIAG 198656   // 128 f32
#define A_RED  199168   // 512 f32
#define A_SIZE 201216

__global__ void __launch_bounds__(512, 1) kA(const float* __restrict__ K,
                                             const float* __restrict__ V) {
    extern __shared__ char smx[];
    int tid = threadIdx.x, wid = tid >> 5, lane = tid & 31;
    int lr = lane >> 2, qk = (lane & 3) * 2;
    int li = lane & 7;
    int t01 = (lane >> 3) & 1, t23 = (lane >> 4) & 1;
    int lrow = li + t01 * 8;          // 0..15 (trans-ldsm row within k16)
    int head = blockIdx.y;
    const float* kb = K + (size_t)head * NN * DD;
    const float* vb = V + (size_t)head * NN * DD;

    char* PH = smx + A_PH; char* PL = smx + A_PL;
    char* KH = smx + A_KH; char* KL = smx + A_KL;
    char* VS = smx + A_VS;
    char* W  = smx + A_W;
    float* diag_s = (float*)(smx + A_DIAG);
    float* red    = (float*)(smx + A_RED);

    for (int i = tid; i < 256 * 32; i += 512) {
        int m = i >> 5, dw = i & 31;
        ((uint32_t*)PH)[m * 36 + dw] = ((const uint32_t*)g_Ph)[i];
        ((uint32_t*)PL)[m * 36 + dw] = ((const uint32_t*)g_Pl)[i];
    }
    // VS pad cols 64..71: col64 = 1.0, rest 0 (never overwritten)
    if (tid < 128) {
        uint32_t one0 = pkbf(__float2bfloat16(1.0f), __float2bfloat16(0.0f));
        *(uint4*)(VS + tid * 144 + 128) = make_uint4(one0, 0u, 0u, 0u);
    }

    int nq = (wid & 3) * 32, mq = (wid >> 2) * 64;
    uint32_t aKH = cvta_s(KH) + (uint32_t)((nq + t01 * 8 + li) * 144) + t23 * 16;
    uint32_t aKL = aKH + (uint32_t)(A_KL - A_KH);
    uint32_t aPH = cvta_s(PH) + (uint32_t)((mq + t23 * 8 + li) * 144) + t01 * 16;
    uint32_t aPL = aPH + (uint32_t)(A_PL - A_PH);
    uint32_t aW  = cvta_s(W)  + (uint32_t)((wid * 16 + t01 * 8 + li) * 272) + t23 * 16;
    uint32_t aVT = cvta_s(VS) + (uint32_t)(lrow * 144) + (uint32_t)((lane >> 4) * 16);
    uint32_t aV1 = cvta_s(VS) + (uint32_t)(lrow * 144) + 128;

    // load/convert mapping: 4 threads per row, 16 floats each
    int kn = tid >> 2, kc = (tid & 3) * 16;

    // prefetch chunk 0
    float4 kr[4], vr[4];
    {
        const float* ks = kb + (size_t)(blockIdx.x * 512 + kn) * 64 + kc;
        const float* vs = vb + (size_t)(blockIdx.x * 512 + kn) * 64 + kc;
        #pragma unroll
        for (int j = 0; j < 4; j++) { kr[j] = *(const float4*)(ks + 4 * j); vr[j] = *(const float4*)(vs + 4 * j); }
    }

    float cacc[9][4] = {};
    float lmax = -1e30f;

    for (int ch = 0; ch < 4; ch++) {
        __syncthreads();
        // convert K (hi/lo + diag) and V (hi) from registers
        {
            char* dh = KH + kn * 144 + kc * 2;
            char* dl = KL + kn * 144 + kc * 2;
            float part = cv8r(kr[0], kr[1], SCALE, dh, dl);
            part      += cv8r(kr[2], kr[3], SCALE, dh + 16, dl + 16);
            part += __shfl_xor_sync(0xffffffffu, part, 1);
            part += __shfl_xor_sync(0xffffffffu, part, 2);
            if ((tid & 3) == 0) diag_s[kn] = 0.5f * part;
            cv8h(vr[0], vr[1], VS + kn * 144 + kc * 2);
            cv8h(vr[2], vr[3], VS + kn * 144 + kc * 2 + 16);
        }
        // prefetch next chunk
        if (ch < 3) {
            const float* ks = kb + (size_t)(blockIdx.x * 512 + (ch + 1) * 128 + kn) * 64 + kc;
            const float* vs = vb + (size_t)(blockIdx.x * 512 + (ch + 1) * 128 + kn) * 64 + kc;
            #pragma unroll
            for (int j = 0; j < 4; j++) { kr[j] = *(const float4*)(ks + 4 * j); vr[j] = *(const float4*)(vs + 4 * j); }
        }
        __syncthreads();
        // ---- dash MMA + exp epilogue: D[n][m] = Ks . P^T (3-split) ----
        for (int rt = 0; rt < 2; rt++) {
            int arow = nq + rt * 16 + lr;
            float dg0 = diag_s[arow], dg1 = diag_s[arow + 8];
            float acc[8][4] = {};
            for (int ks = 0; ks < 4; ks++) {
                uint32_t ah[4], al[4];
                ldsm4(ah, aKH + rt * 2304 + ks * 32);
                ldsm4(al, aKL + rt * 2304 + ks * 32);
                #pragma unroll
                for (int ctp = 0; ctp < 4; ctp++) {
                    uint32_t bh[4], bl[4];
                    ldsm4(bh, aPH + ctp * 2304 + ks * 32);
                    ldsm4(bl, aPL + ctp * 2304 + ks * 32);
                    MMA(acc[2*ctp],   ah, bh[0], bh[1]);
                    MMA(acc[2*ctp],   ah, bl[0], bl[1]);
                    MMA(acc[2*ctp],   al, bh[0], bh[1]);
                    MMA(acc[2*ctp+1], ah, bh[2], bh[3]);
                    MMA(acc[2*ctp+1], ah, bl[2], bl[3]);
                    MMA(acc[2*ctp+1], al, bh[2], bh[3]);
                }
            }
            #pragma unroll
            for (int ct = 0; ct < 8; ct++) {
                int mc = mq + ct * 8 + qk;
                float d0 = acc[ct][0], d1 = acc[ct][1], d2 = acc[ct][2], d3 = acc[ct][3];
                lmax = fmaxf(lmax, fmaxf(fmaxf(d0, d1), fmaxf(d2, d3)));
                float w0 = fexp(d0 - dg0), w1 = fexp(d1 - dg0);
                float w2 = fexp(d2 - dg1), w3 = fexp(d3 - dg1);
                *(__nv_bfloat16*)(W + ((size_t)mc * 136 + arow) * 2)           = __float2bfloat16(w0);
                *(__nv_bfloat16*)(W + ((size_t)(mc + 1) * 136 + arow) * 2)     = __float2bfloat16(w1);
                *(__nv_bfloat16*)(W + ((size_t)mc * 136 + arow + 8) * 2)       = __float2bfloat16(w2);
                *(__nv_bfloat16*)(W + ((size_t)(mc + 1) * 136 + arow + 8) * 2) = __float2bfloat16(w3);
            }
        }
        __syncthreads();
        // ---- ctx MMA: warp = 16 m rows x (64 e + ones col), V via trans ldsm ----
        for (int ks = 0; ks < 8; ks++) {
            uint32_t aw[4];
            ldsm4(aw, aW + ks * 32);
            #pragma unroll
            for (int etp = 0; etp < 4; etp++) {
                uint32_t bh[4];
                ldsm4t(bh, aVT + ks * 2304 + etp * 32);
                MMA(cacc[2*etp],   aw, bh[0], bh[1]);
                MMA(cacc[2*etp+1], aw, bh[2], bh[3]);
            }
            {
                uint32_t b2[2];
                ldsm2t(b2, aV1 + ks * 2304);
                MMA(cacc[8], aw, b2[0], b2[1]);
            }
        }
    }
    // ---- flush ----
    __syncthreads();
    red[tid] = lmax;
    __syncthreads();
    for (int s = 256; s > 0; s >>= 1) {
        if (tid < s) red[tid] = fmaxf(red[tid], red[tid + s]);
        __syncthreads();
    }
    if (tid == 0) atomicMax(&g_gmax[head], enc_f(red[0]));
    float* ctx = g_ctxraw + (size_t)head * MM * DD;
    {
        int m = wid * 16 + lr;
        #pragma unroll
        for (int et = 0; et < 8; et++) {
            int e = et * 8 + qk;
            atomicAdd(&ctx[m * 64 + e],           cacc[et][0]);
            atomicAdd(&ctx[m * 64 + e + 1],       cacc[et][1]);
            atomicAdd(&ctx[(m + 8) * 64 + e],     cacc[et][2]);
            atomicAdd(&ctx[(m + 8) * 64 + e + 1], cacc[et][3]);
        }
        if ((lane & 3) == 0) {
            atomicAdd(&g_ksumraw[head * MM + m],     cacc[8][0]);
            atomicAdd(&g_ksumraw[head * MM + m + 8], cacc[8][2]);
        }
    }
}

// =============== kB: finalize ===============
__global__ void kB() {
    int b = blockIdx.x, head = b >> 3, part = b & 7;
    int tid = threadIdx.x;
    float emx = fexp(-dec_f(g_gmax[head]));
    if (part == 0) g_ksumf[head * MM + tid] = emx * g_ksumraw[head * MM + tid] + EPSILON * (float)NN;
    int i0 = part * 2048;
    for (int i = i0 + tid; i < i0 + 2048; i += 256) {
        int m = i >> 6, e = i & 63;
        float cf = emx * g_ctxraw[(size_t)head * MM * DD + i] + EPSILON * g_vsum[head * DD + e];
        g_Ch[(size_t)head * 16384 + e * 256 + m] = __float2bfloat16(cf);
    }
}

// =============== kC: q-side fused, 512 thr, 64-row chunks + prefetch ===============
#define C_PH   0        // [256][72] bf16
#define C_PL   36864
#define C_CH   73728    // [64][264] bf16 (ctx^T)
#define C_QH   107520   // [64][72]
#define C_QL   116736
#define C_W    125952   // [64][264] bf16
#define C_KSUM 159744   // 256 f32
#define C_DIAG 160768   // 64 f32
#define C_MX   161024   // 64 f32
#define C_PM   161280   // 64*4 f32
#define C_PDEN 162304   // 64*4 f32
#define C_DINV 163328   // 64 f32
#define C_SIZE 163584

__global__ void __launch_bounds__(512, 1) kC(const float* __restrict__ Q,
                                             float* __restrict__ out) {
    extern __shared__ char smx[];
    int tid = threadIdx.x, wid = tid >> 5, lane = tid & 31;
    int lr = lane >> 2, qk = (lane & 3) * 2;
    int li = lane & 7;
    int t01 = (lane >> 3) & 1, t23 = (lane >> 4) & 1;
    int head = blockIdx.y;
    const float* qb = Q + (size_t)head * NN * DD;

    char* PH = smx + C_PH; char* PL = smx + C_PL;
    char* CH = smx + C_CH;
    char* QH = smx + C_QH; char* QL = smx + C_QL;
    char* WB = smx + C_W;
    float* ksum_s = (float*)(smx + C_KSUM);
    float* diag_s = (float*)(smx + C_DIAG);
    float* mxs    = (float*)(smx + C_MX);
    float* pm     = (float*)(smx + C_PM);
    float* pden   = (float*)(smx + C_PDEN);
    float* dinv_s = (float*)(smx + C_DINV);

    for (int i = tid; i < 256 * 32; i += 512) {
        int m = i >> 5, dw = i & 31;
        ((uint32_t*)PH)[m * 36 + dw] = ((const uint32_t*)g_Ph)[i];
        ((uint32_t*)PL)[m * 36 + dw] = ((const uint32_t*)g_Pl)[i];
    }
    for (int i = tid; i < 64 * 128; i += 512) {
        int e = i >> 7, mw = i & 127;
        ((uint32_t*)CH)[e * 132 + mw] = ((const uint32_t*)(g_Ch + (size_t)head * 16384))[i];
    }
    if (tid < 256) ksum_s[tid] = g_ksumf[head * MM + tid];

    int rt = wid & 3, g = wid >> 2;
    int arow = rt * 16 + lr;

    uint32_t aQH = cvta_s(QH) + (uint32_t)((rt * 16 + t01 * 8 + li) * 144) + t23 * 16;
    uint32_t aQL = aQH + (uint32_t)(C_QL - C_QH);
    uint32_t aPH = cvta_s(PH) + (uint32_t)((g * 64 + t23 * 8 + li) * 144) + t01 * 16;
    uint32_t aPL = aPH + (uint32_t)(C_PL - C_PH);
    uint32_t aWB = cvta_s(WB) + (uint32_t)((rt * 16 + t01 * 8 + li) * 528) + t23 * 16;
    uint32_t aCH0 = cvta_s(CH) + (uint32_t)((g * 16 + li) * 528) + (lane >> 3) * 16;
    uint32_t aCH1 = aCH0 + 8 * 528;

    // load/convert mapping: 8 threads per row, 8 floats each
    int qn = tid >> 3, qc = (tid & 7) * 8;

    // prefetch chunk 0
    float4 qr[2];
    {
        const float* src = qb + (size_t)(blockIdx.x * 256 + qn) * 64 + qc;
        qr[0] = *(const float4*)src; qr[1] = *(const float4*)(src + 4);
    }

    for (int ch = 0; ch < 4; ch++) {
        int n0 = blockIdx.x * 256 + ch * 64;
        __syncthreads();
        // convert Q (hi/lo + diag) from registers
        {
            char* dh = QH + qn * 144 + qc * 2;
            char* dl = QL + qn * 144 + qc * 2;
            float part = cv8r(qr[0], qr[1], SCALE, dh, dl);
            part += __shfl_xor_sync(0xffffffffu, part, 1);
            part += __shfl_xor_sync(0xffffffffu, part, 2);
            part += __shfl_xor_sync(0xffffffffu, part, 4);
            if ((tid & 7) == 0) diag_s[qn] = 0.5f * part;
        }
        if (ch < 3) {
            const float* src = qb + (size_t)(blockIdx.x * 256 + (ch + 1) * 64 + qn) * 64 + qc;
            qr[0] = *(const float4*)src; qr[1] = *(const float4*)(src + 4);
        }
        __syncthreads();
        // ---- dash MMA: warp = 16n x 64m (3-split) ----
        float acc[8][4] = {};
        for (int ks = 0; ks < 4; ks++) {
            uint32_t ah[4], al[4];
            ldsm4(ah, aQH + ks * 32);
            ldsm4(al, aQL + ks * 32);
            #pragma unroll
            for (int ctp = 0; ctp < 4; ctp++) {
                uint32_t bh[4], bl[4];
                ldsm4(bh, aPH + ctp * 2304 + ks * 32);
                ldsm4(bl, aPL + ctp * 2304 + ks * 32);
                MMA(acc[2*ctp],   ah, bh[0], bh[1]);
                MMA(acc[2*ctp],   ah, bl[0], bl[1]);
                MMA(acc[2*ctp],   al, bh[0], bh[1]);
                MMA(acc[2*ctp+1], ah, bh[2], bh[3]);
                MMA(acc[2*ctp+1], ah, bl[2], bl[3]);
                MMA(acc[2*ctp+1], al, bh[2], bh[3]);
            }
        }
        // ---- in-register rowmax (per warp over its 64 m) ----
        {
            float mx0 = -1e30f, mx1 = -1e30f;
            #pragma unroll
            for (int ct = 0; ct < 8; ct++) {
                mx0 = fmaxf(mx0, fmaxf(acc[ct][0], acc[ct][1]));
                mx1 = fmaxf(mx1, fmaxf(acc[ct][2], acc[ct][3]));
            }
            mx0 = fmaxf(mx0, __shfl_xor_sync(0xffffffffu, mx0, 1));
            mx0 = fmaxf(mx0, __shfl_xor_sync(0xffffffffu, mx0, 2));
            mx1 = fmaxf(mx1, __shfl_xor_sync(0xffffffffu, mx1, 1));
            mx1 = fmaxf(mx1, __shfl_xor_sync(0xffffffffu, mx1, 2));
            if ((lane & 3) == 0) {
                pm[arow * 4 + g] = mx0;
                pm[(arow + 8) * 4 + g] = mx1;
            }
        }
        __syncthreads();
        if (tid < 64) {
            float m = fmaxf(fmaxf(pm[tid * 4], pm[tid * 4 + 1]),
                            fmaxf(pm[tid * 4 + 2], pm[tid * 4 + 3]));
            mxs[tid] = m;
        }
        __syncthreads();
        // ---- exp + den + W write ----
        {
            float dg0 = diag_s[arow] + mxs[arow];
            float dg1 = diag_s[arow + 8] + mxs[arow + 8];
            float den0 = 0.0f, den1 = 0.0f;
            #pragma unroll
            for (int ct = 0; ct < 8; ct++) {
                int mc = g * 64 + ct * 8 + qk;
                __nv_bfloat16 b0 = __float2bfloat16(fexp(acc[ct][0] - dg0) + EPSILON);
                __nv_bfloat16 b1 = __float2bfloat16(fexp(acc[ct][1] - dg0) + EPSILON);
                __nv_bfloat16 b2 = __float2bfloat16(fexp(acc[ct][2] - dg1) + EPSILON);
                __nv_bfloat16 b3 = __float2bfloat16(fexp(acc[ct][3] - dg1) + EPSILON);
                den0 += __bfloat162float(b0) * ksum_s[mc] + __bfloat162float(b1) * ksum_s[mc + 1];
                den1 += __bfloat162float(b2) * ksum_s[mc] + __bfloat162float(b3) * ksum_s[mc + 1];
                *(uint32_t*)(WB + ((size_t)arow * 264 + mc) * 2)       = pkbf(b0, b1);
                *(uint32_t*)(WB + ((size_t)(arow + 8) * 264 + mc) * 2) = pkbf(b2, b3);
            }
            den0 += __shfl_xor_sync(0xffffffffu, den0, 1);
            den0 += __shfl_xor_sync(0xffffffffu, den0, 2);
            den1 += __shfl_xor_sync(0xffffffffu, den1, 1);
            den1 += __shfl_xor_sync(0xffffffffu, den1, 2);
            if ((lane & 3) == 0) {
                pden[arow * 4 + g] = den0;
                pden[(arow + 8) * 4 + g] = den1;
            }
        }
        __syncthreads();
        if (tid < 64) {
            float s = pden[tid * 4] + pden[tid * 4 + 1] + pden[tid * 4 + 2] + pden[tid * 4 + 3];
            dinv_s[tid] = 1.0f / s;
        }
        __syncthreads();
        // ---- out MMA: warp = 16n x 16e, k=256 ----
        {
            float oacc[2][4] = {};
            for (int ks2 = 0; ks2 < 8; ks2++) {
                uint32_t aw0[4], aw1[4], bc0[4], bc1[4];
                ldsm4(aw0, aWB + (2 * ks2) * 32);
                ldsm4(aw1, aWB + (2 * ks2 + 1) * 32);
                ldsm4(bc0, aCH0 + ks2 * 64);
                ldsm4(bc1, aCH1 + ks2 * 64);
                MMA(oacc[0], aw0, bc0[0], bc0[1]);
                MMA(oacc[0], aw1, bc0[2], bc0[3]);
                MMA(oacc[1], aw0, bc1[0], bc1[1]);
                MMA(oacc[1], aw1, bc1[2], bc1[3]);
            }
            float di0 = dinv_s[arow];
            float di1 = dinv_s[arow + 8];
            int nr = n0 + arow;
            #pragma unroll
            for (int et = 0; et < 2; et++) {
                int e = g * 16 + et * 8 + qk;
                float* ob0 = out + ((size_t)head * NN + nr) * 64 + e;
                float* ob1 = out + ((size_t)head * NN + nr + 8) * 64 + e;
                ob0[0] = oacc[et][0] * di0;
                ob0[1] = oacc[et][1] * di0;
                ob1[0] = oacc[et][2] * di1;
                ob1[1] = oacc[et][3] * di1;
            }
        }
    }
}

// ---------------- launch ----------------
extern "C" void kernel_launch(void* const* d_in, const int* in_sizes, int n_in,
                              void* d_out, int out_size) {
    const float* q = (const float*)d_in[0];
    const float* k = (const float*)d_in[1];
    const float* v = (const float*)d_in[2];
    const float* P = (const float*)d_in[3];
    float* out = (float*)d_out;

    cudaFuncSetAttribute(kA, cudaFuncAttributeMaxDynamicSharedMemorySize, A_SIZE);
    cudaFuncSetAttribute(kC, cudaFuncAttributeMaxDynamicSharedMemorySize, C_SIZE);

    k0_init<<<(NH * MM * DD + 255) / 256, 256>>>();
    kP<<<64, 256>>>(P);
    kV<<<dim3(16, NH), 256>>>(v);
    kA<<<dim3(8, NH), 512, A_SIZE>>>(k, v);
    kB<<<512, 256>>>();
    kC<<<dim3(16, NH), 512, C_SIZE>>>(q, out);
}

// round 12
// speedup vs baseline: 3.4995x; 1.0515x over previous
#include <cuda_runtime.h>
#include <cuda_bf16.h>
#include <stdint.h>

#define NH 64
#define NN 4096
#define DD 64
#define MM 256
#define SCALE   0.35355339059327379f   // 64^-0.25
#define EPSILON 1e-4f

// ---------------- scratch ----------------
__device__ float         g_ctxraw [NH*MM*DD];
__device__ float         g_ksumraw[NH*MM];
__device__ float         g_vsum   [NH*DD];
__device__ unsigned      g_gmax   [NH];
__device__ float         g_ksumf  [NH*MM];
__device__ __nv_bfloat16 g_Ph[MM*DD], g_Pl[MM*DD];   // P hi/lo [256 m][64 d]
__device__ __nv_bfloat16 g_Ch[NH*DD*MM];             // ctx^T [64 e][256 m] per head

// ---------------- helpers ----------------
__device__ __forceinline__ unsigned enc_f(float f) {
    unsigned u = __float_as_uint(f);
    return (u & 0x80000000u) ? ~u : (u | 0x80000000u);
}
__device__ __forceinline__ float dec_f(unsigned u) {
    return __uint_as_float((u & 0x80000000u) ? (u & 0x7fffffffu) : ~u);
}
__device__ __forceinline__ float fexp(float x) {
    float y = fmaxf(x * 1.4426950408889634f, -126.0f);
    float n = rintf(y);
    float f = y - n;
    float p = 1.5403530393381609e-4f;
    p = fmaf(p, f, 1.3333558146428443e-3f);
    p = fmaf(p, f, 9.6181291076284772e-3f);
    p = fmaf(p, f, 5.5504108664821580e-2f);
    p = fmaf(p, f, 2.4022650695910071e-1f);
    p = fmaf(p, f, 6.9314718055994531e-1f);
    p = fmaf(p, f, 1.0f);
    return p * __int_as_float(((int)n + 127) << 23);
}
__device__ __forceinline__ void MMA(float d[4], const uint32_t a[4], uint32_t b0, uint32_t b1) {
    asm volatile("mma.sync.aligned.m16n8k16.row.col.f32.bf16.bf16.f32 "
        "{%0,%1,%2,%3}, {%4,%5,%6,%7}, {%8,%9}, {%0,%1,%2,%3};"
        : "+f"(d[0]), "+f"(d[1]), "+f"(d[2]), "+f"(d[3])
        : "r"(a[0]), "r"(a[1]), "r"(a[2]), "r"(a[3]), "r"(b0), "r"(b1));
}
__device__ __forceinline__ uint32_t cvta_s(const void* p) {
    uint32_t a;
    asm("{ .reg .u64 t; cvta.to.shared.u64 t, %1; cvt.u32.u64 %0, t; }" : "=r"(a) : "l"(p));
    return a;
}
__device__ __forceinline__ void ldsm4(uint32_t r[4], uint32_t a) {
    asm volatile("ldmatrix.sync.aligned.m8n8.x4.shared.b16 {%0,%1,%2,%3}, [%4];"
        : "=r"(r[0]), "=r"(r[1]), "=r"(r[2]), "=r"(r[3]) : "r"(a));
}
__device__ __forceinline__ void ldsm4t(uint32_t r[4], uint32_t a) {
    asm volatile("ldmatrix.sync.aligned.m8n8.x4.trans.shared.b16 {%0,%1,%2,%3}, [%4];"
        : "=r"(r[0]), "=r"(r[1]), "=r"(r[2]), "=r"(r[3]) : "r"(a));
}
__device__ __forceinline__ void ldsm2t(uint32_t r[2], uint32_t a) {
    asm volatile("ldmatrix.sync.aligned.m8n8.x2.trans.shared.b16 {%0,%1}, [%2];"
        : "=r"(r[0]), "=r"(r[1]) : "r"(a));
}
__device__ __forceinline__ uint32_t pkbf(__nv_bfloat16 a, __nv_bfloat16 b) {
    uint16_t ua = *(uint16_t*)&a, ub = *(uint16_t*)&b;
    return (uint32_t)ua | ((uint32_t)ub << 16);
}
// 8 floats (2 float4) -> scale, hi/lo split, packed 16B stores; returns sum sq
__device__ __forceinline__ float cv8r(float4 u, float4 v, float scale, char* dhi, char* dlo) {
    float a[8] = {scale*u.x, scale*u.y, scale*u.z, scale*u.w,
                  scale*v.x, scale*v.y, scale*v.z, scale*v.w};
    float ss = 0.0f;
    __nv_bfloat16 h[8];
    uint32_t hw[4], lw[4];
    #pragma unroll
    for (int i = 0; i < 8; i++) { ss += a[i]*a[i]; h[i] = __float2bfloat16(a[i]); }
    #pragma unroll
    for (int i = 0; i < 4; i++) {
        hw[i] = pkbf(h[2*i], h[2*i+1]);
        lw[i] = pkbf(__float2bfloat16(a[2*i]   - __bfloat162float(h[2*i])),
                     __float2bfloat16(a[2*i+1] - __bfloat162float(h[2*i+1])));
    }
    *(uint4*)dhi = make_uint4(hw[0], hw[1], hw[2], hw[3]);
    *(uint4*)dlo = make_uint4(lw[0], lw[1], lw[2], lw[3]);
    return ss;
}
// 8 floats -> bf16 packed 16B store (no split)
__device__ __forceinline__ void cv8h(float4 u, float4 v, char* dst) {
    uint32_t hw[4];
    hw[0] = pkbf(__float2bfloat16(u.x), __float2bfloat16(u.y));
    hw[1] = pkbf(__float2bfloat16(u.z), __float2bfloat16(u.w));
    hw[2] = pkbf(__float2bfloat16(v.x), __float2bfloat16(v.y));
    hw[3] = pkbf(__float2bfloat16(v.z), __float2bfloat16(v.w));
    *(uint4*)dst = make_uint4(hw[0], hw[1], hw[2], hw[3]);
}

// ---------------- K0: init ----------------
__global__ void k0_init() {
    int i = blockIdx.x * blockDim.x + threadIdx.x;
    if (i < NH*MM*DD) g_ctxraw[i] = 0.0f;
    if (i < NH*MM)    g_ksumraw[i] = 0.0f;
    if (i < NH*DD)    g_vsum[i] = 0.0f;
    if (i < NH)       g_gmax[i] = enc_f(-1e30f);
}

// ---------------- kP: P bf16 hi/lo images ----------------
__global__ void kP(const float* __restrict__ P) {
    int i = blockIdx.x * 256 + threadIdx.x;
    float p = P[i];
    __nv_bfloat16 h = __float2bfloat16(p);
    g_Ph[i] = h;
    g_Pl[i] = __float2bfloat16(p - __bfloat162float(h));
}

// ---------------- kV: vsum[e] = sum_n V[n][e], coalesced ----------------
__global__ void kV(const float* __restrict__ V) {
    __shared__ float vs_s[64];
    int tid = threadIdx.x, head = blockIdx.y;
    if (tid < 64) vs_s[tid] = 0.0f;
    __syncthreads();
    const float* vb = V + (size_t)head * NN * DD;
    int e0 = (tid & 15) * 4;
    int rbase = blockIdx.x * 256 + (tid >> 4);
    float4 a = make_float4(0.f, 0.f, 0.f, 0.f);
    #pragma unroll 4
    for (int i = 0; i < 16; i++) {
        float4 v = *(const float4*)(vb + (size_t)(rbase + i * 16) * 64 + e0);
        a.x += v.x; a.y += v.y; a.z += v.z; a.w += v.w;
    }
    atomicAdd(&vs_s[e0], a.x);
    atomicAdd(&vs_s[e0 + 1], a.y);
    atomicAdd(&vs_s[e0 + 2], a.z);
    atomicAdd(&vs_s[e0 + 3], a.w);
    __syncthreads();
    if (tid < 64) atomicAdd(&g_vsum[head * DD + tid], vs_s[tid]);
}

// =============== kA: k-side fused, m-split for 2 CTAs/SM ===============
// grid (8, 2, NH): x = 512-row n-block, y = m-half (128 m), z = head
#define A_PH   0        // [128][72] bf16 (this CTA's m-half of P hi)
#define A_PL   18432    // [128][72]
#define A_KH   36864    // [64][72]
#define A_KL   46080
#define A_VS   55296    // [64][72] natural [n][e]; col 64 = ones
#define A_W    64512    // [128 m][72 n] bf16 (w^T)
#define A_DIAG 82944    // 64 f32
#define A_RED  83200    // 512 f32
#define A_SIZE 85248

__global__ void __launch_bounds__(512, 2) kA(const float* __restrict__ K,
                                             const float* __restrict__ V) {
    extern __shared__ char smx[];
    int tid = threadIdx.x, wid = tid >> 5, lane = tid & 31;
    int lr = lane >> 2, qk = (lane & 3) * 2;
    int li = lane & 7;
    int t01 = (lane >> 3) & 1, t23 = (lane >> 4) & 1;
    int lrow = li + t01 * 8;
    int head = blockIdx.z, mh = blockIdx.y;
    const float* kb = K + (size_t)head * NN * DD;
    const float* vb = V + (size_t)head * NN * DD;

    char* PH = smx + A_PH; char* PL = smx + A_PL;
    char* KH = smx + A_KH; char* KL = smx + A_KL;
    char* VS = smx + A_VS;
    char* W  = smx + A_W;
    float* diag_s = (float*)(smx + A_DIAG);
    float* red    = (float*)(smx + A_RED);

    // persistent: this m-half of P (hi/lo), repad 64 -> 72 elems/row
    for (int i = tid; i < 128 * 32; i += 512) {
        int m = i >> 5, dw = i & 31;
        ((uint32_t*)PH)[m * 36 + dw] = ((const uint32_t*)g_Ph)[mh * 4096 + i];
        ((uint32_t*)PL)[m * 36 + dw] = ((const uint32_t*)g_Pl)[mh * 4096 + i];
    }
    // VS pad cols 64..71: col64 = 1.0, rest 0
    if (tid < 64) {
        uint32_t one0 = pkbf(__float2bfloat16(1.0f), __float2bfloat16(0.0f));
        *(uint4*)(VS + tid * 144 + 128) = make_uint4(one0, 0u, 0u, 0u);
    }

    int nw2 = wid >> 2;   // dash n-tile (16 n)
    int mw2 = wid & 3;    // dash m-tile (32 m)
    int cmw = wid >> 1;   // ctx m-tile (16 m)
    int cew = wid & 1;    // ctx e-half (32 e)

    uint32_t aKH = cvta_s(KH) + (uint32_t)((nw2 * 16 + t01 * 8 + li) * 144) + t23 * 16;
    uint32_t aKL = aKH + (uint32_t)(A_KL - A_KH);
    uint32_t aPH = cvta_s(PH) + (uint32_t)((mw2 * 32 + t23 * 8 + li) * 144) + t01 * 16;
    uint32_t aPL = aPH + (uint32_t)(A_PL - A_PH);
    uint32_t aW  = cvta_s(W)  + (uint32_t)((cmw * 16 + t01 * 8 + li) * 144) + t23 * 16;
    uint32_t aVT = cvta_s(VS) + (uint32_t)(lrow * 144) + (uint32_t)(cew * 64) + (uint32_t)((lane >> 4) * 16);
    uint32_t aV1 = cvta_s(VS) + (uint32_t)(lrow * 144) + 128;

    // load/convert mapping: 8 threads per row, 8 floats each (64 rows)
    int kn = tid >> 3, kc = (tid & 7) * 8;

    float cacc[4][4] = {};
    float cone[4] = {};
    float lmax = -1e30f;

    for (int ch = 0; ch < 8; ch++) {
        int n0 = blockIdx.x * 512 + ch * 64;
        __syncthreads();
        // convert K (hi/lo + diag) and V (hi)
        {
            const float* ks = kb + (size_t)(n0 + kn) * 64 + kc;
            float4 k0 = *(const float4*)ks, k1 = *(const float4*)(ks + 4);
            float part = cv8r(k0, k1, SCALE, KH + kn * 144 + kc * 2, KL + kn * 144 + kc * 2);
            part += __shfl_xor_sync(0xffffffffu, part, 1);
            part += __shfl_xor_sync(0xffffffffu, part, 2);
            part += __shfl_xor_sync(0xffffffffu, part, 4);
            if ((tid & 7) == 0) diag_s[kn] = 0.5f * part;
            const float* vs = vb + (size_t)(n0 + kn) * 64 + kc;
            float4 v0 = *(const float4*)vs, v1 = *(const float4*)(vs + 4);
            cv8h(v0, v1, VS + kn * 144 + kc * 2);
        }
        __syncthreads();
        // ---- dash MMA + exp epilogue: warp = 16n x 32m (3-split) ----
        {
            int arow = nw2 * 16 + lr;
            float dg0 = diag_s[arow], dg1 = diag_s[arow + 8];
            float acc[4][4] = {};
            for (int ks = 0; ks < 4; ks++) {
                uint32_t ah[4], al[4];
                ldsm4(ah, aKH + ks * 32);
                ldsm4(al, aKL + ks * 32);
                #pragma unroll
                for (int ctp = 0; ctp < 2; ctp++) {
                    uint32_t bh[4], bl[4];
                    ldsm4(bh, aPH + ctp * 2304 + ks * 32);
                    ldsm4(bl, aPL + ctp * 2304 + ks * 32);
                    MMA(acc[2*ctp],   ah, bh[0], bh[1]);
                    MMA(acc[2*ctp],   ah, bl[0], bl[1]);
                    MMA(acc[2*ctp],   al, bh[0], bh[1]);
                    MMA(acc[2*ctp+1], ah, bh[2], bh[3]);
                    MMA(acc[2*ctp+1], ah, bl[2], bl[3]);
                    MMA(acc[2*ctp+1], al, bh[2], bh[3]);
                }
            }
            #pragma unroll
            for (int ct = 0; ct < 4; ct++) {
                int mc = mw2 * 32 + ct * 8 + qk;
                float d0 = acc[ct][0], d1 = acc[ct][1], d2 = acc[ct][2], d3 = acc[ct][3];
                lmax = fmaxf(lmax, fmaxf(fmaxf(d0, d1), fmaxf(d2, d3)));
                float w0 = fexp(d0 - dg0), w1 = fexp(d1 - dg0);
                float w2 = fexp(d2 - dg1), w3 = fexp(d3 - dg1);
                *(__nv_bfloat16*)(W + (size_t)mc * 144 + arow * 2)             = __float2bfloat16(w0);
                *(__nv_bfloat16*)(W + (size_t)(mc + 1) * 144 + arow * 2)       = __float2bfloat16(w1);
                *(__nv_bfloat16*)(W + (size_t)mc * 144 + (arow + 8) * 2)       = __float2bfloat16(w2);
                *(__nv_bfloat16*)(W + (size_t)(mc + 1) * 144 + (arow + 8) * 2) = __float2bfloat16(w3);
            }
        }
        __syncthreads();
        // ---- ctx MMA: warp = 16m x 32e (+ ones col for cew==0), k=64 ----
        for (int ks = 0; ks < 4; ks++) {
            uint32_t aw[4];
            ldsm4(aw, aW + ks * 32);
            #pragma unroll
            for (int etp = 0; etp < 2; etp++) {
                uint32_t bh[4];
                ldsm4t(bh, aVT + ks * 2304 + etp * 32);
                MMA(cacc[2*etp],   aw, bh[0], bh[1]);
                MMA(cacc[2*etp+1], aw, bh[2], bh[3]);
            }
            if (cew == 0) {
                uint32_t b2[2];
                ldsm2t(b2, aV1 + ks * 2304);
                MMA(cone, aw, b2[0], b2[1]);
            }
        }
    }
    // ---- flush ----
    __syncthreads();
    red[tid] = lmax;
    __syncthreads();
    for (int s = 256; s > 0; s >>= 1) {
        if (tid < s) red[tid] = fmaxf(red[tid], red[tid + s]);
        __syncthreads();
    }
    if (tid == 0) atomicMax(&g_gmax[head], enc_f(red[0]));
    float* ctx = g_ctxraw + (size_t)head * MM * DD;
    {
        int m = mh * 128 + cmw * 16 + lr;
        #pragma unroll
        for (int et = 0; et < 4; et++) {
            int e = cew * 32 + et * 8 + qk;
            atomicAdd(&ctx[m * 64 + e],           cacc[et][0]);
            atomicAdd(&ctx[m * 64 + e + 1],       cacc[et][1]);
            atomicAdd(&ctx[(m + 8) * 64 + e],     cacc[et][2]);
            atomicAdd(&ctx[(m + 8) * 64 + e + 1], cacc[et][3]);
        }
        if (cew == 0 && (lane & 3) == 0) {
            atomicAdd(&g_ksumraw[head * MM + m],     cone[0]);
            atomicAdd(&g_ksumraw[head * MM + m + 8], cone[2]);
        }
    }
}

// =============== kB: finalize ===============
__global__ void kB() {
    int b = blockIdx.x, head = b >> 3, part = b & 7;
    int tid = threadIdx.x;
    float emx = fexp(-dec_f(g_gmax[head]));
    if (part == 0) g_ksumf[head * MM + tid] = emx * g_ksumraw[head * MM + tid] + EPSILON * (float)NN;
    int i0 = part * 2048;
    for (int i = i0 + tid; i < i0 + 2048; i += 256) {
        int m = i >> 6, e = i & 63;
        float cf = emx * g_ctxraw[(size_t)head * MM * DD + i] + EPSILON * g_vsum[head * DD + e];
        g_Ch[(size_t)head * 16384 + e * 256 + m] = __float2bfloat16(cf);
    }
}

// =============== kC: q-side fused, 512 thr, 64-row chunks + prefetch ===============
#define C_PH   0        // [256][72] bf16
#define C_PL   36864
#define C_CH   73728    // [64][264] bf16 (ctx^T)
#define C_QH   107520   // [64][72]
#define C_QL   116736
#define C_W    125952   // [64][264] bf16
#define C_KSUM 159744   // 256 f32
#define C_DIAG 160768   // 64 f32
#define C_MX   161024   // 64 f32
#define C_PM   161280   // 64*4 f32
#define C_PDEN 162304   // 64*4 f32
#define C_DINV 163328   // 64 f32
#define C_SIZE 163584

__global__ void __launch_bounds__(512, 1) kC(const float* __restrict__ Q,
                                             float* __restrict__ out) {
    extern __shared__ char smx[];
    int tid = threadIdx.x, wid = tid >> 5, lane = tid & 31;
    int lr = lane >> 2, qk = (lane & 3) * 2;
    int li = lane & 7;
    int t01 = (lane >> 3) & 1, t23 = (lane >> 4) & 1;
    int head = blockIdx.y;
    const float* qb = Q + (size_t)head * NN * DD;

    char* PH = smx + C_PH; char* PL = smx + C_PL;
    char* CH = smx + C_CH;
    char* QH = smx + C_QH; char* QL = smx + C_QL;
    char* WB = smx + C_W;
    float* ksum_s = (float*)(smx + C_KSUM);
    float* diag_s = (float*)(smx + C_DIAG);
    float* mxs    = (float*)(smx + C_MX);
    float* pm     = (float*)(smx + C_PM);
    float* pden   = (float*)(smx + C_PDEN);
    float* dinv_s = (float*)(smx + C_DINV);

    for (int i = tid; i < 256 * 32; i += 512) {
        int m = i >> 5, dw = i & 31;
        ((uint32_t*)PH)[m * 36 + dw] = ((const uint32_t*)g_Ph)[i];
        ((uint32_t*)PL)[m * 36 + dw] = ((const uint32_t*)g_Pl)[i];
    }
    for (int i = tid; i < 64 * 128; i += 512) {
        int e = i >> 7, mw = i & 127;
        ((uint32_t*)CH)[e * 132 + mw] = ((const uint32_t*)(g_Ch + (size_t)head * 16384))[i];
    }
    if (tid < 256) ksum_s[tid] = g_ksumf[head * MM + tid];

    int rt = wid & 3, g = wid >> 2;
    int arow = rt * 16 + lr;

    uint32_t aQH = cvta_s(QH) + (uint32_t)((rt * 16 + t01 * 8 + li) * 144) + t23 * 16;
    uint32_t aQL = aQH + (uint32_t)(C_QL - C_QH);
    uint32_t aPH = cvta_s(PH) + (uint32_t)((g * 64 + t23 * 8 + li) * 144) + t01 * 16;
    uint32_t aPL = aPH + (uint32_t)(C_PL - C_PH);
    uint32_t aWB = cvta_s(WB) + (uint32_t)((rt * 16 + t01 * 8 + li) * 528) + t23 * 16;
    uint32_t aCH0 = cvta_s(CH) + (uint32_t)((g * 16 + li) * 528) + (lane >> 3) * 16;
    uint32_t aCH1 = aCH0 + 8 * 528;

    int qn = tid >> 3, qc = (tid & 7) * 8;

    // prefetch chunk 0
    float4 qr[2];
    {
        const float* src = qb + (size_t)(blockIdx.x * 256 + qn) * 64 + qc;
        qr[0] = *(const float4*)src; qr[1] = *(const float4*)(src + 4);
    }

    for (int ch = 0; ch < 4; ch++) {
        int n0 = blockIdx.x * 256 + ch * 64;
        __syncthreads();
        {
            char* dh = QH + qn * 144 + qc * 2;
            char* dl = QL + qn * 144 + qc * 2;
            float part = cv8r(qr[0], qr[1], SCALE, dh, dl);
            part += __shfl_xor_sync(0xffffffffu, part, 1);
            part += __shfl_xor_sync(0xffffffffu, part, 2);
            part += __shfl_xor_sync(0xffffffffu, part, 4);
            if ((tid & 7) == 0) diag_s[qn] = 0.5f * part;
        }
        if (ch < 3) {
            const float* src = qb + (size_t)(blockIdx.x * 256 + (ch + 1) * 64 + qn) * 64 + qc;
            qr[0] = *(const float4*)src; qr[1] = *(const float4*)(src + 4);
        }
        __syncthreads();
        // ---- dash MMA: warp = 16n x 64m (3-split) ----
        float acc[8][4] = {};
        for (int ks = 0; ks < 4; ks++) {
            uint32_t ah[4], al[4];
            ldsm4(ah, aQH + ks * 32);
            ldsm4(al, aQL + ks * 32);
            #pragma unroll
            for (int ctp = 0; ctp < 4; ctp++) {
                uint32_t bh[4], bl[4];
                ldsm4(bh, aPH + ctp * 2304 + ks * 32);
                ldsm4(bl, aPL + ctp * 2304 + ks * 32);
                MMA(acc[2*ctp],   ah, bh[0], bh[1]);
                MMA(acc[2*ctp],   ah, bl[0], bl[1]);
                MMA(acc[2*ctp],   al, bh[0], bh[1]);
                MMA(acc[2*ctp+1], ah, bh[2], bh[3]);
                MMA(acc[2*ctp+1], ah, bl[2], bl[3]);
                MMA(acc[2*ctp+1], al, bh[2], bh[3]);
            }
        }
        // ---- in-register rowmax ----
        {
            float mx0 = -1e30f, mx1 = -1e30f;
            #pragma unroll
            for (int ct = 0; ct < 8; ct++) {
                mx0 = fmaxf(mx0, fmaxf(acc[ct][0], acc[ct][1]));
                mx1 = fmaxf(mx1, fmaxf(acc[ct][2], acc[ct][3]));
            }
            mx0 = fmaxf(mx0, __shfl_xor_sync(0xffffffffu, mx0, 1));
            mx0 = fmaxf(mx0, __shfl_xor_sync(0xffffffffu, mx0, 2));
            mx1 = fmaxf(mx1, __shfl_xor_sync(0xffffffffu, mx1, 1));
            mx1 = fmaxf(mx1, __shfl_xor_sync(0xffffffffu, mx1, 2));
            if ((lane & 3) == 0) {
                pm[arow * 4 + g] = mx0;
                pm[(arow + 8) * 4 + g] = mx1;
            }
        }
        __syncthreads();
        if (tid < 64) {
            float m = fmaxf(fmaxf(pm[tid * 4], pm[tid * 4 + 1]),
                            fmaxf(pm[tid * 4 + 2], pm[tid * 4 + 3]));
            mxs[tid] = m;
        }
        __syncthreads();
        // ---- exp + den + W write ----
        {
            float dg0 = diag_s[arow] + mxs[arow];
            float dg1 = diag_s[arow + 8] + mxs[arow + 8];
            float den0 = 0.0f, den1 = 0.0f;
            #pragma unroll
            for (int ct = 0; ct < 8; ct++) {
                int mc = g * 64 + ct * 8 + qk;
                __nv_bfloat16 b0 = __float2bfloat16(fexp(acc[ct][0] - dg0) + EPSILON);
                __nv_bfloat16 b1 = __float2bfloat16(fexp(acc[ct][1] - dg0) + EPSILON);
                __nv_bfloat16 b2 = __float2bfloat16(fexp(acc[ct][2] - dg1) + EPSILON);
                __nv_bfloat16 b3 = __float2bfloat16(fexp(acc[ct][3] - dg1) + EPSILON);
                den0 += __bfloat162float(b0) * ksum_s[mc] + __bfloat162float(b1) * ksum_s[mc + 1];
                den1 += __bfloat162float(b2) * ksum_s[mc] + __bfloat162float(b3) * ksum_s[mc + 1];
                *(uint32_t*)(WB + ((size_t)arow * 264 + mc) * 2)       = pkbf(b0, b1);
                *(uint32_t*)(WB + ((size_t)(arow + 8) * 264 + mc) * 2) = pkbf(b2, b3);
            }
            den0 += __shfl_xor_sync(0xffffffffu, den0, 1);
            den0 += __shfl_xor_sync(0xffffffffu, den0, 2);
            den1 += __shfl_xor_sync(0xffffffffu, den1, 1);
            den1 += __shfl_xor_sync(0xffffffffu, den1, 2);
            if ((lane & 3) == 0) {
                pden[arow * 4 + g] = den0;
                pden[(arow + 8) * 4 + g] = den1;
            }
        }
        __syncthreads();
        if (tid < 64) {
            float s = pden[tid * 4] + pden[tid * 4 + 1] + pden[tid * 4 + 2] + pden[tid * 4 + 3];
            dinv_s[tid] = 1.0f / s;
        }
        __syncthreads();
        // ---- out MMA: warp = 16n x 16e, k=256 ----
        {
            float oacc[2][4] = {};
            for (int ks2 = 0; ks2 < 8; ks2++) {
                uint32_t aw0[4], aw1[4], bc0[4], bc1[4];
                ldsm4(aw0, aWB + (2 * ks2) * 32);
                ldsm4(aw1, aWB + (2 * ks2 + 1) * 32);
                ldsm4(bc0, aCH0 + ks2 * 64);
                ldsm4(bc1, aCH1 + ks2 * 64);
                MMA(oacc[0], aw0, bc0[0], bc0[1]);
                MMA(oacc[0], aw1, bc0[2], bc0[3]);
                MMA(oacc[1], aw0, bc1[0], bc1[1]);
                MMA(oacc[1], aw1, bc1[2], bc1[3]);
            }
            float di0 = dinv_s[arow];
            float di1 = dinv_s[arow + 8];
            int nr = n0 + arow;
            #pragma unroll
            for (int et = 0; et < 2; et++) {
                int e = g * 16 + et * 8 + qk;
                float* ob0 = out + ((size_t)head * NN + nr) * 64 + e;
                float* ob1 = out + ((size_t)head * NN + nr + 8) * 64 + e;
                ob0[0] = oacc[et][0] * di0;
                ob0[1] = oacc[et][1] * di0;
                ob1[0] = oacc[et][2] * di1;
                ob1[1] = oacc[et][3] * di1;
            }
        }
    }
}

// ---------------- launch ----------------
extern "C" void kernel_launch(void* const* d_in, const int* in_sizes, int n_in,
                              void* d_out, int out_size) {
    const float* q = (const float*)d_in[0];
    const float* k = (const float*)d_in[1];
    const float* v = (const float*)d_in[2];
    const float* P = (const float*)d_in[3];
    float* out = (float*)d_out;

    cudaFuncSetAttribute(kA, cudaFuncAttributeMaxDynamicSharedMemorySize, A_SIZE);
    cudaFuncSetAttribute(kC, cudaFuncAttributeMaxDynamicSharedMemorySize, C_SIZE);

    k0_init<<<(NH * MM * DD + 255) / 256, 256>>>();
    kP<<<64, 256>>>(P);
    kV<<<dim3(16, NH), 256>>>(v);
    kA<<<dim3(8, 2, NH), 512, A_SIZE>>>(k, v);
    kB<<<512, 256>>>();
    kC<<<dim3(16, NH), 512, C_SIZE>>>(q, out);
}

// round 16
// speedup vs baseline: 4.0535x; 1.1583x over previous
#include <cuda_runtime.h>
#include <cuda_fp16.h>
#include <stdint.h>

#define NH 64
#define NN 4096
#define DD 64
#define MM 256
#define SCALE   0.35355339059327379f   // 64^-0.25
#define EPSILON 1e-4f

// ---------------- scratch ----------------
__device__ float  g_ctxraw [NH*MM*DD];
__device__ float  g_ksumraw[NH*MM];
__device__ float  g_vsum   [NH*DD];
__device__ unsigned g_gmax [NH];
__device__ float  g_ksumf  [NH*MM];
__device__ __half g_Pf[MM*DD];        // P fp16 [256 m][64 d]
__device__ __half g_Ch[NH*DD*MM];     // ctx^T fp16 [64 e][256 m] per head

// ---------------- helpers ----------------
__device__ __forceinline__ unsigned enc_f(float f) {
    unsigned u = __float_as_uint(f);
    return (u & 0x80000000u) ? ~u : (u | 0x80000000u);
}
__device__ __forceinline__ float dec_f(unsigned u) {
    return __uint_as_float((u & 0x80000000u) ? (u & 0x7fffffffu) : ~u);
}
__device__ __forceinline__ float fexp(float x) {
    float y = fmaxf(x * 1.4426950408889634f, -126.0f);
    float n = rintf(y);
    float f = y - n;
    float p = 1.5403530393381609e-4f;
    p = fmaf(p, f, 1.3333558146428443e-3f);
    p = fmaf(p, f, 9.6181291076284772e-3f);
    p = fmaf(p, f, 5.5504108664821580e-2f);
    p = fmaf(p, f, 2.4022650695910071e-1f);
    p = fmaf(p, f, 6.9314718055994531e-1f);
    p = fmaf(p, f, 1.0f);
    return p * __int_as_float(((int)n + 127) << 23);
}
__device__ __forceinline__ void MMA(float d[4], const uint32_t a[4], uint32_t b0, uint32_t b1) {
    asm volatile("mma.sync.aligned.m16n8k16.row.col.f32.f16.f16.f32 "
        "{%0,%1,%2,%3}, {%4,%5,%6,%7}, {%8,%9}, {%0,%1,%2,%3};"
        : "+f"(d[0]), "+f"(d[1]), "+f"(d[2]), "+f"(d[3])
        : "r"(a[0]), "r"(a[1]), "r"(a[2]), "r"(a[3]), "r"(b0), "r"(b1));
}
__device__ __forceinline__ uint32_t cvta_s(const void* p) {
    uint32_t a;
    asm("{ .reg .u64 t; cvta.to.shared.u64 t, %1; cvt.u32.u64 %0, t; }" : "=r"(a) : "l"(p));
    return a;
}
__device__ __forceinline__ void ldsm4(uint32_t r[4], uint32_t a) {
    asm volatile("ldmatrix.sync.aligned.m8n8.x4.shared.b16 {%0,%1,%2,%3}, [%4];"
        : "=r"(r[0]), "=r"(r[1]), "=r"(r[2]), "=r"(r[3]) : "r"(a));
}
__device__ __forceinline__ void ldsm4t(uint32_t r[4], uint32_t a) {
    asm volatile("ldmatrix.sync.aligned.m8n8.x4.trans.shared.b16 {%0,%1,%2,%3}, [%4];"
        : "=r"(r[0]), "=r"(r[1]), "=r"(r[2]), "=r"(r[3]) : "r"(a));
}
__device__ __forceinline__ void ldsm2t(uint32_t r[2], uint32_t a) {
    asm volatile("ldmatrix.sync.aligned.m8n8.x2.trans.shared.b16 {%0,%1}, [%2];"
        : "=r"(r[0]), "=r"(r[1]) : "r"(a));
}
__device__ __forceinline__ uint32_t pkh(float a, float b) {
    __half2 h = __floats2half2_rn(a, b);
    return *(uint32_t*)&h;
}
// 8 floats -> scale -> fp16 packed 16B store; returns sum of squares
__device__ __forceinline__ float cv8f(float4 u, float4 v, float scale, char* dst) {
    float a[8] = {scale*u.x, scale*u.y, scale*u.z, scale*u.w,
                  scale*v.x, scale*v.y, scale*v.z, scale*v.w};
    float ss = 0.0f;
    #pragma unroll
    for (int i = 0; i < 8; i++) ss += a[i]*a[i];
    *(uint4*)dst = make_uint4(pkh(a[0],a[1]), pkh(a[2],a[3]), pkh(a[4],a[5]), pkh(a[6],a[7]));
    return ss;
}
__device__ __forceinline__ void cv8n(float4 u, float4 v, char* dst) {
    *(uint4*)dst = make_uint4(pkh(u.x,u.y), pkh(u.z,u.w), pkh(v.x,v.y), pkh(v.z,v.w));
}

// ---------------- K0: init ----------------
__global__ void k0_init() {
    int i = blockIdx.x * blockDim.x + threadIdx.x;
    if (i < NH*MM*DD) g_ctxraw[i] = 0.0f;
    if (i < NH*MM)    g_ksumraw[i] = 0.0f;
    if (i < NH*DD)    g_vsum[i] = 0.0f;
    if (i < NH)       g_gmax[i] = enc_f(-1e30f);
}

// ---------------- kP: P fp16 image ----------------
__global__ void kP(const float* __restrict__ P) {
    int i = blockIdx.x * 256 + threadIdx.x;
    g_Pf[i] = __float2half(P[i]);
}

// ---------------- kV: vsum[e] = sum_n V[n][e] ----------------
__global__ void kV(const float* __restrict__ V) {
    __shared__ float vs_s[64];
    int tid = threadIdx.x, head = blockIdx.y;
    if (tid < 64) vs_s[tid] = 0.0f;
    __syncthreads();
    const float* vb = V + (size_t)head * NN * DD;
    int e0 = (tid & 15) * 4;
    int rbase = blockIdx.x * 256 + (tid >> 4);
    float4 a = make_float4(0.f, 0.f, 0.f, 0.f);
    #pragma unroll 4
    for (int i = 0; i < 16; i++) {
        float4 v = *(const float4*)(vb + (size_t)(rbase + i * 16) * 64 + e0);
        a.x += v.x; a.y += v.y; a.z += v.z; a.w += v.w;
    }
    atomicAdd(&vs_s[e0], a.x);
    atomicAdd(&vs_s[e0 + 1], a.y);
    atomicAdd(&vs_s[e0 + 2], a.z);
    atomicAdd(&vs_s[e0 + 3], a.w);
    __syncthreads();
    if (tid < 64) atomicAdd(&g_vsum[head * DD + tid], vs_s[tid]);
}

// =============== kG: exact per-head gmax = max dash (fp16 MMA, max only) ===============
// 16 warps: warp = 16 n x 64 m
#define G_P    0        // [256 m][72] fp16
#define G_K    36864    // [64 n][72]
#define G_RED  46080    // 512 f32
#define G_SIZE 48128

__global__ void __launch_bounds__(512, 2) kG(const float* __restrict__ K) {
    extern __shared__ char smx[];
    int tid = threadIdx.x, wid = tid >> 5, lane = tid & 31;
    int li = lane & 7;
    int t01 = (lane >> 3) & 1, t23 = (lane >> 4) & 1;
    int head = blockIdx.y;
    const float* kb = K + (size_t)head * NN * DD;

    char* Pm = smx + G_P;
    char* Km = smx + G_K;
    float* red = (float*)(smx + G_RED);

    for (int i = tid; i < 256 * 32; i += 512) {
        int m = i >> 5, dw = i & 31;
        ((uint32_t*)Pm)[m * 36 + dw] = ((const uint32_t*)g_Pf)[i];
    }

    int nw = wid & 3, mw = wid >> 2;   // warp: 16 n x 64 m
    uint32_t aK = cvta_s(Km) + (uint32_t)((nw * 16 + t01 * 8 + li) * 144) + t23 * 16;
    uint32_t aP = cvta_s(Pm) + (uint32_t)((mw * 64 + t23 * 8 + li) * 144) + t01 * 16;

    int kn = tid >> 3, kc = (tid & 7) * 8;
    float lmax = -1e30f;

    for (int ch = 0; ch < 8; ch++) {
        int n0 = blockIdx.x * 512 + ch * 64;
        __syncthreads();
        {
            const float* ks = kb + (size_t)(n0 + kn) * 64 + kc;
            float4 k0 = *(const float4*)ks, k1 = *(const float4*)(ks + 4);
            cv8f(k0, k1, SCALE, Km + kn * 144 + kc * 2);
        }
        __syncthreads();
        {
            float acc[8][4] = {};
            for (int ks = 0; ks < 4; ks++) {
                uint32_t a[4];
                ldsm4(a, aK + ks * 32);
                #pragma unroll
                for (int ctp = 0; ctp < 4; ctp++) {
                    uint32_t b[4];
                    ldsm4(b, aP + ctp * 2304 + ks * 32);
                    MMA(acc[2*ctp],   a, b[0], b[1]);
                    MMA(acc[2*ctp+1], a, b[2], b[3]);
                }
            }
            #pragma unroll
            for (int ct = 0; ct < 8; ct++)
                lmax = fmaxf(lmax, fmaxf(fmaxf(acc[ct][0], acc[ct][1]),
                                         fmaxf(acc[ct][2], acc[ct][3])));
        }
    }
    red[tid] = lmax;
    __syncthreads();
    for (int s = 256; s > 0; s >>= 1) {
        if (tid < s) red[tid] = fmaxf(red[tid], red[tid + s]);
        __syncthreads();
    }
    if (tid == 0) atomicMax(&g_gmax[head], enc_f(red[0]));
}

// =============== kA: k-side fused, fp16 w (gmax-normalized), 2 CTAs/SM ===============
// grid (8, 2, NH): x = 512-row n-block, y = m-half (128 m), z = head
#define A_P    0        // [128 m][72] fp16
#define A_K    18432    // [64 n][72]
#define A_VS   27648    // [64 n][72]  natural [n][e]; col 64 = ones
#define A_W    36864    // [64 n][136 m] fp16
#define A_DIAG 54272    // 64 f32
#define A_SIZE 54528

__global__ void __launch_bounds__(512, 2) kA(const float* __restrict__ K,
                                             const float* __restrict__ V) {
    extern __shared__ char smx[];
    int tid = threadIdx.x, wid = tid >> 5, lane = tid & 31;
    int lr = lane >> 2, qk = (lane & 3) * 2;
    int li = lane & 7;
    int t01 = (lane >> 3) & 1, t23 = (lane >> 4) & 1;
    int head = blockIdx.z, mh = blockIdx.y;
    const float* kb = K + (size_t)head * NN * DD;
    const float* vb = V + (size_t)head * NN * DD;
    float gmax = dec_f(g_gmax[head]);

    char* Pm = smx + A_P;
    char* Km = smx + A_K;
    char* VS = smx + A_VS;
    char* W  = smx + A_W;
    float* diag_s = (float*)(smx + A_DIAG);

    for (int i = tid; i < 128 * 32; i += 512) {
        int m = i >> 5, dw = i & 31;
        ((uint32_t*)Pm)[m * 36 + dw] = ((const uint32_t*)(g_Pf + (size_t)mh * 8192))[i];
    }
    if (tid < 64) {
        *(uint4*)(VS + tid * 144 + 128) = make_uint4(pkh(1.0f, 0.0f), 0u, 0u, 0u);
    }

    int nw2 = wid >> 2;   // dash n-tile (16 n)
    int mw2 = wid & 3;    // dash m-tile (32 m)
    int cm  = wid >> 1;   // ctx m-tile (16 m)
    int ce  = wid & 1;    // ctx e-half (32 e)

    uint32_t aK  = cvta_s(Km) + (uint32_t)((nw2 * 16 + t01 * 8 + li) * 144) + t23 * 16;
    uint32_t aP  = cvta_s(Pm) + (uint32_t)((mw2 * 32 + t23 * 8 + li) * 144) + t01 * 16;
    uint32_t aWt = cvta_s(W)  + (uint32_t)((li + t23 * 8) * 272) + (uint32_t)((cm * 16 + t01 * 8) * 2);
    // FIX: warp's 32-e tile base = ce*32 ELEMENTS (was ce*64 -> read ones col + OOB garbage)
    uint32_t aVt = cvta_s(VS) + (uint32_t)((li + t01 * 8) * 144) + (uint32_t)((ce * 32 + (lane >> 4) * 8) * 2);
    uint32_t aV1 = cvta_s(VS) + (uint32_t)((li + t01 * 8) * 144) + 128;

    int kn = tid >> 3, kc = (tid & 7) * 8;

    float cacc[4][4] = {};
    float cone[4] = {};

    for (int ch = 0; ch < 8; ch++) {
        int n0 = blockIdx.x * 512 + ch * 64;
        __syncthreads();
        {
            const float* ks = kb + (size_t)(n0 + kn) * 64 + kc;
            float4 k0 = *(const float4*)ks, k1 = *(const float4*)(ks + 4);
            float part = cv8f(k0, k1, SCALE, Km + kn * 144 + kc * 2);
            part += __shfl_xor_sync(0xffffffffu, part, 1);
            part += __shfl_xor_sync(0xffffffffu, part, 2);
            part += __shfl_xor_sync(0xffffffffu, part, 4);
            if ((tid & 7) == 0) diag_s[kn] = 0.5f * part;
            const float* vs = vb + (size_t)(n0 + kn) * 64 + kc;
            float4 v0 = *(const float4*)vs, v1 = *(const float4*)(vs + 4);
            cv8n(v0, v1, VS + kn * 144 + kc * 2);
        }
        __syncthreads();
        // ---- dash MMA + exp epilogue: warp = 16n x 32m, w = exp(d - diag - gmax) <= 1 ----
        {
            int arow = nw2 * 16 + lr;
            float dg0 = diag_s[arow] + gmax, dg1 = diag_s[arow + 8] + gmax;
            float acc[4][4] = {};
            for (int ks = 0; ks < 4; ks++) {
                uint32_t a[4];
                ldsm4(a, aK + ks * 32);
                #pragma unroll
                for (int ctp = 0; ctp < 2; ctp++) {
                    uint32_t b[4];
                    ldsm4(b, aP + ctp * 2304 + ks * 32);
                    MMA(acc[2*ctp],   a, b[0], b[1]);
                    MMA(acc[2*ctp+1], a, b[2], b[3]);
                }
            }
            #pragma unroll
            for (int ct = 0; ct < 4; ct++) {
                int mc = mw2 * 32 + ct * 8 + qk;
                float w0 = fexp(acc[ct][0] - dg0), w1 = fexp(acc[ct][1] - dg0);
                float w2 = fexp(acc[ct][2] - dg1), w3 = fexp(acc[ct][3] - dg1);
                *(uint32_t*)(W + (size_t)arow * 272 + mc * 2)       = pkh(w0, w1);
                *(uint32_t*)(W + (size_t)(arow + 8) * 272 + mc * 2) = pkh(w2, w3);
            }
        }
        __syncthreads();
        // ---- ctx MMA: warp = 16m x 32e (+ ones col if ce==0), k=64 ----
        for (int ks = 0; ks < 4; ks++) {
            uint32_t aw[4];
            ldsm4t(aw, aWt + ks * 4352);
            #pragma unroll
            for (int etp = 0; etp < 2; etp++) {
                uint32_t bv[4];
                ldsm4t(bv, aVt + ks * 2304 + etp * 32);
                MMA(cacc[2*etp],   aw, bv[0], bv[1]);
                MMA(cacc[2*etp+1], aw, bv[2], bv[3]);
            }
            if (ce == 0) {
                uint32_t b2[2];
                ldsm2t(b2, aV1 + ks * 2304);
                MMA(cone, aw, b2[0], b2[1]);
            }
        }
    }
    // ---- flush ----
    __syncthreads();
    float* ctx = g_ctxraw + (size_t)head * MM * DD;
    {
        int m = mh * 128 + cm * 16 + lr;
        #pragma unroll
        for (int et = 0; et < 4; et++) {
            int e = ce * 32 + et * 8 + qk;
            atomicAdd(&ctx[m * 64 + e],           cacc[et][0]);
            atomicAdd(&ctx[m * 64 + e + 1],       cacc[et][1]);
            atomicAdd(&ctx[(m + 8) * 64 + e],     cacc[et][2]);
            atomicAdd(&ctx[(m + 8) * 64 + e + 1], cacc[et][3]);
        }
        if (ce == 0 && (lane & 3) == 0) {
            atomicAdd(&g_ksumraw[head * MM + m],     cone[0]);
            atomicAdd(&g_ksumraw[head * MM + m + 8], cone[2]);
        }
    }
}

// =============== kB: finalize (weights already gmax-normalized) ===============
__global__ void kB() {
    int b = blockIdx.x, head = b >> 3, part = b & 7;
    int tid = threadIdx.x;
    if (part == 0) g_ksumf[head * MM + tid] = g_ksumraw[head * MM + tid] + EPSILON * (float)NN;
    int i0 = part * 2048;
    for (int i = i0 + tid; i < i0 + 2048; i += 256) {
        int m = i >> 6, e = i & 63;
        float cf = g_ctxraw[(size_t)head * MM * DD + i] + EPSILON * g_vsum[head * DD + e];
        g_Ch[(size_t)head * 16384 + e * 256 + m] = __float2half(cf);
    }
}

// =============== kC: q-side fused, fp16, 2 CTAs/SM, 32-row chunks ===============
#define C_P    0        // [256 m][72] fp16
#define C_CH   36864    // [64 e][264 m] fp16
#define C_Q    70656    // [32 n][72]
#define C_W    75264    // [32 n][264 m] fp16
#define C_KSUM 92160    // 256 f32
#define C_DIAG 93184    // 32 f32
#define C_MX   93312    // 32 f32
#define C_PM   93440    // 32*8 f32
#define C_PDEN 94464    // 32*8 f32
#define C_DINV 95488    // 32 f32
#define C_SIZE 95616

__global__ void __launch_bounds__(512, 2) kC(const float* __restrict__ Q,
                                             float* __restrict__ out) {
    extern __shared__ char smx[];
    int tid = threadIdx.x, wid = tid >> 5, lane = tid & 31;
    int lr = lane >> 2, qk = (lane & 3) * 2;
    int li = lane & 7;
    int t01 = (lane >> 3) & 1, t23 = (lane >> 4) & 1;
    int head = blockIdx.y;
    const float* qb = Q + (size_t)head * NN * DD;

    char* Pm = smx + C_P;
    char* CH = smx + C_CH;
    char* Qm = smx + C_Q;
    char* W  = smx + C_W;
    float* ksum_s = (float*)(smx + C_KSUM);
    float* diag_s = (float*)(smx + C_DIAG);
    float* mxs    = (float*)(smx + C_MX);
    float* pm     = (float*)(smx + C_PM);
    float* pden   = (float*)(smx + C_PDEN);
    float* dinv_s = (float*)(smx + C_DINV);

    for (int i = tid; i < 256 * 32; i += 512) {
        int m = i >> 5, dw = i & 31;
        ((uint32_t*)Pm)[m * 36 + dw] = ((const uint32_t*)g_Pf)[i];
    }
    for (int i = tid; i < 64 * 128; i += 512) {
        int e = i >> 7, mw = i & 127;
        ((uint32_t*)CH)[e * 132 + mw] = ((const uint32_t*)(g_Ch + (size_t)head * 16384))[i];
    }
    if (tid < 256) ksum_s[tid] = g_ksumf[head * MM + tid];

    int rt = wid & 1;     // n-tile (16 n)
    int g  = wid >> 1;    // dash m-tile (32 m) / out e-tile (8 e)
    int arow = rt * 16 + lr;

    uint32_t aQ  = cvta_s(Qm) + (uint32_t)((rt * 16 + t01 * 8 + li) * 144) + t23 * 16;
    uint32_t aP  = cvta_s(Pm) + (uint32_t)((g * 32 + t23 * 8 + li) * 144) + t01 * 16;
    uint32_t aWA = cvta_s(W)  + (uint32_t)((rt * 16 + t01 * 8 + li) * 528) + t23 * 16;
    uint32_t aCB = cvta_s(CH) + (uint32_t)((g * 8 + li) * 528) + (lane >> 3) * 16;

    int qn = tid >> 3, qc = (tid & 7) * 8;

    for (int ch = 0; ch < 8; ch++) {
        int n0 = blockIdx.x * 256 + ch * 32;
        __syncthreads();
        if (tid < 256) {
            const float* src = qb + (size_t)(n0 + qn) * 64 + qc;
            float4 u = *(const float4*)src, v = *(const float4*)(src + 4);
            float part = cv8f(u, v, SCALE, Qm + qn * 144 + qc * 2);
            part += __shfl_xor_sync(0xffffffffu, part, 1);
            part += __shfl_xor_sync(0xffffffffu, part, 2);
            part += __shfl_xor_sync(0xffffffffu, part, 4);
            if ((tid & 7) == 0) diag_s[qn] = 0.5f * part;
        }
        __syncthreads();
        // ---- dash MMA: warp = 16n x 32m, single fp16 ----
        float acc[4][4] = {};
        for (int ks = 0; ks < 4; ks++) {
            uint32_t a[4];
            ldsm4(a, aQ + ks * 32);
            #pragma unroll
            for (int ctp = 0; ctp < 2; ctp++) {
                uint32_t b[4];
                ldsm4(b, aP + ctp * 2304 + ks * 32);
                MMA(acc[2*ctp],   a, b[0], b[1]);
                MMA(acc[2*ctp+1], a, b[2], b[3]);
            }
        }
        // ---- rowmax ----
        {
            float mx0 = -1e30f, mx1 = -1e30f;
            #pragma unroll
            for (int ct = 0; ct < 4; ct++) {
                mx0 = fmaxf(mx0, fmaxf(acc[ct][0], acc[ct][1]));
                mx1 = fmaxf(mx1, fmaxf(acc[ct][2], acc[ct][3]));
            }
            mx0 = fmaxf(mx0, __shfl_xor_sync(0xffffffffu, mx0, 1));
            mx0 = fmaxf(mx0, __shfl_xor_sync(0xffffffffu, mx0, 2));
            mx1 = fmaxf(mx1, __shfl_xor_sync(0xffffffffu, mx1, 1));
            mx1 = fmaxf(mx1, __shfl_xor_sync(0xffffffffu, mx1, 2));
            if ((lane & 3) == 0) {
                pm[arow * 8 + g] = mx0;
                pm[(arow + 8) * 8 + g] = mx1;
            }
        }
        __syncthreads();
        if (tid < 32) {
            float m = -1e30f;
            #pragma unroll
            for (int j = 0; j < 8; j++) m = fmaxf(m, pm[tid * 8 + j]);
            mxs[tid] = m;
        }
        __syncthreads();
        // ---- exp + den + W write (fp16-consistent den) ----
        {
            float dg0 = diag_s[arow] + mxs[arow];
            float dg1 = diag_s[arow + 8] + mxs[arow + 8];
            float den0 = 0.0f, den1 = 0.0f;
            #pragma unroll
            for (int ct = 0; ct < 4; ct++) {
                int mc = g * 32 + ct * 8 + qk;
                float w0 = fexp(acc[ct][0] - dg0) + EPSILON;
                float w1 = fexp(acc[ct][1] - dg0) + EPSILON;
                float w2 = fexp(acc[ct][2] - dg1) + EPSILON;
                float w3 = fexp(acc[ct][3] - dg1) + EPSILON;
                uint32_t p01 = pkh(w0, w1), p23 = pkh(w2, w3);
                __half2 h01 = *(__half2*)&p01, h23 = *(__half2*)&p23;
                den0 += __half2float(h01.x) * ksum_s[mc] + __half2float(h01.y) * ksum_s[mc + 1];
                den1 += __half2float(h23.x) * ksum_s[mc] + __half2float(h23.y) * ksum_s[mc + 1];
                *(uint32_t*)(W + (size_t)arow * 528 + mc * 2)       = p01;
                *(uint32_t*)(W + (size_t)(arow + 8) * 528 + mc * 2) = p23;
            }
            den0 += __shfl_xor_sync(0xffffffffu, den0, 1);
            den0 += __shfl_xor_sync(0xffffffffu, den0, 2);
            den1 += __shfl_xor_sync(0xffffffffu, den1, 1);
            den1 += __shfl_xor_sync(0xffffffffu, den1, 2);
            if ((lane & 3) == 0) {
                pden[arow * 8 + g] = den0;
                pden[(arow + 8) * 8 + g] = den1;
            }
        }
        __syncthreads();
        if (tid < 32) {
            float s = 0.0f;
            #pragma unroll
            for (int j = 0; j < 8; j++) s += pden[tid * 8 + j];
            dinv_s[tid] = 1.0f / s;
        }
        __syncthreads();
        // ---- out MMA: warp = 16n x 8e, k=256 ----
        {
            float oacc[4] = {};
            for (int ks2 = 0; ks2 < 8; ks2++) {
                uint32_t aw0[4], aw1[4], bc[4];
                ldsm4(aw0, aWA + ks2 * 64);
                ldsm4(aw1, aWA + ks2 * 64 + 32);
                ldsm4(bc, aCB + ks2 * 64);
                MMA(oacc, aw0, bc[0], bc[1]);
                MMA(oacc, aw1, bc[2], bc[3]);
            }
            float di0 = dinv_s[arow];
            float di1 = dinv_s[arow + 8];
            int nr = n0 + arow;
            int e = g * 8 + qk;
            float* ob0 = out + ((size_t)head * NN + nr) * 64 + e;
            float* ob1 = out + ((size_t)head * NN + nr + 8) * 64 + e;
            ob0[0] = oacc[0] * di0;
            ob0[1] = oacc[1] * di0;
            ob1[0] = oacc[2] * di1;
            ob1[1] = oacc[3] * di1;
        }
    }
}

// ---------------- launch ----------------
extern "C" void kernel_launch(void* const* d_in, const int* in_sizes, int n_in,
                              void* d_out, int out_size) {
    const float* q = (const float*)d_in[0];
    const float* k = (const float*)d_in[1];
    const float* v = (const float*)d_in[2];
    const float* P = (const float*)d_in[3];
    float* out = (float*)d_out;

    cudaFuncSetAttribute(kG, cudaFuncAttributeMaxDynamicSharedMemorySize, G_SIZE);
    cudaFuncSetAttribute(kA, cudaFuncAttributeMaxDynamicSharedMemorySize, A_SIZE);
    cudaFuncSetAttribute(kC, cudaFuncAttributeMaxDynamicSharedMemorySize, C_SIZE);

    k0_init<<<(NH * MM * DD + 255) / 256, 256>>>();
    kP<<<64, 256>>>(P);
    kV<<<dim3(16, NH), 256>>>(v);
    kG<<<dim3(8, NH), 512, G_SIZE>>>(k);
    kA<<<dim3(8, 2, NH), 512, A_SIZE>>>(k, v);
    kB<<<512, 256>>>();
    kC<<<dim3(16, NH), 512, C_SIZE>>>(q, out);
}

// round 17
// speedup vs baseline: 4.4184x; 1.0900x over previous
#include <cuda_runtime.h>
#include <cuda_fp16.h>
#include <stdint.h>

#define NH 64
#define NN 4096
#define DD 64
#define MM 256
#define SCALE   0.35355339059327379f   // 64^-0.25
#define EPSILON 1e-4f

// ---------------- scratch ----------------
__device__ float  g_ctxraw [NH*MM*DD];
__device__ float  g_ksumraw[NH*MM];
__device__ float  g_vsum   [NH*DD];
__device__ unsigned g_gmax [NH];
__device__ float  g_ksumf  [NH*MM];
__device__ __half g_Pf[MM*DD];        // P fp16 [256 m][64 d]
__device__ __half g_Ch[NH*DD*MM];     // ctx^T fp16 [64 e][256 m] per head

// ---------------- helpers ----------------
__device__ __forceinline__ unsigned enc_f(float f) {
    unsigned u = __float_as_uint(f);
    return (u & 0x80000000u) ? ~u : (u | 0x80000000u);
}
__device__ __forceinline__ float dec_f(unsigned u) {
    return __uint_as_float((u & 0x80000000u) ? (u & 0x7fffffffu) : ~u);
}
__device__ __forceinline__ float fexp(float x) {
    float y = fmaxf(x * 1.4426950408889634f, -126.0f);
    float n = rintf(y);
    float f = y - n;
    float p = 1.5403530393381609e-4f;
    p = fmaf(p, f, 1.3333558146428443e-3f);
    p = fmaf(p, f, 9.6181291076284772e-3f);
    p = fmaf(p, f, 5.5504108664821580e-2f);
    p = fmaf(p, f, 2.4022650695910071e-1f);
    p = fmaf(p, f, 6.9314718055994531e-1f);
    p = fmaf(p, f, 1.0f);
    return p * __int_as_float(((int)n + 127) << 23);
}
__device__ __forceinline__ void MMA(float d[4], const uint32_t a[4], uint32_t b0, uint32_t b1) {
    asm volatile("mma.sync.aligned.m16n8k16.row.col.f32.f16.f16.f32 "
        "{%0,%1,%2,%3}, {%4,%5,%6,%7}, {%8,%9}, {%0,%1,%2,%3};"
        : "+f"(d[0]), "+f"(d[1]), "+f"(d[2]), "+f"(d[3])
        : "r"(a[0]), "r"(a[1]), "r"(a[2]), "r"(a[3]), "r"(b0), "r"(b1));
}
__device__ __forceinline__ uint32_t cvta_s(const void* p) {
    uint32_t a;
    asm("{ .reg .u64 t; cvta.to.shared.u64 t, %1; cvt.u32.u64 %0, t; }" : "=r"(a) : "l"(p));
    return a;
}
__device__ __forceinline__ void ldsm4(uint32_t r[4], uint32_t a) {
    asm volatile("ldmatrix.sync.aligned.m8n8.x4.shared.b16 {%0,%1,%2,%3}, [%4];"
        : "=r"(r[0]), "=r"(r[1]), "=r"(r[2]), "=r"(r[3]) : "r"(a));
}
__device__ __forceinline__ void ldsm4t(uint32_t r[4], uint32_t a) {
    asm volatile("ldmatrix.sync.aligned.m8n8.x4.trans.shared.b16 {%0,%1,%2,%3}, [%4];"
        : "=r"(r[0]), "=r"(r[1]), "=r"(r[2]), "=r"(r[3]) : "r"(a));
}
__device__ __forceinline__ void ldsm2t(uint32_t r[2], uint32_t a) {
    asm volatile("ldmatrix.sync.aligned.m8n8.x2.trans.shared.b16 {%0,%1}, [%2];"
        : "=r"(r[0]), "=r"(r[1]) : "r"(a));
}
__device__ __forceinline__ uint32_t pkh(float a, float b) {
    __half2 h = __floats2half2_rn(a, b);
    return *(uint32_t*)&h;
}
// 8 floats -> scale -> fp16 packed 16B store; returns sum of squares
__device__ __forceinline__ float cv8f(float4 u, float4 v, float scale, char* dst) {
    float a[8] = {scale*u.x, scale*u.y, scale*u.z, scale*u.w,
                  scale*v.x, scale*v.y, scale*v.z, scale*v.w};
    float ss = 0.0f;
    #pragma unroll
    for (int i = 0; i < 8; i++) ss += a[i]*a[i];
    *(uint4*)dst = make_uint4(pkh(a[0],a[1]), pkh(a[2],a[3]), pkh(a[4],a[5]), pkh(a[6],a[7]));
    return ss;
}
__device__ __forceinline__ void cv8n(float4 u, float4 v, char* dst) {
    *(uint4*)dst = make_uint4(pkh(u.x,u.y), pkh(u.z,u.w), pkh(v.x,v.y), pkh(v.z,v.w));
}

// ---------------- K0: init ----------------
__global__ void k0_init() {
    int i = blockIdx.x * blockDim.x + threadIdx.x;
    if (i < NH*MM*DD) g_ctxraw[i] = 0.0f;
    if (i < NH*MM)    g_ksumraw[i] = 0.0f;
    if (i < NH*DD)    g_vsum[i] = 0.0f;
    if (i < NH)       g_gmax[i] = enc_f(-1e30f);
}

// ---------------- kP: P fp16 image ----------------
__global__ void kP(const float* __restrict__ P) {
    int i = blockIdx.x * 256 + threadIdx.x;
    g_Pf[i] = __float2half(P[i]);
}

// ---------------- kV: vsum[e] = sum_n V[n][e] ----------------
__global__ void kV(const float* __restrict__ V) {
    __shared__ float vs_s[64];
    int tid = threadIdx.x, head = blockIdx.y;
    if (tid < 64) vs_s[tid] = 0.0f;
    __syncthreads();
    const float* vb = V + (size_t)head * NN * DD;
    int e0 = (tid & 15) * 4;
    int rbase = blockIdx.x * 256 + (tid >> 4);
    float4 a = make_float4(0.f, 0.f, 0.f, 0.f);
    #pragma unroll 4
    for (int i = 0; i < 16; i++) {
        float4 v = *(const float4*)(vb + (size_t)(rbase + i * 16) * 64 + e0);
        a.x += v.x; a.y += v.y; a.z += v.z; a.w += v.w;
    }
    atomicAdd(&vs_s[e0], a.x);
    atomicAdd(&vs_s[e0 + 1], a.y);
    atomicAdd(&vs_s[e0 + 2], a.z);
    atomicAdd(&vs_s[e0 + 3], a.w);
    __syncthreads();
    if (tid < 64) atomicAdd(&g_vsum[head * DD + tid], vs_s[tid]);
}

// =============== kA: k-side fused, fp16 w with ONLINE running max, 2 CTAs/SM ===============
// grid (8, 2, NH): x = 512-row n-block, y = m-half (128 m), z = head
// w_stored = exp(dash - diag - M_cta); flush scales by e^{M_cta}; kB applies e^{-gmax}.
#define A_P    0        // [128 m][72] fp16
#define A_K    18432    // [64 n][72]
#define A_VS   27648    // [64 n][72]  natural [n][e]; col 64 = ones
#define A_W    36864    // [64 n][136 m] fp16
#define A_DIAG 54272    // 64 f32
#define A_WMX  54528    // 16 f32
#define A_RED  54592    // 512 f32
#define A_SIZE 56640

__global__ void __launch_bounds__(512, 2) kA(const float* __restrict__ K,
                                             const float* __restrict__ V) {
    extern __shared__ char smx[];
    int tid = threadIdx.x, wid = tid >> 5, lane = tid & 31;
    int lr = lane >> 2, qk = (lane & 3) * 2;
    int li = lane & 7;
    int t01 = (lane >> 3) & 1, t23 = (lane >> 4) & 1;
    int head = blockIdx.z, mh = blockIdx.y;
    const float* kb = K + (size_t)head * NN * DD;
    const float* vb = V + (size_t)head * NN * DD;

    char* Pm = smx + A_P;
    char* Km = smx + A_K;
    char* VS = smx + A_VS;
    char* W  = smx + A_W;
    float* diag_s = (float*)(smx + A_DIAG);
    float* wmx_s  = (float*)(smx + A_WMX);
    float* red    = (float*)(smx + A_RED);

    for (int i = tid; i < 128 * 32; i += 512) {
        int m = i >> 5, dw = i & 31;
        ((uint32_t*)Pm)[m * 36 + dw] = ((const uint32_t*)(g_Pf + (size_t)mh * 8192))[i];
    }
    if (tid < 64) {
        *(uint4*)(VS + tid * 144 + 128) = make_uint4(pkh(1.0f, 0.0f), 0u, 0u, 0u);
    }

    int nw2 = wid >> 2;   // dash n-tile (16 n)
    int mw2 = wid & 3;    // dash m-tile (32 m)
    int cm  = wid >> 1;   // ctx m-tile (16 m)
    int ce  = wid & 1;    // ctx e-half (32 e)

    uint32_t aK  = cvta_s(Km) + (uint32_t)((nw2 * 16 + t01 * 8 + li) * 144) + t23 * 16;
    uint32_t aP  = cvta_s(Pm) + (uint32_t)((mw2 * 32 + t23 * 8 + li) * 144) + t01 * 16;
    uint32_t aWt = cvta_s(W)  + (uint32_t)((li + t23 * 8) * 272) + (uint32_t)((cm * 16 + t01 * 8) * 2);
    uint32_t aVt = cvta_s(VS) + (uint32_t)((li + t01 * 8) * 144) + (uint32_t)((ce * 32 + (lane >> 4) * 8) * 2);
    uint32_t aV1 = cvta_s(VS) + (uint32_t)((li + t01 * 8) * 144) + 128;

    int kn = tid >> 3, kc = (tid & 7) * 8;

    float cacc[4][4] = {};
    float cone[4] = {};
    float M = -1e30f;      // running max of (dash - diag), CTA-wide
    float lmax = -1e30f;   // raw dash max (for exact gmax)

    for (int ch = 0; ch < 8; ch++) {
        int n0 = blockIdx.x * 512 + ch * 64;
        __syncthreads();
        {
            const float* ks = kb + (size_t)(n0 + kn) * 64 + kc;
            float4 k0 = *(const float4*)ks, k1 = *(const float4*)(ks + 4);
            float part = cv8f(k0, k1, SCALE, Km + kn * 144 + kc * 2);
            part += __shfl_xor_sync(0xffffffffu, part, 1);
            part += __shfl_xor_sync(0xffffffffu, part, 2);
            part += __shfl_xor_sync(0xffffffffu, part, 4);
            if ((tid & 7) == 0) diag_s[kn] = 0.5f * part;
            const float* vs = vb + (size_t)(n0 + kn) * 64 + kc;
            float4 v0 = *(const float4*)vs, v1 = *(const float4*)(vs + 4);
            cv8n(v0, v1, VS + kn * 144 + kc * 2);
        }
        __syncthreads();
        // ---- dash MMA: warp = 16n x 32m ----
        {
            int arow = nw2 * 16 + lr;
            float dg0 = diag_s[arow], dg1 = diag_s[arow + 8];
            float acc[4][4] = {};
            for (int ks = 0; ks < 4; ks++) {
                uint32_t a[4];
                ldsm4(a, aK + ks * 32);
                #pragma unroll
                for (int ctp = 0; ctp < 2; ctp++) {
                    uint32_t b[4];
                    ldsm4(b, aP + ctp * 2304 + ks * 32);
                    MMA(acc[2*ctp],   a, b[0], b[1]);
                    MMA(acc[2*ctp+1], a, b[2], b[3]);
                }
            }
            // ---- chunk max of (dash - diag) + raw dash max ----
            float tmax = -1e30f;
            #pragma unroll
            for (int ct = 0; ct < 4; ct++) {
                lmax = fmaxf(lmax, fmaxf(fmaxf(acc[ct][0], acc[ct][1]),
                                         fmaxf(acc[ct][2], acc[ct][3])));
                tmax = fmaxf(tmax, fmaxf(fmaxf(acc[ct][0] - dg0, acc[ct][1] - dg0),
                                         fmaxf(acc[ct][2] - dg1, acc[ct][3] - dg1)));
            }
            tmax = fmaxf(tmax, __shfl_xor_sync(0xffffffffu, tmax, 1));
            tmax = fmaxf(tmax, __shfl_xor_sync(0xffffffffu, tmax, 2));
            tmax = fmaxf(tmax, __shfl_xor_sync(0xffffffffu, tmax, 4));
            tmax = fmaxf(tmax, __shfl_xor_sync(0xffffffffu, tmax, 8));
            tmax = fmaxf(tmax, __shfl_xor_sync(0xffffffffu, tmax, 16));
            if (lane == 0) wmx_s[wid] = tmax;
            __syncthreads();
            float cmx = -1e30f;
            #pragma unroll
            for (int j = 0; j < 16; j++) cmx = fmaxf(cmx, wmx_s[j]);
            float Mn = fmaxf(M, cmx);
            float f = fexp(M - Mn);
            #pragma unroll
            for (int ct = 0; ct < 4; ct++) {
                cacc[ct][0] *= f; cacc[ct][1] *= f; cacc[ct][2] *= f; cacc[ct][3] *= f;
            }
            cone[0] *= f; cone[1] *= f; cone[2] *= f; cone[3] *= f;
            M = Mn;
            // ---- w = exp(dash - diag - M) <= 1, fp16 store ----
            float o0 = dg0 + M, o1 = dg1 + M;
            #pragma unroll
            for (int ct = 0; ct < 4; ct++) {
                int mc = mw2 * 32 + ct * 8 + qk;
                float w0 = fexp(acc[ct][0] - o0), w1 = fexp(acc[ct][1] - o0);
                float w2 = fexp(acc[ct][2] - o1), w3 = fexp(acc[ct][3] - o1);
                *(uint32_t*)(W + (size_t)arow * 272 + mc * 2)       = pkh(w0, w1);
                *(uint32_t*)(W + (size_t)(arow + 8) * 272 + mc * 2) = pkh(w2, w3);
            }
        }
        __syncthreads();
        // ---- ctx MMA: warp = 16m x 32e (+ ones col if ce==0), k=64 ----
        for (int ks = 0; ks < 4; ks++) {
            uint32_t aw[4];
            ldsm4t(aw, aWt + ks * 4352);
            #pragma unroll
            for (int etp = 0; etp < 2; etp++) {
                uint32_t bv[4];
                ldsm4t(bv, aVt + ks * 2304 + etp * 32);
                MMA(cacc[2*etp],   aw, bv[0], bv[1]);
                MMA(cacc[2*etp+1], aw, bv[2], bv[3]);
            }
            if (ce == 0) {
                uint32_t b2[2];
                ldsm2t(b2, aV1 + ks * 2304);
                MMA(cone, aw, b2[0], b2[1]);
            }
        }
    }
    // ---- flush: scale by e^{M}, track exact gmax ----
    __syncthreads();
    red[tid] = lmax;
    __syncthreads();
    for (int s = 256; s > 0; s >>= 1) {
        if (tid < s) red[tid] = fmaxf(red[tid], red[tid + s]);
        __syncthreads();
    }
    if (tid == 0) atomicMax(&g_gmax[head], enc_f(red[0]));
    float scl = fexp(M);
    float* ctx = g_ctxraw + (size_t)head * MM * DD;
    {
        int m = mh * 128 + cm * 16 + lr;
        #pragma unroll
        for (int et = 0; et < 4; et++) {
            int e = ce * 32 + et * 8 + qk;
            atomicAdd(&ctx[m * 64 + e],           cacc[et][0] * scl);
            atomicAdd(&ctx[m * 64 + e + 1],       cacc[et][1] * scl);
            atomicAdd(&ctx[(m + 8) * 64 + e],     cacc[et][2] * scl);
            atomicAdd(&ctx[(m + 8) * 64 + e + 1], cacc[et][3] * scl);
        }
        if (ce == 0 && (lane & 3) == 0) {
            atomicAdd(&g_ksumraw[head * MM + m],     cone[0] * scl);
            atomicAdd(&g_ksumraw[head * MM + m + 8], cone[2] * scl);
        }
    }
}

// =============== kB: finalize with exact e^{-gmax} ===============
__global__ void kB() {
    int b = blockIdx.x, head = b >> 3, part = b & 7;
    int tid = threadIdx.x;
    float emx = fexp(-dec_f(g_gmax[head]));
    if (part == 0) g_ksumf[head * MM + tid] = emx * g_ksumraw[head * MM + tid] + EPSILON * (float)NN;
    int i0 = part * 2048;
    for (int i = i0 + tid; i < i0 + 2048; i += 256) {
        int m = i >> 6, e = i & 63;
        float cf = emx * g_ctxraw[(size_t)head * MM * DD + i] + EPSILON * g_vsum[head * DD + e];
        g_Ch[(size_t)head * 16384 + e * 256 + m] = __float2half(cf);
    }
}

// =============== kC: q-side fused, fp16, 2 CTAs/SM, 32-row chunks ===============
#define C_P    0        // [256 m][72] fp16
#define C_CH   36864    // [64 e][264 m] fp16
#define C_Q    70656    // [32 n][72]
#define C_W    75264    // [32 n][264 m] fp16
#define C_KSUM 92160    // 256 f32
#define C_DIAG 93184    // 32 f32
#define C_MX   93312    // 32 f32
#define C_PM   93440    // 32*8 f32
#define C_PDEN 94464    // 32*8 f32
#define C_DINV 95488    // 32 f32
#define C_SIZE 95616

__global__ void __launch_bounds__(512, 2) kC(const float* __restrict__ Q,
                                             float* __restrict__ out) {
    extern __shared__ char smx[];
    int tid = threadIdx.x, wid = tid >> 5, lane = tid & 31;
    int lr = lane >> 2, qk = (lane & 3) * 2;
    int li = lane & 7;
    int t01 = (lane >> 3) & 1, t23 = (lane >> 4) & 1;
    int head = blockIdx.y;
    const float* qb = Q + (size_t)head * NN * DD;

    char* Pm = smx + C_P;
    char* CH = smx + C_CH;
    char* Qm = smx + C_Q;
    char* W  = smx + C_W;
    float* ksum_s = (float*)(smx + C_KSUM);
    float* diag_s = (float*)(smx + C_DIAG);
    float* mxs    = (float*)(smx + C_MX);
    float* pm     = (float*)(smx + C_PM);
    float* pden   = (float*)(smx + C_PDEN);
    float* dinv_s = (float*)(smx + C_DINV);

    for (int i = tid; i < 256 * 32; i += 512) {
        int m = i >> 5, dw = i & 31;
        ((uint32_t*)Pm)[m * 36 + dw] = ((const uint32_t*)g_Pf)[i];
    }
    for (int i = tid; i < 64 * 128; i += 512) {
        int e = i >> 7, mw = i & 127;
        ((uint32_t*)CH)[e * 132 + mw] = ((const uint32_t*)(g_Ch + (size_t)head * 16384))[i];
    }
    if (tid < 256) ksum_s[tid] = g_ksumf[head * MM + tid];

    int rt = wid & 1;     // n-tile (16 n)
    int g  = wid >> 1;    // dash m-tile (32 m) / out e-tile (8 e)
    int arow = rt * 16 + lr;

    uint32_t aQ  = cvta_s(Qm) + (uint32_t)((rt * 16 + t01 * 8 + li) * 144) + t23 * 16;
    uint32_t aP  = cvta_s(Pm) + (uint32_t)((g * 32 + t23 * 8 + li) * 144) + t01 * 16;
    uint32_t aWA = cvta_s(W)  + (uint32_t)((rt * 16 + t01 * 8 + li) * 528) + t23 * 16;
    uint32_t aCB = cvta_s(CH) + (uint32_t)((g * 8 + li) * 528) + (lane >> 3) * 16;

    int qn = tid >> 3, qc = (tid & 7) * 8;

    for (int ch = 0; ch < 8; ch++) {
        int n0 = blockIdx.x * 256 + ch * 32;
        __syncthreads();
        if (tid < 256) {
            const float* src = qb + (size_t)(n0 + qn) * 64 + qc;
            float4 u = *(const float4*)src, v = *(const float4*)(src + 4);
            float part = cv8f(u, v, SCALE, Qm + qn * 144 + qc * 2);
            part += __shfl_xor_sync(0xffffffffu, part, 1);
            part += __shfl_xor_sync(0xffffffffu, part, 2);
            part += __shfl_xor_sync(0xffffffffu, part, 4);
            if ((tid & 7) == 0) diag_s[qn] = 0.5f * part;
        }
        __syncthreads();
        // ---- dash MMA: warp = 16n x 32m ----
        float acc[4][4] = {};
        for (int ks = 0; ks < 4; ks++) {
            uint32_t a[4];
            ldsm4(a, aQ + ks * 32);
            #pragma unroll
            for (int ctp = 0; ctp < 2; ctp++) {
                uint32_t b[4];
                ldsm4(b, aP + ctp * 2304 + ks * 32);
                MMA(acc[2*ctp],   a, b[0], b[1]);
                MMA(acc[2*ctp+1], a, b[2], b[3]);
            }
        }
        // ---- rowmax ----
        {
            float mx0 = -1e30f, mx1 = -1e30f;
            #pragma unroll
            for (int ct = 0; ct < 4; ct++) {
                mx0 = fmaxf(mx0, fmaxf(acc[ct][0], acc[ct][1]));
                mx1 = fmaxf(mx1, fmaxf(acc[ct][2], acc[ct][3]));
            }
            mx0 = fmaxf(mx0, __shfl_xor_sync(0xffffffffu, mx0, 1));
            mx0 = fmaxf(mx0, __shfl_xor_sync(0xffffffffu, mx0, 2));
            mx1 = fmaxf(mx1, __shfl_xor_sync(0xffffffffu, mx1, 1));
            mx1 = fmaxf(mx1, __shfl_xor_sync(0xffffffffu, mx1, 2));
            if ((lane & 3) == 0) {
                pm[arow * 8 + g] = mx0;
                pm[(arow + 8) * 8 + g] = mx1;
            }
        }
        __syncthreads();
        if (tid < 32) {
            float m = -1e30f;
            #pragma unroll
            for (int j = 0; j < 8; j++) m = fmaxf(m, pm[tid * 8 + j]);
            mxs[tid] = m;
        }
        __syncthreads();
        // ---- exp + den + W write (fp16-consistent den) ----
        {
            float dg0 = diag_s[arow] + mxs[arow];
            float dg1 = diag_s[arow + 8] + mxs[arow + 8];
            float den0 = 0.0f, den1 = 0.0f;
            #pragma unroll
            for (int ct = 0; ct < 4; ct++) {
                int mc = g * 32 + ct * 8 + qk;
                float w0 = fexp(acc[ct][0] - dg0) + EPSILON;
                float w1 = fexp(acc[ct][1] - dg0) + EPSILON;
                float w2 = fexp(acc[ct][2] - dg1) + EPSILON;
                float w3 = fexp(acc[ct][3] - dg1) + EPSILON;
                uint32_t p01 = pkh(w0, w1), p23 = pkh(w2, w3);
                __half2 h01 = *(__half2*)&p01, h23 = *(__half2*)&p23;
                den0 += __half2float(h01.x) * ksum_s[mc] + __half2float(h01.y) * ksum_s[mc + 1];
                den1 += __half2float(h23.x) * ksum_s[mc] + __half2float(h23.y) * ksum_s[mc + 1];
                *(uint32_t*)(W + (size_t)arow * 528 + mc * 2)       = p01;
                *(uint32_t*)(W + (size_t)(arow + 8) * 528 + mc * 2) = p23;
            }
            den0 += __shfl_xor_sync(0xffffffffu, den0, 1);
            den0 += __shfl_xor_sync(0xffffffffu, den0, 2);
            den1 += __shfl_xor_sync(0xffffffffu, den1, 1);
            den1 += __shfl_xor_sync(0xffffffffu, den1, 2);
            if ((lane & 3) == 0) {
                pden[arow * 8 + g] = den0;
                pden[(arow + 8) * 8 + g] = den1;
            }
        }
        __syncthreads();
        if (tid < 32) {
            float s = 0.0f;
            #pragma unroll
            for (int j = 0; j < 8; j++) s += pden[tid * 8 + j];
            dinv_s[tid] = 1.0f / s;
        }
        __syncthreads();
        // ---- out MMA: warp = 16n x 8e, k=256 ----
        {
            float oacc[4] = {};
            for (int ks2 = 0; ks2 < 8; ks2++) {
                uint32_t aw0[4], aw1[4], bc[4];
                ldsm4(aw0, aWA + ks2 * 64);
                ldsm4(aw1, aWA + ks2 * 64 + 32);
                ldsm4(bc, aCB + ks2 * 64);
                MMA(oacc, aw0, bc[0], bc[1]);
                MMA(oacc, aw1, bc[2], bc[3]);
            }
            float di0 = dinv_s[arow];
            float di1 = dinv_s[arow + 8];
            int nr = n0 + arow;
            int e = g * 8 + qk;
            float* ob0 = out + ((size_t)head * NN + nr) * 64 + e;
            float* ob1 = out + ((size_t)head * NN + nr + 8) * 64 + e;
            ob0[0] = oacc[0] * di0;
            ob0[1] = oacc[1] * di0;
            ob1[0] = oacc[2] * di1;
            ob1[1] = oacc[3] * di1;
        }
    }
}

// ---------------- launch ----------------
extern "C" void kernel_launch(void* const* d_in, const int* in_sizes, int n_in,
                              void* d_out, int out_size) {
    const float* q = (const float*)d_in[0];
    const float* k = (const float*)d_in[1];
    const float* v = (const float*)d_in[2];
    const float* P = (const float*)d_in[3];
    float* out = (float*)d_out;

    cudaFuncSetAttribute(kA, cudaFuncAttributeMaxDynamicSharedMemorySize, A_SIZE);
    cudaFuncSetAttribute(kC, cudaFuncAttributeMaxDynamicSharedMemorySize, C_SIZE);

    k0_init<<<(NH * MM * DD + 255) / 256, 256>>>();
    kP<<<64, 256>>>(P);
    kV<<<dim3(16, NH), 256>>>(v);
    kA<<<dim3(8, 2, NH), 512, A_SIZE>>>(k, v);
    kB<<<512, 256>>>();
    kC<<<dim3(16, NH), 512, C_SIZE>>>(q, out);
}